// round 11
// baseline (speedup 1.0000x reference)
#include <cuda_runtime.h>
#include <cuda_bf16.h>
#include <math.h>
#include <stdint.h>

#define B_ 8
#define C_ 256
#define H_ 128
#define W_ 128
#define HW_ 16384
#define HEADS_ 8
#define HD_ 32
#define GSEG 4

typedef __nv_bfloat16 bf16;
typedef __nv_bfloat162 bf162;

// ---------------- scratch (device globals; no allocation allowed) ------------
__device__ bf16 g_bufA[B_ * C_ * HW_];           // q_pre
__device__ bf16 g_bufB[B_ * 2 * C_ * HW_];       // kv_pre
__device__ bf16 g_q[B_ * C_ * HW_];
__device__ bf16 g_k[B_ * C_ * HW_];
__device__ bf16 g_v[B_ * C_ * HW_];
__device__ bf16 g_pe[B_ * C_ * HW_];             // pemb (WITHOUT hx)
__device__ unsigned g_Wqh[C_ * 128];             // bf16-pair packed folded weights
__device__ unsigned g_Wkvh[2 * C_ * 128];
__device__ unsigned g_Mh[B_ * C_ * 128];         // packed M = ao_w @ blockdiag(attn)
__device__ float g_bq[C_];
__device__ float g_bkv[2 * C_];
__device__ float g_rsq[C_];
__device__ float g_rskv[2 * C_];
__device__ float g_ss[2 * B_ * C_];
__device__ float g_part[B_ * HEADS_ * GSEG * 1024];
__device__ float g_attn[B_ * HEADS_ * 1024];

// ---------------- helpers ------------------------------------------------
__device__ __forceinline__ void mma_bf16(float* c, const unsigned* a, unsigned b0, unsigned b1) {
    asm volatile(
        "mma.sync.aligned.m16n8k16.row.col.f32.bf16.bf16.f32 "
        "{%0,%1,%2,%3}, {%4,%5,%6,%7}, {%8,%9}, {%0,%1,%2,%3};\n"
        : "+f"(c[0]), "+f"(c[1]), "+f"(c[2]), "+f"(c[3])
        : "r"(a[0]), "r"(a[1]), "r"(a[2]), "r"(a[3]), "r"(b0), "r"(b1));
}
__device__ __forceinline__ void ldsm_x4(unsigned* r, uint32_t addr) {
    asm volatile("ldmatrix.sync.aligned.m8n8.x4.shared.b16 {%0,%1,%2,%3}, [%4];"
                 : "=r"(r[0]), "=r"(r[1]), "=r"(r[2]), "=r"(r[3])
                 : "r"(addr));
}
__device__ __forceinline__ uint32_t smem_u32(const void* p) {
    return (uint32_t)__cvta_generic_to_shared(p);
}
__device__ __forceinline__ unsigned packbf(float lo, float hi) {
    bf162 t = __floats2bfloat162_rn(lo, hi);
    return *reinterpret_cast<unsigned*>(&t);
}
__device__ __forceinline__ float gelu_tanh(float s) {
    float x3 = s * s * s;
    return 0.5f * s * (1.f + tanhf(0.7978845608028654f * (s + 0.044715f * x3)));
}
__device__ __forceinline__ void u4_to_f8(uint4 u, float4& lo, float4& hi) {
    bf162 h0 = *reinterpret_cast<bf162*>(&u.x);
    bf162 h1 = *reinterpret_cast<bf162*>(&u.y);
    bf162 h2 = *reinterpret_cast<bf162*>(&u.z);
    bf162 h3 = *reinterpret_cast<bf162*>(&u.w);
    float2 f0 = __bfloat1622float2(h0), f1 = __bfloat1622float2(h1);
    float2 f2 = __bfloat1622float2(h2), f3 = __bfloat1622float2(h3);
    lo = make_float4(f0.x, f0.y, f1.x, f1.y);
    hi = make_float4(f2.x, f2.y, f3.x, f3.y);
}
__device__ __forceinline__ uint4 f8_to_u4(const float* o) {
    uint4 r;
    r.x = packbf(o[0], o[1]);
    r.y = packbf(o[2], o[3]);
    r.z = packbf(o[4], o[5]);
    r.w = packbf(o[6], o[7]);
    return r;
}

// 8-wide 3-tap over a padded smem row (data at +4; pads zero at 0..3 / 132..135)
__device__ __forceinline__ void stencil8(const float* R, int s, float w0, float w1, float w2,
                                         float* o) {
    float4 m0 = *reinterpret_cast<const float4*>(R + 4 + s);
    float4 m1 = *reinterpret_cast<const float4*>(R + 8 + s);
    float l = R[3 + s], r = R[12 + s];
    o[0] += w0 * l    + w1 * m0.x + w2 * m0.y;
    o[1] += w0 * m0.x + w1 * m0.y + w2 * m0.z;
    o[2] += w0 * m0.y + w1 * m0.z + w2 * m0.w;
    o[3] += w0 * m0.z + w1 * m0.w + w2 * m1.x;
    o[4] += w0 * m0.w + w1 * m1.x + w2 * m1.y;
    o[5] += w0 * m1.x + w1 * m1.y + w2 * m1.z;
    o[6] += w0 * m1.y + w1 * m1.z + w2 * m1.w;
    o[7] += w0 * m1.z + w1 * m1.w + w2 * r;
}

// single-pass fill of N padded rows from bf16 global
template <int NROWS>
__device__ __forceinline__ void fill_rows(float (*dst)[136], const bf16* src, int r0, int roff,
                                          int tid) {
    float4 z4 = make_float4(0.f, 0.f, 0.f, 0.f);
    for (int i = tid; i < NROWS * 16; i += 256) {
        int row = i >> 4, c8 = (i & 15) * 8;
        int gr = r0 + roff + row;
        float4 lo = z4, hi = z4;
        if (gr >= 0 && gr < H_) {
            uint4 u = *reinterpret_cast<const uint4*>(src + (size_t)gr * W_ + c8);
            u4_to_f8(u, lo, hi);
        }
        *reinterpret_cast<float4*>(&dst[row][4 + c8]) = lo;
        *reinterpret_cast<float4*>(&dst[row][8 + c8]) = hi;
    }
    for (int i = tid; i < NROWS * 2; i += 256) {
        int row = i >> 1;
        *reinterpret_cast<float4*>(&dst[row][(i & 1) ? 132 : 0]) = z4;
    }
}

// ---------------- weight prep: fold LN gamma/beta, pack to bf16 pairs --------
__global__ void prep_w_kernel(const float* __restrict__ qw, const float* __restrict__ qb,
                              const float* __restrict__ ln1w, const float* __restrict__ ln1b,
                              const float* __restrict__ kvw, const float* __restrict__ kvb,
                              const float* __restrict__ ln2w, const float* __restrict__ ln2b) {
    int r = blockIdx.x;
    int tid = threadIdx.x;
    if (r < 16) g_ss[r * 256 + tid] = 0.f;
    const float *w, *lnw, *lnb;
    float cb;
    unsigned* dWh;
    float *dB, *dR;
    if (r < C_) {
        int o = r;
        w = qw + (size_t)o * C_; lnw = ln1w; lnb = ln1b; cb = qb[o];
        dWh = g_Wqh + (size_t)o * 128; dB = g_bq + o; dR = g_rsq + o;
    } else {
        int o = r - C_;
        w = kvw + (size_t)o * C_; lnw = ln2w; lnb = ln2b; cb = kvb[o];
        dWh = g_Wkvh + (size_t)o * 128; dB = g_bkv + o; dR = g_rskv + o;
    }
    float wv = w[tid];
    float we = wv * lnw[tid];
    float we_r = __bfloat162float(__float2bfloat16(we));
    __shared__ float shw[256], sh1[256], sh2[256];
    shw[tid] = we_r;
    sh1[tid] = we_r;
    sh2[tid] = wv * lnb[tid];
    __syncthreads();
    if (tid < 128) dWh[tid] = packbf(shw[2 * tid], shw[2 * tid + 1]);
    for (int s = 128; s > 0; s >>= 1) {
        if (tid < s) { sh1[tid] += sh1[tid + s]; sh2[tid] += sh2[tid + s]; }
        __syncthreads();
    }
    if (tid == 0) { *dR = sh1[0]; *dB = cb + sh2[0]; }
}

// ========= LN-fused GEMM: bf16 m16n8k16 + ldmatrix, fp32 X pack ==============
struct GemmArgs {
    const float* X;
    const unsigned* Wh;
    const float* bias;
    const float* rsum;
    bf16* Yh;
    int O;
};

#define SA_U 20
#define SB_U 136
#define STG_U (128 * SA_U + 16 * SB_U)   // 4736 uints / stage

__global__ __launch_bounds__(256, 2) void gemm_lnh_kernel(GemmArgs ga) {
    __shared__ unsigned sm[2 * STG_U];
    __shared__ float sS[8][128], sQ[8][128];
    int b = blockIdx.z;
    int oBase = blockIdx.x * 128;
    int pBase = blockIdx.y * 128;
    int tid = threadIdx.x;
    int wid = tid >> 5, lane = tid & 31;
    int g = lane >> 2, tig = lane & 3;
    int oW = (wid >> 2) * 64;
    int pW = (wid & 3) * 32;
    uint32_t smBase = smem_u32(sm);
    uint32_t aRowOff = (uint32_t)((lane & 15) * SA_U * 4 + (lane >> 4) * 16);

    const float* Xb = ga.X + (size_t)b * C_ * HW_;
    const unsigned* Wb = ga.Wh;

    int lk2 = tid >> 5;
    int lp0 = (tid & 31) * 4;

    uint4 wR[2];
    float4 xR[2][2];
    auto ldg = [&](int kc) {
        int k0 = kc * 32;
#pragma unroll
        for (int i = 0; i < 2; i++) {
            int idx = tid + i * 256;
            int o = idx >> 2, q = idx & 3;
            wR[i] = *reinterpret_cast<const uint4*>(Wb + (size_t)(oBase + o) * 128 + k0 / 2 + q * 4);
        }
#pragma unroll
        for (int i = 0; i < 2; i++) {
            int kk = k0 + 2 * (lk2 + i * 8);
            xR[i][0] = *reinterpret_cast<const float4*>(Xb + (size_t)kk * HW_ + pBase + lp0);
            xR[i][1] = *reinterpret_cast<const float4*>(Xb + (size_t)(kk + 1) * HW_ + pBase + lp0);
        }
    };
    float stS[4] = {}, stQ[4] = {};
    auto sts = [&](int st) {
        unsigned* sA = sm + st * STG_U;
        unsigned* sB = sA + 128 * SA_U;
#pragma unroll
        for (int i = 0; i < 2; i++) {
            int idx = tid + i * 256;
            int o = idx >> 2, q = idx & 3;
            *reinterpret_cast<uint4*>(sA + o * SA_U + q * 4) = wR[i];
        }
#pragma unroll
        for (int i = 0; i < 2; i++) {
            float4 a = xR[i][0], c = xR[i][1];
            stS[0] += a.x + c.x; stQ[0] += a.x * a.x + c.x * c.x;
            stS[1] += a.y + c.y; stQ[1] += a.y * a.y + c.y * c.y;
            stS[2] += a.z + c.z; stQ[2] += a.z * a.z + c.z * c.z;
            stS[3] += a.w + c.w; stQ[3] += a.w * a.w + c.w * c.w;
            uint4 u;
            u.x = packbf(a.x, c.x);
            u.y = packbf(a.y, c.y);
            u.z = packbf(a.z, c.z);
            u.w = packbf(a.w, c.w);
            *reinterpret_cast<uint4*>(sB + (lk2 + i * 8) * SB_U + lp0) = u;
        }
    };

    float acc[4][4][4] = {};
    ldg(0);
    for (int kc = 0; kc < 8; kc++) {
        sts(kc & 1);
        __syncthreads();
        if (kc < 7) ldg(kc + 1);
        uint32_t sAaddr = smBase + (kc & 1) * STG_U * 4;
        unsigned* sB = sm + (kc & 1) * STG_U + 128 * SA_U;
#pragma unroll
        for (int s2 = 0; s2 < 16; s2 += 8) {
            unsigned afr[4][4];
#pragma unroll
            for (int mt = 0; mt < 4; mt++)
                ldsm_x4(afr[mt], sAaddr + (uint32_t)((oW + mt * 16) * SA_U + s2) * 4 + aRowOff);
#pragma unroll
            for (int nt = 0; nt < 4; nt++) {
                int cp = pW + nt * 8 + g;
                unsigned b0 = sB[(s2 + tig) * SB_U + cp];
                unsigned b1 = sB[(s2 + 4 + tig) * SB_U + cp];
#pragma unroll
                for (int mt = 0; mt < 4; mt++)
                    mma_bf16(acc[mt][nt], afr[mt], b0, b1);
            }
        }
        __syncthreads();
    }

    *reinterpret_cast<float4*>(&sS[lk2][lp0]) = make_float4(stS[0], stS[1], stS[2], stS[3]);
    *reinterpret_cast<float4*>(&sQ[lk2][lp0]) = make_float4(stQ[0], stQ[1], stQ[2], stQ[3]);
    __syncthreads();
    float mu[4][2], iv[4][2];
#pragma unroll
    for (int nt = 0; nt < 4; nt++) {
#pragma unroll
        for (int u = 0; u < 2; u++) {
            int pl = pW + nt * 8 + 2 * tig + u;
            float s0 = 0.f, q0 = 0.f;
#pragma unroll
            for (int wrow = 0; wrow < 8; wrow++) { s0 += sS[wrow][pl]; q0 += sQ[wrow][pl]; }
            float m = s0 * (1.f / 256.f);
            float var = q0 * (1.f / 256.f) - m * m;
            mu[nt][u] = m;
            iv[nt][u] = rsqrtf(var + 1e-5f);
        }
    }
#pragma unroll
    for (int mt = 0; mt < 4; mt++) {
        int o0 = oBase + oW + mt * 16 + g;
        int o1 = o0 + 8;
        float rs0 = ga.rsum[o0], b0v = ga.bias[o0];
        float rs1 = ga.rsum[o1], b1v = ga.bias[o1];
#pragma unroll
        for (int nt = 0; nt < 4; nt++) {
            int p = pBase + pW + nt * 8 + 2 * tig;
            bf162 r0 = __floats2bfloat162_rn(
                iv[nt][0] * (acc[mt][nt][0] - mu[nt][0] * rs0) + b0v,
                iv[nt][1] * (acc[mt][nt][1] - mu[nt][1] * rs0) + b0v);
            bf162 r1 = __floats2bfloat162_rn(
                iv[nt][0] * (acc[mt][nt][2] - mu[nt][0] * rs1) + b1v,
                iv[nt][1] * (acc[mt][nt][3] - mu[nt][1] * rs1) + b1v);
            *reinterpret_cast<bf162*>(ga.Yh + ((size_t)b * ga.O + o0) * HW_ + p) = r0;
            *reinterpret_cast<bf162*>(ga.Yh + ((size_t)b * ga.O + o1) * HW_ + p) = r1;
        }
    }
}

// ====== merged stencil kernel: q-dw | k-dw | v-dw + positional branch =========
// grid (8, 3*C, B); branch uniform per block.
//   ci < C      : q = dw(bufA) -> g_q (+sumsq q)      [1 row x 8 cols / thread]
//   C <= ci <2C : k = dw(bufB lo) -> g_k (+sumsq k)
//   ci >= 2C    : v/pe chain (16-row tile, smem)
__global__ __launch_bounds__(256) void dwvpe_kernel(const float* __restrict__ qw9,
                                                    const float* __restrict__ qb,
                                                    const float* __restrict__ kvw9,
                                                    const float* __restrict__ kvb,
                                                    const float* __restrict__ pe1,
                                                    const float* __restrict__ pe2) {
    __shared__ float sbuf[(22 + 20) * 136];
    int b = blockIdx.z, ci = blockIdx.y;
    int tid = threadIdx.x;

    if (ci < 2 * C_) {
        // ---------------- register-strip dw for q or k ----------------
        int cg = tid & 15, rg = tid >> 4;
        int c0 = cg * 8;
        int r0 = blockIdx.x * 16 + rg;
        const bf16* Xc;
        const float* w9;
        const float* bp;
        bf16* D;
        float* ssq;
        if (ci < C_) {
            Xc = g_bufA + ((size_t)(b * C_ + ci)) * HW_;
            w9 = qw9 + (size_t)ci * 9;
            bp = qb + ci;
            D = g_q + ((size_t)(b * C_ + ci)) * HW_;
            ssq = &g_ss[b * C_ + ci];
        } else {
            int c = ci - C_;
            Xc = g_bufB + ((size_t)(b * 2 * C_ + c)) * HW_;
            w9 = kvw9 + (size_t)c * 9;
            bp = kvb + c;
            D = g_k + ((size_t)(b * C_ + c)) * HW_;
            ssq = &g_ss[B_ * C_ + b * C_ + c];
        }
        float wk[9];
#pragma unroll
        for (int t = 0; t < 9; t++) wk[t] = __ldg(w9 + t);
        float bv = __ldg(bp);
        float o[8] = {bv, bv, bv, bv, bv, bv, bv, bv};
#pragma unroll
        for (int t = 0; t < 3; t++) {
            int ir = r0 - 1 + t;
            float f[10];
#pragma unroll
            for (int u = 0; u < 10; u++) f[u] = 0.f;
            if (ir >= 0 && ir < H_) {
                uint4 u4 = *reinterpret_cast<const uint4*>(Xc + (size_t)ir * W_ + c0);
                float4 lo, hi;
                u4_to_f8(u4, lo, hi);
                f[1] = lo.x; f[2] = lo.y; f[3] = lo.z; f[4] = lo.w;
                f[5] = hi.x; f[6] = hi.y; f[7] = hi.z; f[8] = hi.w;
                if (c0 > 0) f[0] = __bfloat162float(__ldg(Xc + (size_t)ir * W_ + c0 - 1));
                if (c0 + 8 < W_) f[9] = __bfloat162float(__ldg(Xc + (size_t)ir * W_ + c0 + 8));
            }
#pragma unroll
            for (int u = 0; u < 8; u++)
                o[u] += wk[t * 3] * f[u] + wk[t * 3 + 1] * f[u + 1] + wk[t * 3 + 2] * f[u + 2];
        }
        *reinterpret_cast<uint4*>(D + (size_t)r0 * W_ + c0) = f8_to_u4(o);
        float ss = 0.f;
#pragma unroll
        for (int u = 0; u < 8; u++) ss += o[u] * o[u];
#pragma unroll
        for (int d = 16; d > 0; d >>= 1) ss += __shfl_down_sync(0xffffffffu, ss, d);
        if ((tid & 31) == 0) atomicAdd(ssq, ss);
        return;
    }

    // ---------------- v dwconv + positional branch ----------------
    float (*svi)[136] = reinterpret_cast<float(*)[136]>(sbuf);            // 22 rows
    float (*sv)[136]  = reinterpret_cast<float(*)[136]>(sbuf + 22 * 136); // 20 rows
    float (*st1)[136] = svi;                                              // alias (18 rows)
    int c = ci - 2 * C_;
    int r0 = blockIdx.x * 16;
    const bf16* Vc = g_bufB + ((size_t)(b * 2 * C_ + C_ + c)) * HW_;
    fill_rows<22>(svi, Vc, r0, -3, tid);
    {
        float4 z4 = make_float4(0.f, 0.f, 0.f, 0.f);
        for (int i = tid; i < 20 * 2; i += 256)
            *reinterpret_cast<float4*>(&sv[i >> 1][(i & 1) ? 132 : 0]) = z4;
    }
    float wkv[9], w1[9], w2[9];
#pragma unroll
    for (int t = 0; t < 9; t++) {
        wkv[t] = __ldg(kvw9 + (size_t)(C_ + c) * 9 + t);
        w1[t] = __ldg(pe1 + (size_t)c * 9 + t);
        w2[t] = __ldg(pe2 + (size_t)c * 9 + t);
    }
    float bvv = __ldg(kvb + C_ + c);
    __syncthreads();

    int row0 = tid >> 4, s0 = (tid & 15) * 8;

    bf16* Dv = g_v + ((size_t)(b * C_ + c)) * HW_;
    for (int i = tid; i < 20 * 16; i += 256) {
        int row = i >> 4, cc = (i & 15) * 8;
        int gr = r0 - 2 + row;
        float o[8] = {};
        if (gr >= 0 && gr < H_) {
#pragma unroll
            for (int u = 0; u < 8; u++) o[u] = bvv;
#pragma unroll
            for (int dr = 0; dr < 3; dr++)
                stencil8(svi[row + dr], cc, wkv[dr * 3], wkv[dr * 3 + 1], wkv[dr * 3 + 2], o);
        }
        *reinterpret_cast<float4*>(&sv[row][4 + cc]) = make_float4(o[0], o[1], o[2], o[3]);
        *reinterpret_cast<float4*>(&sv[row][8 + cc]) = make_float4(o[4], o[5], o[6], o[7]);
        if (row >= 2 && row < 18)
            *reinterpret_cast<uint4*>(Dv + (size_t)gr * W_ + cc) = f8_to_u4(o);
    }
    __syncthreads();

    for (int i = tid; i < 18 * 16; i += 256) {
        int row = i >> 4, cc = (i & 15) * 8;
        int gr = r0 - 1 + row;
        float o[8] = {};
        if (gr >= 0 && gr < H_) {
#pragma unroll
            for (int dr = 0; dr < 3; dr++)
                stencil8(sv[row + dr], cc, w1[dr * 3], w1[dr * 3 + 1], w1[dr * 3 + 2], o);
#pragma unroll
            for (int u = 0; u < 8; u++) o[u] = gelu_tanh(o[u]);
        }
        *reinterpret_cast<float4*>(&st1[row][4 + cc]) = make_float4(o[0], o[1], o[2], o[3]);
        *reinterpret_cast<float4*>(&st1[row][8 + cc]) = make_float4(o[4], o[5], o[6], o[7]);
    }
    __syncthreads();

    bf16* Dp = g_pe + ((size_t)(b * C_ + c)) * HW_;
    {
        float o[8] = {};
#pragma unroll
        for (int dr = 0; dr < 3; dr++)
            stencil8(st1[row0 + dr], s0, w2[dr * 3], w2[dr * 3 + 1], w2[dr * 3 + 2], o);
        *reinterpret_cast<uint4*>(Dp + (size_t)(r0 + row0) * W_ + s0) = f8_to_u4(o);
    }
}

// ---------------- gram via bf16 mma m16n8k16, split-K=4 ----------------------
__global__ __launch_bounds__(256) void gram_mma() {
    __shared__ float sbuf[8192];
    bf16* sqh = reinterpret_cast<bf16*>(sbuf);
    bf16* skh = sqh + 32 * 136;
    unsigned* squ = reinterpret_cast<unsigned*>(sqh);
    unsigned* sku = reinterpret_cast<unsigned*>(skh);
    int seg = blockIdx.x, h = blockIdx.y, b = blockIdx.z;
    const bf16* Q = g_q + ((size_t)(b * C_ + h * HD_)) * HW_;
    const bf16* K = g_k + ((size_t)(b * C_ + h * HD_)) * HW_;
    int tid = threadIdx.x, wid = tid >> 5, lane = tid & 31;
    int g = lane >> 2, tig = lane & 3;
    float acc[2][4][4] = {};
    int n0 = seg * (HW_ / GSEG);
    int klu = wid * 8;
    for (int ch = 0; ch < (HW_ / GSEG) / 128; ch++) {
        int base = n0 + ch * 128;
        for (int i = tid; i < 32 * 16; i += 256) {
            int row = i >> 4, c8 = (i & 15) * 8;
            *reinterpret_cast<uint4*>(sqh + row * 136 + c8) =
                *reinterpret_cast<const uint4*>(Q + (size_t)row * HW_ + base + c8);
            *reinterpret_cast<uint4*>(skh + row * 136 + c8) =
                *reinterpret_cast<const uint4*>(K + (size_t)row * HW_ + base + c8);
        }
        __syncthreads();
        unsigned afr[2][4];
#pragma unroll
        for (int mt = 0; mt < 2; mt++) {
            int r = mt * 16 + g;
            afr[mt][0] = squ[r * 68 + klu + tig];
            afr[mt][1] = squ[(r + 8) * 68 + klu + tig];
            afr[mt][2] = squ[r * 68 + klu + 4 + tig];
            afr[mt][3] = squ[(r + 8) * 68 + klu + 4 + tig];
        }
#pragma unroll
        for (int nt = 0; nt < 4; nt++) {
            unsigned b0 = sku[(nt * 8 + g) * 68 + klu + tig];
            unsigned b1 = sku[(nt * 8 + g) * 68 + klu + 4 + tig];
#pragma unroll
            for (int mt = 0; mt < 2; mt++)
                mma_bf16(acc[mt][nt], afr[mt], b0, b1);
        }
        __syncthreads();
    }
    float* red = sbuf;
#pragma unroll
    for (int mt = 0; mt < 2; mt++)
#pragma unroll
        for (int nt = 0; nt < 4; nt++) {
            int r = mt * 16 + g, cl = nt * 8 + 2 * tig;
            red[wid * 1024 + r * 32 + cl] = acc[mt][nt][0];
            red[wid * 1024 + r * 32 + cl + 1] = acc[mt][nt][1];
            red[wid * 1024 + (r + 8) * 32 + cl] = acc[mt][nt][2];
            red[wid * 1024 + (r + 8) * 32 + cl + 1] = acc[mt][nt][3];
        }
    __syncthreads();
    float* outp = g_part + ((size_t)(b * HEADS_ + h) * GSEG + seg) * 1024;
    for (int i = tid; i < 1024; i += 256) {
        float s = 0.f;
#pragma unroll
        for (int w = 0; w < 8; w++) s += red[w * 1024 + i];
        outp[i] = s;
    }
}

// ---------------- softmax with fused q/k norm scales + temperature -----------
__global__ void softmax_kernel(const float* __restrict__ temp) {
    int bh = blockIdx.x;
    int b = bh >> 3, h = bh & 7;
    int i = threadIdx.x;
    float qs = 1.f / fmaxf(sqrtf(g_ss[b * C_ + h * HD_ + i]), 1e-12f);
    float T = __ldg(temp + h);
    float v[32];
    float mx = -1e30f;
#pragma unroll 4
    for (int j = 0; j < 32; j++) {
        float s = 0.f;
#pragma unroll
        for (int seg = 0; seg < GSEG; seg++)
            s += g_part[((size_t)bh * GSEG + seg) * 1024 + i * 32 + j];
        float ks = 1.f / fmaxf(sqrtf(g_ss[B_ * C_ + b * C_ + h * HD_ + j]), 1e-12f);
        float val = s * qs * ks * T;
        v[j] = val;
        mx = fmaxf(mx, val);
    }
    float sum = 0.f;
#pragma unroll
    for (int j = 0; j < 32; j++) {
        v[j] = expf(v[j] - mx);
        sum += v[j];
    }
    float inv = 1.f / sum;
#pragma unroll
    for (int j = 0; j < 32; j++) g_attn[bh * 1024 + i * 32 + j] = v[j] * inv;
}

// ------------ M[b] = ao_w @ blockdiag(attn[b]), packed bf16 pairs ------------
__global__ void buildM_kernel(const float* __restrict__ ao_w) {
    int h = blockIdx.x, b = blockIdx.y;
    int tid = threadIdx.x;
    __shared__ float sa[32][33];
#pragma unroll
    for (int t = 0; t < 4; t++) {
        int idx = tid + t * 256;
        sa[idx >> 5][idx & 31] = g_attn[(b * HEADS_ + h) * 1024 + idx];
    }
    __syncthreads();
    float wreg[32];
#pragma unroll
    for (int c = 0; c < 32; c++) wreg[c] = ao_w[(size_t)tid * C_ + h * HD_ + c];
    float m[32];
#pragma unroll 4
    for (int d = 0; d < 32; d++) {
        float s = 0.f;
#pragma unroll
        for (int c = 0; c < 32; c++) s += wreg[c] * sa[c][d];
        m[d] = s;
    }
    unsigned* Mo = g_Mh + ((size_t)(b * C_) + tid) * 128 + h * 16;
#pragma unroll
    for (int j = 0; j < 16; j++) Mo[j] = packbf(m[2 * j], m[2 * j + 1]);
}

// ======= final GEMM: out = M@v + ao_b + pemb + hx (bf16 mma + ldmatrix) ======
__global__ __launch_bounds__(256, 2) void gemm_outh_kernel(const float* __restrict__ bias,
                                                           const float* __restrict__ hx,
                                                           float* __restrict__ out) {
    __shared__ unsigned sm[2 * STG_U];
    int b = blockIdx.z;
    int oBase = blockIdx.x * 128;
    int pBase = blockIdx.y * 128;
    int tid = threadIdx.x;
    int wid = tid >> 5, lane = tid & 31;
    int g = lane >> 2, tig = lane & 3;
    int oW = (wid >> 2) * 64;
    int pW = (wid & 3) * 32;
    uint32_t smBase = smem_u32(sm);
    uint32_t aRowOff = (uint32_t)((lane & 15) * SA_U * 4 + (lane >> 4) * 16);

    const unsigned* Mb = g_Mh + (size_t)b * C_ * 128;
    const bf16* Vb = g_v + (size_t)b * C_ * HW_;

    int lk2 = tid >> 4;
    int lp8 = (tid & 15) * 8;

    uint4 aR[2];
    uint4 vA, vB;
    auto ldg = [&](int kc) {
        int k0 = kc * 32;
#pragma unroll
        for (int i = 0; i < 2; i++) {
            int idx = tid + i * 256;
            int o = idx >> 2, q = idx & 3;
            aR[i] = *reinterpret_cast<const uint4*>(Mb + (size_t)(oBase + o) * 128 + k0 / 2 + q * 4);
        }
        int kk = k0 + 2 * lk2;
        vA = *reinterpret_cast<const uint4*>(Vb + (size_t)kk * HW_ + pBase + lp8);
        vB = *reinterpret_cast<const uint4*>(Vb + (size_t)(kk + 1) * HW_ + pBase + lp8);
    };
    auto sts = [&](int st) {
        unsigned* sA = sm + st * STG_U;
        unsigned* sB = sA + 128 * SA_U;
#pragma unroll
        for (int i = 0; i < 2; i++) {
            int idx = tid + i * 256;
            int o = idx >> 2, q = idx & 3;
            *reinterpret_cast<uint4*>(sA + o * SA_U + q * 4) = aR[i];
        }
        uint4 o0, o1;
        o0.x = __byte_perm(vA.x, vB.x, 0x5410);
        o0.y = __byte_perm(vA.x, vB.x, 0x7632);
        o0.z = __byte_perm(vA.y, vB.y, 0x5410);
        o0.w = __byte_perm(vA.y, vB.y, 0x7632);
        o1.x = __byte_perm(vA.z, vB.z, 0x5410);
        o1.y = __byte_perm(vA.z, vB.z, 0x7632);
        o1.z = __byte_perm(vA.w, vB.w, 0x5410);
        o1.w = __byte_perm(vA.w, vB.w, 0x7632);
        *reinterpret_cast<uint4*>(sB + lk2 * SB_U + lp8) = o0;
        *reinterpret_cast<uint4*>(sB + lk2 * SB_U + lp8 + 4) = o1;
    };

    float acc[4][4][4] = {};
    ldg(0);
    for (int kc = 0; kc < 8; kc++) {
        sts(kc & 1);
        __syncthreads();
        if (kc < 7) ldg(kc + 1);
        uint32_t sAaddr = smBase + (kc & 1) * STG_U * 4;
        unsigned* sB = sm + (kc & 1) * STG_U + 128 * SA_U;
#pragma unroll
        for (int s2 = 0; s2 < 16; s2 += 8) {
            unsigned afr[4][4];
#pragma unroll
            for (int mt = 0; mt < 4; mt++)
                ldsm_x4(afr[mt], sAaddr + (uint32_t)((oW + mt * 16) * SA_U + s2) * 4 + aRowOff);
#pragma unroll
            for (int nt = 0; nt < 4; nt++) {
                int cp = pW + nt * 8 + g;
                unsigned b0 = sB[(s2 + tig) * SB_U + cp];
                unsigned b1 = sB[(s2 + 4 + tig) * SB_U + cp];
#pragma unroll
                for (int mt = 0; mt < 4; mt++)
                    mma_bf16(acc[mt][nt], afr[mt], b0, b1);
            }
        }
        __syncthreads();
    }

    const bf16* PEb = g_pe + (size_t)b * C_ * HW_;
    const float* HXb = hx + (size_t)b * C_ * HW_;
#pragma unroll
    for (int mt = 0; mt < 4; mt++) {
        int o0 = oBase + oW + mt * 16 + g;
        int o1 = o0 + 8;
        float b0v = bias[o0], b1v = bias[o1];
#pragma unroll
        for (int nt = 0; nt < 4; nt++) {
            int p = pBase + pW + nt * 8 + 2 * tig;
            float2 h0 = *reinterpret_cast<const float2*>(HXb + (size_t)o0 * HW_ + p);
            float2 h1 = *reinterpret_cast<const float2*>(HXb + (size_t)o1 * HW_ + p);
            float2 pf0 = __bfloat1622float2(
                *reinterpret_cast<const bf162*>(PEb + (size_t)o0 * HW_ + p));
            float2 pf1 = __bfloat1622float2(
                *reinterpret_cast<const bf162*>(PEb + (size_t)o1 * HW_ + p));
            float2 r0, r1;
            r0.x = acc[mt][nt][0] + b0v + pf0.x + h0.x;
            r0.y = acc[mt][nt][1] + b0v + pf0.y + h0.y;
            r1.x = acc[mt][nt][2] + b1v + pf1.x + h1.x;
            r1.y = acc[mt][nt][3] + b1v + pf1.y + h1.y;
            *reinterpret_cast<float2*>(out + ((size_t)b * C_ + o0) * HW_ + p) = r0;
            *reinterpret_cast<float2*>(out + ((size_t)b * C_ + o1) * HW_ + p) = r1;
        }
    }
}

// -----------------------------------------------------------------------------
extern "C" void kernel_launch(void* const* d_in, const int* in_sizes, int n_in,
                              void* d_out, int out_size) {
    const float* x = (const float*)d_in[0];
    const float* hx = (const float*)d_in[1];
    const float* ln1_w = (const float*)d_in[2];
    const float* ln1_b = (const float*)d_in[3];
    const float* ln2_w = (const float*)d_in[4];
    const float* ln2_b = (const float*)d_in[5];
    const float* q_w = (const float*)d_in[6];
    const float* q_b = (const float*)d_in[7];
    const float* q_dw_w = (const float*)d_in[8];
    const float* q_dw_b = (const float*)d_in[9];
    const float* kv_w = (const float*)d_in[10];
    const float* kv_b = (const float*)d_in[11];
    const float* kv_dw_w = (const float*)d_in[12];
    const float* kv_dw_b = (const float*)d_in[13];
    const float* ao_w = (const float*)d_in[14];
    const float* ao_b = (const float*)d_in[15];
    const float* pe1_w = (const float*)d_in[16];
    const float* pe2_w = (const float*)d_in[17];
    const float* temperature = (const float*)d_in[18];
    float* out = (float*)d_out;

    unsigned *p_Wqh, *p_Wkvh;
    float *p_bq, *p_bkv, *p_rsq, *p_rskv;
    bf16 *p_bufA, *p_bufB;
    cudaGetSymbolAddress((void**)&p_Wqh, g_Wqh);
    cudaGetSymbolAddress((void**)&p_Wkvh, g_Wkvh);
    cudaGetSymbolAddress((void**)&p_bq, g_bq);
    cudaGetSymbolAddress((void**)&p_bkv, g_bkv);
    cudaGetSymbolAddress((void**)&p_rsq, g_rsq);
    cudaGetSymbolAddress((void**)&p_rskv, g_rskv);
    cudaGetSymbolAddress((void**)&p_bufA, g_bufA);
    cudaGetSymbolAddress((void**)&p_bufB, g_bufB);

    // 1. fold LN into weights (pack bf16 pairs); zero sumsq accumulators
    prep_w_kernel<<<3 * C_, 256>>>(q_w, q_b, ln1_w, ln1_b, kv_w, kv_b, ln2_w, ln2_b);

    // 2. q_pre = conv1x1(ln(x)) -> bufA ; kv_pre = conv1x1(ln(hx)) -> bufB
    {
        GemmArgs ga{};
        ga.X = x; ga.Wh = p_Wqh; ga.bias = p_bq; ga.rsum = p_rsq;
        ga.Yh = p_bufA; ga.O = C_;
        gemm_lnh_kernel<<<dim3(C_ / 128, HW_ / 128, B_), 256>>>(ga);
    }
    {
        GemmArgs ga{};
        ga.X = hx; ga.Wh = p_Wkvh; ga.bias = p_bkv; ga.rsum = p_rskv;
        ga.Yh = p_bufB; ga.O = 2 * C_;
        gemm_lnh_kernel<<<dim3(2 * C_ / 128, HW_ / 128, B_), 256>>>(ga);
    }

    // 3. merged stencils: q-dw, k-dw, v-dw + positional branch (one launch)
    dwvpe_kernel<<<dim3(8, 3 * C_, B_), 256>>>(q_dw_w, q_dw_b, kv_dw_w, kv_dw_b, pe1_w, pe2_w);

    // 4. gram (bf16 mma, split-K=4), softmax with fused norms
    gram_mma<<<dim3(GSEG, HEADS_, B_), 256>>>();
    softmax_kernel<<<B_ * HEADS_, 32>>>(temperature);

    // 5. fold attn into output projection; final fused GEMM
    buildM_kernel<<<dim3(HEADS_, B_), 256>>>(ao_w);
    gemm_outh_kernel<<<dim3(C_ / 128, HW_ / 128, B_), 256>>>(ao_b, hx, out);
}

// round 12
// speedup vs baseline: 1.0639x; 1.0639x over previous
#include <cuda_runtime.h>
#include <cuda_bf16.h>
#include <math.h>
#include <stdint.h>

#define B_ 8
#define C_ 256
#define H_ 128
#define W_ 128
#define HW_ 16384
#define HEADS_ 8
#define HD_ 32
#define GSEG 4

typedef __nv_bfloat16 bf16;
typedef __nv_bfloat162 bf162;

// ---------------- scratch (device globals; no allocation allowed) ------------
__device__ bf16 g_bufA[B_ * C_ * HW_];           // q_pre
__device__ bf16 g_bufB[B_ * 2 * C_ * HW_];       // kv_pre
__device__ bf16 g_q[B_ * C_ * HW_];
__device__ bf16 g_k[B_ * C_ * HW_];
__device__ bf16 g_v[B_ * C_ * HW_];
__device__ bf16 g_pe[B_ * C_ * HW_];             // pemb (WITHOUT hx)
__device__ unsigned g_Wqh[C_ * 128];             // bf16-pair packed folded weights
__device__ unsigned g_Wkvh[2 * C_ * 128];
__device__ unsigned g_Mh[B_ * C_ * 128];         // packed M = ao_w @ blockdiag(attn)
__device__ float g_bq[C_];
__device__ float g_bkv[2 * C_];
__device__ float g_rsq[C_];
__device__ float g_rskv[2 * C_];
__device__ float g_ss[2 * B_ * C_];
__device__ float g_part[B_ * HEADS_ * GSEG * 1024];
__device__ float g_attn[B_ * HEADS_ * 1024];

// ---------------- helpers ------------------------------------------------
__device__ __forceinline__ void mma_bf16(float* c, const unsigned* a, unsigned b0, unsigned b1) {
    asm volatile(
        "mma.sync.aligned.m16n8k16.row.col.f32.bf16.bf16.f32 "
        "{%0,%1,%2,%3}, {%4,%5,%6,%7}, {%8,%9}, {%0,%1,%2,%3};\n"
        : "+f"(c[0]), "+f"(c[1]), "+f"(c[2]), "+f"(c[3])
        : "r"(a[0]), "r"(a[1]), "r"(a[2]), "r"(a[3]), "r"(b0), "r"(b1));
}
__device__ __forceinline__ void ldsm_x4(unsigned* r, uint32_t addr) {
    asm volatile("ldmatrix.sync.aligned.m8n8.x4.shared.b16 {%0,%1,%2,%3}, [%4];"
                 : "=r"(r[0]), "=r"(r[1]), "=r"(r[2]), "=r"(r[3])
                 : "r"(addr));
}
__device__ __forceinline__ uint32_t smem_u32(const void* p) {
    return (uint32_t)__cvta_generic_to_shared(p);
}
__device__ __forceinline__ unsigned packbf(float lo, float hi) {
    bf162 t = __floats2bfloat162_rn(lo, hi);
    return *reinterpret_cast<unsigned*>(&t);
}
__device__ __forceinline__ float gelu_tanh(float s) {
    float x3 = s * s * s;
    return 0.5f * s * (1.f + tanhf(0.7978845608028654f * (s + 0.044715f * x3)));
}
__device__ __forceinline__ void u4_to_f8(uint4 u, float4& lo, float4& hi) {
    bf162 h0 = *reinterpret_cast<bf162*>(&u.x);
    bf162 h1 = *reinterpret_cast<bf162*>(&u.y);
    bf162 h2 = *reinterpret_cast<bf162*>(&u.z);
    bf162 h3 = *reinterpret_cast<bf162*>(&u.w);
    float2 f0 = __bfloat1622float2(h0), f1 = __bfloat1622float2(h1);
    float2 f2 = __bfloat1622float2(h2), f3 = __bfloat1622float2(h3);
    lo = make_float4(f0.x, f0.y, f1.x, f1.y);
    hi = make_float4(f2.x, f2.y, f3.x, f3.y);
}
__device__ __forceinline__ uint4 f8_to_u4(const float* o) {
    uint4 r;
    r.x = packbf(o[0], o[1]);
    r.y = packbf(o[2], o[3]);
    r.z = packbf(o[4], o[5]);
    r.w = packbf(o[6], o[7]);
    return r;
}

// 8-wide 3-tap over a padded smem row (data at +4; pads zero at 0..3 / 132..135)
__device__ __forceinline__ void stencil8(const float* R, int s, float w0, float w1, float w2,
                                         float* o) {
    float4 m0 = *reinterpret_cast<const float4*>(R + 4 + s);
    float4 m1 = *reinterpret_cast<const float4*>(R + 8 + s);
    float l = R[3 + s], r = R[12 + s];
    o[0] += w0 * l    + w1 * m0.x + w2 * m0.y;
    o[1] += w0 * m0.x + w1 * m0.y + w2 * m0.z;
    o[2] += w0 * m0.y + w1 * m0.z + w2 * m0.w;
    o[3] += w0 * m0.z + w1 * m0.w + w2 * m1.x;
    o[4] += w0 * m0.w + w1 * m1.x + w2 * m1.y;
    o[5] += w0 * m1.x + w1 * m1.y + w2 * m1.z;
    o[6] += w0 * m1.y + w1 * m1.z + w2 * m1.w;
    o[7] += w0 * m1.z + w1 * m1.w + w2 * r;
}

// single-pass fill of N padded rows from bf16 global
template <int NROWS>
__device__ __forceinline__ void fill_rows(float (*dst)[136], const bf16* src, int r0, int roff,
                                          int tid) {
    float4 z4 = make_float4(0.f, 0.f, 0.f, 0.f);
    for (int i = tid; i < NROWS * 16; i += 256) {
        int row = i >> 4, c8 = (i & 15) * 8;
        int gr = r0 + roff + row;
        float4 lo = z4, hi = z4;
        if (gr >= 0 && gr < H_) {
            uint4 u = *reinterpret_cast<const uint4*>(src + (size_t)gr * W_ + c8);
            u4_to_f8(u, lo, hi);
        }
        *reinterpret_cast<float4*>(&dst[row][4 + c8]) = lo;
        *reinterpret_cast<float4*>(&dst[row][8 + c8]) = hi;
    }
    for (int i = tid; i < NROWS * 2; i += 256) {
        int row = i >> 1;
        *reinterpret_cast<float4*>(&dst[row][(i & 1) ? 132 : 0]) = z4;
    }
}

// ---------------- weight prep: fold LN gamma/beta, pack to bf16 pairs --------
__global__ void prep_w_kernel(const float* __restrict__ qw, const float* __restrict__ qb,
                              const float* __restrict__ ln1w, const float* __restrict__ ln1b,
                              const float* __restrict__ kvw, const float* __restrict__ kvb,
                              const float* __restrict__ ln2w, const float* __restrict__ ln2b) {
    int r = blockIdx.x;
    int tid = threadIdx.x;
    if (r < 16) g_ss[r * 256 + tid] = 0.f;
    const float *w, *lnw, *lnb;
    float cb;
    unsigned* dWh;
    float *dB, *dR;
    if (r < C_) {
        int o = r;
        w = qw + (size_t)o * C_; lnw = ln1w; lnb = ln1b; cb = qb[o];
        dWh = g_Wqh + (size_t)o * 128; dB = g_bq + o; dR = g_rsq + o;
    } else {
        int o = r - C_;
        w = kvw + (size_t)o * C_; lnw = ln2w; lnb = ln2b; cb = kvb[o];
        dWh = g_Wkvh + (size_t)o * 128; dB = g_bkv + o; dR = g_rskv + o;
    }
    float wv = w[tid];
    float we = wv * lnw[tid];
    float we_r = __bfloat162float(__float2bfloat16(we));
    __shared__ float shw[256], sh1[256], sh2[256];
    shw[tid] = we_r;
    sh1[tid] = we_r;
    sh2[tid] = wv * lnb[tid];
    __syncthreads();
    if (tid < 128) dWh[tid] = packbf(shw[2 * tid], shw[2 * tid + 1]);
    for (int s = 128; s > 0; s >>= 1) {
        if (tid < s) { sh1[tid] += sh1[tid + s]; sh2[tid] += sh2[tid + s]; }
        __syncthreads();
    }
    if (tid == 0) { *dR = sh1[0]; *dB = cb + sh2[0]; }
}

// ========= LN-fused GEMM: bf16 m16n8k16 + ldmatrix, fp32 X pack ==============
struct GemmArgs {
    const float* X;
    const unsigned* Wh;
    const float* bias;
    const float* rsum;
    bf16* Yh;
    int O;
};

#define SA_U 20
#define SB_U 136
#define STG_U (128 * SA_U + 16 * SB_U)   // 4736 uints / stage

__global__ __launch_bounds__(256, 2) void gemm_lnh_kernel(GemmArgs ga) {
    __shared__ unsigned sm[2 * STG_U];
    __shared__ float sS[8][128], sQ[8][128];
    int b = blockIdx.z;
    int oBase = blockIdx.x * 128;
    int pBase = blockIdx.y * 128;
    int tid = threadIdx.x;
    int wid = tid >> 5, lane = tid & 31;
    int g = lane >> 2, tig = lane & 3;
    int oW = (wid >> 2) * 64;
    int pW = (wid & 3) * 32;
    uint32_t smBase = smem_u32(sm);
    uint32_t aRowOff = (uint32_t)((lane & 15) * SA_U * 4 + (lane >> 4) * 16);

    const float* Xb = ga.X + (size_t)b * C_ * HW_;
    const unsigned* Wb = ga.Wh;

    int lk2 = tid >> 5;
    int lp0 = (tid & 31) * 4;

    uint4 wR[2];
    float4 xR[2][2];
    auto ldg = [&](int kc) {
        int k0 = kc * 32;
#pragma unroll
        for (int i = 0; i < 2; i++) {
            int idx = tid + i * 256;
            int o = idx >> 2, q = idx & 3;
            wR[i] = *reinterpret_cast<const uint4*>(Wb + (size_t)(oBase + o) * 128 + k0 / 2 + q * 4);
        }
#pragma unroll
        for (int i = 0; i < 2; i++) {
            int kk = k0 + 2 * (lk2 + i * 8);
            xR[i][0] = *reinterpret_cast<const float4*>(Xb + (size_t)kk * HW_ + pBase + lp0);
            xR[i][1] = *reinterpret_cast<const float4*>(Xb + (size_t)(kk + 1) * HW_ + pBase + lp0);
        }
    };
    float stS[4] = {}, stQ[4] = {};
    auto sts = [&](int st) {
        unsigned* sA = sm + st * STG_U;
        unsigned* sB = sA + 128 * SA_U;
#pragma unroll
        for (int i = 0; i < 2; i++) {
            int idx = tid + i * 256;
            int o = idx >> 2, q = idx & 3;
            *reinterpret_cast<uint4*>(sA + o * SA_U + q * 4) = wR[i];
        }
#pragma unroll
        for (int i = 0; i < 2; i++) {
            float4 a = xR[i][0], c = xR[i][1];
            stS[0] += a.x + c.x; stQ[0] += a.x * a.x + c.x * c.x;
            stS[1] += a.y + c.y; stQ[1] += a.y * a.y + c.y * c.y;
            stS[2] += a.z + c.z; stQ[2] += a.z * a.z + c.z * c.z;
            stS[3] += a.w + c.w; stQ[3] += a.w * a.w + c.w * c.w;
            uint4 u;
            u.x = packbf(a.x, c.x);
            u.y = packbf(a.y, c.y);
            u.z = packbf(a.z, c.z);
            u.w = packbf(a.w, c.w);
            *reinterpret_cast<uint4*>(sB + (lk2 + i * 8) * SB_U + lp0) = u;
        }
    };

    float acc[4][4][4] = {};
    ldg(0);
    for (int kc = 0; kc < 8; kc++) {
        sts(kc & 1);
        __syncthreads();
        if (kc < 7) ldg(kc + 1);
        uint32_t sAaddr = smBase + (kc & 1) * STG_U * 4;
        unsigned* sB = sm + (kc & 1) * STG_U + 128 * SA_U;
#pragma unroll
        for (int s2 = 0; s2 < 16; s2 += 8) {
            unsigned afr[4][4];
#pragma unroll
            for (int mt = 0; mt < 4; mt++)
                ldsm_x4(afr[mt], sAaddr + (uint32_t)((oW + mt * 16) * SA_U + s2) * 4 + aRowOff);
#pragma unroll
            for (int nt = 0; nt < 4; nt++) {
                int cp = pW + nt * 8 + g;
                unsigned b0 = sB[(s2 + tig) * SB_U + cp];
                unsigned b1 = sB[(s2 + 4 + tig) * SB_U + cp];
#pragma unroll
                for (int mt = 0; mt < 4; mt++)
                    mma_bf16(acc[mt][nt], afr[mt], b0, b1);
            }
        }
        __syncthreads();
    }

    *reinterpret_cast<float4*>(&sS[lk2][lp0]) = make_float4(stS[0], stS[1], stS[2], stS[3]);
    *reinterpret_cast<float4*>(&sQ[lk2][lp0]) = make_float4(stQ[0], stQ[1], stQ[2], stQ[3]);
    __syncthreads();
    float mu[4][2], iv[4][2];
#pragma unroll
    for (int nt = 0; nt < 4; nt++) {
#pragma unroll
        for (int u = 0; u < 2; u++) {
            int pl = pW + nt * 8 + 2 * tig + u;
            float s0 = 0.f, q0 = 0.f;
#pragma unroll
            for (int wrow = 0; wrow < 8; wrow++) { s0 += sS[wrow][pl]; q0 += sQ[wrow][pl]; }
            float m = s0 * (1.f / 256.f);
            float var = q0 * (1.f / 256.f) - m * m;
            mu[nt][u] = m;
            iv[nt][u] = rsqrtf(var + 1e-5f);
        }
    }
#pragma unroll
    for (int mt = 0; mt < 4; mt++) {
        int o0 = oBase + oW + mt * 16 + g;
        int o1 = o0 + 8;
        float rs0 = ga.rsum[o0], b0v = ga.bias[o0];
        float rs1 = ga.rsum[o1], b1v = ga.bias[o1];
#pragma unroll
        for (int nt = 0; nt < 4; nt++) {
            int p = pBase + pW + nt * 8 + 2 * tig;
            bf162 r0 = __floats2bfloat162_rn(
                iv[nt][0] * (acc[mt][nt][0] - mu[nt][0] * rs0) + b0v,
                iv[nt][1] * (acc[mt][nt][1] - mu[nt][1] * rs0) + b0v);
            bf162 r1 = __floats2bfloat162_rn(
                iv[nt][0] * (acc[mt][nt][2] - mu[nt][0] * rs1) + b1v,
                iv[nt][1] * (acc[mt][nt][3] - mu[nt][1] * rs1) + b1v);
            *reinterpret_cast<bf162*>(ga.Yh + ((size_t)b * ga.O + o0) * HW_ + p) = r0;
            *reinterpret_cast<bf162*>(ga.Yh + ((size_t)b * ga.O + o1) * HW_ + p) = r1;
        }
    }
}

// ===== merged q+k register-strip depthwise 3x3 (+bias, +sumsq), no smem =======
// thread: 4x8 output patch; streams 6 input rows through registers.
__global__ __launch_bounds__(256, 4) void dwqk_kernel(const float* __restrict__ qw9,
                                                      const float* __restrict__ qb,
                                                      const float* __restrict__ kvw9,
                                                      const float* __restrict__ kvb) {
    int b = blockIdx.z, ci = blockIdx.y;
    int tid = threadIdx.x;
    int cg = tid & 15, rg = tid >> 4;
    int c0 = cg * 8, r0 = blockIdx.x * 64 + rg * 4;

    const bf16* Xc;
    const float* w9;
    const float* bp;
    bf16* D;
    float* ssq;
    if (ci < C_) {
        Xc = g_bufA + ((size_t)(b * C_ + ci)) * HW_;
        w9 = qw9 + (size_t)ci * 9;
        bp = qb + ci;
        D = g_q + ((size_t)(b * C_ + ci)) * HW_;
        ssq = &g_ss[b * C_ + ci];
    } else {
        int c = ci - C_;
        Xc = g_bufB + ((size_t)(b * 2 * C_ + c)) * HW_;
        w9 = kvw9 + (size_t)c * 9;
        bp = kvb + c;
        D = g_k + ((size_t)(b * C_ + c)) * HW_;
        ssq = &g_ss[B_ * C_ + b * C_ + c];
    }
    float wk[9];
#pragma unroll
    for (int t = 0; t < 9; t++) wk[t] = __ldg(w9 + t);
    float bv = __ldg(bp);

    float acc[4][8];
#pragma unroll
    for (int r = 0; r < 4; r++)
#pragma unroll
        for (int u = 0; u < 8; u++) acc[r][u] = bv;
#pragma unroll
    for (int t = 0; t < 6; t++) {
        int ir = r0 - 1 + t;
        float f[10];
#pragma unroll
        for (int u = 0; u < 10; u++) f[u] = 0.f;
        if (ir >= 0 && ir < H_) {
            uint4 u4 = *reinterpret_cast<const uint4*>(Xc + (size_t)ir * W_ + c0);
            float4 lo, hi;
            u4_to_f8(u4, lo, hi);
            f[1] = lo.x; f[2] = lo.y; f[3] = lo.z; f[4] = lo.w;
            f[5] = hi.x; f[6] = hi.y; f[7] = hi.z; f[8] = hi.w;
            if (c0 > 0) f[0] = __bfloat162float(__ldg(Xc + (size_t)ir * W_ + c0 - 1));
            if (c0 + 8 < W_) f[9] = __bfloat162float(__ldg(Xc + (size_t)ir * W_ + c0 + 8));
        }
        if (t >= 2) {
#pragma unroll
            for (int u = 0; u < 8; u++)
                acc[t - 2][u] += wk[6] * f[u] + wk[7] * f[u + 1] + wk[8] * f[u + 2];
        }
        if (t >= 1 && t <= 4) {
#pragma unroll
            for (int u = 0; u < 8; u++)
                acc[t - 1][u] += wk[3] * f[u] + wk[4] * f[u + 1] + wk[5] * f[u + 2];
        }
        if (t <= 3) {
#pragma unroll
            for (int u = 0; u < 8; u++)
                acc[t][u] += wk[0] * f[u] + wk[1] * f[u + 1] + wk[2] * f[u + 2];
        }
    }
    float ss = 0.f;
#pragma unroll
    for (int r = 0; r < 4; r++) {
        *reinterpret_cast<uint4*>(D + (size_t)(r0 + r) * W_ + c0) = f8_to_u4(acc[r]);
#pragma unroll
        for (int u = 0; u < 8; u++) ss += acc[r][u] * acc[r][u];
    }
#pragma unroll
    for (int d = 16; d > 0; d >>= 1) ss += __shfl_down_sync(0xffffffffu, ss, d);
    if ((tid & 31) == 0) atomicAdd(ssq, ss);
}

// ------------- v dwconv + positional branch -----------------------------------
__global__ __launch_bounds__(256) void vpe_kernel(const float* __restrict__ kvw9,
                                                  const float* __restrict__ kvb,
                                                  const float* __restrict__ pe1,
                                                  const float* __restrict__ pe2) {
    __shared__ float sbuf[(22 + 20) * 136];
    float (*svi)[136] = reinterpret_cast<float(*)[136]>(sbuf);
    float (*sv)[136]  = reinterpret_cast<float(*)[136]>(sbuf + 22 * 136);
    float (*st1)[136] = svi;
    int b = blockIdx.z, c = blockIdx.y, r0 = blockIdx.x * 16;
    int tid = threadIdx.x;
    const bf16* Vc = g_bufB + ((size_t)(b * 2 * C_ + C_ + c)) * HW_;
    fill_rows<22>(svi, Vc, r0, -3, tid);
    {
        float4 z4 = make_float4(0.f, 0.f, 0.f, 0.f);
        for (int i = tid; i < 20 * 2; i += 256)
            *reinterpret_cast<float4*>(&sv[i >> 1][(i & 1) ? 132 : 0]) = z4;
    }
    float wkv[9], w1[9], w2[9];
#pragma unroll
    for (int t = 0; t < 9; t++) {
        wkv[t] = __ldg(kvw9 + (size_t)(C_ + c) * 9 + t);
        w1[t] = __ldg(pe1 + (size_t)c * 9 + t);
        w2[t] = __ldg(pe2 + (size_t)c * 9 + t);
    }
    float bvv = __ldg(kvb + C_ + c);
    __syncthreads();

    int row0 = tid >> 4, s0 = (tid & 15) * 8;

    bf16* Dv = g_v + ((size_t)(b * C_ + c)) * HW_;
    for (int i = tid; i < 20 * 16; i += 256) {
        int row = i >> 4, cc = (i & 15) * 8;
        int gr = r0 - 2 + row;
        float o[8] = {};
        if (gr >= 0 && gr < H_) {
#pragma unroll
            for (int u = 0; u < 8; u++) o[u] = bvv;
#pragma unroll
            for (int dr = 0; dr < 3; dr++)
                stencil8(svi[row + dr], cc, wkv[dr * 3], wkv[dr * 3 + 1], wkv[dr * 3 + 2], o);
        }
        *reinterpret_cast<float4*>(&sv[row][4 + cc]) = make_float4(o[0], o[1], o[2], o[3]);
        *reinterpret_cast<float4*>(&sv[row][8 + cc]) = make_float4(o[4], o[5], o[6], o[7]);
        if (row >= 2 && row < 18)
            *reinterpret_cast<uint4*>(Dv + (size_t)gr * W_ + cc) = f8_to_u4(o);
    }
    __syncthreads();

    for (int i = tid; i < 18 * 16; i += 256) {
        int row = i >> 4, cc = (i & 15) * 8;
        int gr = r0 - 1 + row;
        float o[8] = {};
        if (gr >= 0 && gr < H_) {
#pragma unroll
            for (int dr = 0; dr < 3; dr++)
                stencil8(sv[row + dr], cc, w1[dr * 3], w1[dr * 3 + 1], w1[dr * 3 + 2], o);
#pragma unroll
            for (int u = 0; u < 8; u++) o[u] = gelu_tanh(o[u]);
        }
        *reinterpret_cast<float4*>(&st1[row][4 + cc]) = make_float4(o[0], o[1], o[2], o[3]);
        *reinterpret_cast<float4*>(&st1[row][8 + cc]) = make_float4(o[4], o[5], o[6], o[7]);
    }
    __syncthreads();

    bf16* Dp = g_pe + ((size_t)(b * C_ + c)) * HW_;
    {
        float o[8] = {};
#pragma unroll
        for (int dr = 0; dr < 3; dr++)
            stencil8(st1[row0 + dr], s0, w2[dr * 3], w2[dr * 3 + 1], w2[dr * 3 + 2], o);
        *reinterpret_cast<uint4*>(Dp + (size_t)(r0 + row0) * W_ + s0) = f8_to_u4(o);
    }
}

// ---------------- gram via bf16 mma m16n8k16, split-K=4 ----------------------
__global__ __launch_bounds__(256) void gram_mma() {
    __shared__ float sbuf[8192];
    bf16* sqh = reinterpret_cast<bf16*>(sbuf);
    bf16* skh = sqh + 32 * 136;
    unsigned* squ = reinterpret_cast<unsigned*>(sqh);
    unsigned* sku = reinterpret_cast<unsigned*>(skh);
    int seg = blockIdx.x, h = blockIdx.y, b = blockIdx.z;
    const bf16* Q = g_q + ((size_t)(b * C_ + h * HD_)) * HW_;
    const bf16* K = g_k + ((size_t)(b * C_ + h * HD_)) * HW_;
    int tid = threadIdx.x, wid = tid >> 5, lane = tid & 31;
    int g = lane >> 2, tig = lane & 3;
    float acc[2][4][4] = {};
    int n0 = seg * (HW_ / GSEG);
    int klu = wid * 8;
    for (int ch = 0; ch < (HW_ / GSEG) / 128; ch++) {
        int base = n0 + ch * 128;
        for (int i = tid; i < 32 * 16; i += 256) {
            int row = i >> 4, c8 = (i & 15) * 8;
            *reinterpret_cast<uint4*>(sqh + row * 136 + c8) =
                *reinterpret_cast<const uint4*>(Q + (size_t)row * HW_ + base + c8);
            *reinterpret_cast<uint4*>(skh + row * 136 + c8) =
                *reinterpret_cast<const uint4*>(K + (size_t)row * HW_ + base + c8);
        }
        __syncthreads();
        unsigned afr[2][4];
#pragma unroll
        for (int mt = 0; mt < 2; mt++) {
            int r = mt * 16 + g;
            afr[mt][0] = squ[r * 68 + klu + tig];
            afr[mt][1] = squ[(r + 8) * 68 + klu + tig];
            afr[mt][2] = squ[r * 68 + klu + 4 + tig];
            afr[mt][3] = squ[(r + 8) * 68 + klu + 4 + tig];
        }
#pragma unroll
        for (int nt = 0; nt < 4; nt++) {
            unsigned b0 = sku[(nt * 8 + g) * 68 + klu + tig];
            unsigned b1 = sku[(nt * 8 + g) * 68 + klu + 4 + tig];
#pragma unroll
            for (int mt = 0; mt < 2; mt++)
                mma_bf16(acc[mt][nt], afr[mt], b0, b1);
        }
        __syncthreads();
    }
    float* red = sbuf;
#pragma unroll
    for (int mt = 0; mt < 2; mt++)
#pragma unroll
        for (int nt = 0; nt < 4; nt++) {
            int r = mt * 16 + g, cl = nt * 8 + 2 * tig;
            red[wid * 1024 + r * 32 + cl] = acc[mt][nt][0];
            red[wid * 1024 + r * 32 + cl + 1] = acc[mt][nt][1];
            red[wid * 1024 + (r + 8) * 32 + cl] = acc[mt][nt][2];
            red[wid * 1024 + (r + 8) * 32 + cl + 1] = acc[mt][nt][3];
        }
    __syncthreads();
    float* outp = g_part + ((size_t)(b * HEADS_ + h) * GSEG + seg) * 1024;
    for (int i = tid; i < 1024; i += 256) {
        float s = 0.f;
#pragma unroll
        for (int w = 0; w < 8; w++) s += red[w * 1024 + i];
        outp[i] = s;
    }
}

// ---------------- softmax with fused q/k norm scales + temperature -----------
__global__ void softmax_kernel(const float* __restrict__ temp) {
    int bh = blockIdx.x;
    int b = bh >> 3, h = bh & 7;
    int i = threadIdx.x;
    float qs = 1.f / fmaxf(sqrtf(g_ss[b * C_ + h * HD_ + i]), 1e-12f);
    float T = __ldg(temp + h);
    float v[32];
    float mx = -1e30f;
#pragma unroll 4
    for (int j = 0; j < 32; j++) {
        float s = 0.f;
#pragma unroll
        for (int seg = 0; seg < GSEG; seg++)
            s += g_part[((size_t)bh * GSEG + seg) * 1024 + i * 32 + j];
        float ks = 1.f / fmaxf(sqrtf(g_ss[B_ * C_ + b * C_ + h * HD_ + j]), 1e-12f);
        float val = s * qs * ks * T;
        v[j] = val;
        mx = fmaxf(mx, val);
    }
    float sum = 0.f;
#pragma unroll
    for (int j = 0; j < 32; j++) {
        v[j] = expf(v[j] - mx);
        sum += v[j];
    }
    float inv = 1.f / sum;
#pragma unroll
    for (int j = 0; j < 32; j++) g_attn[bh * 1024 + i * 32 + j] = v[j] * inv;
}

// ------------ M[b] = ao_w @ blockdiag(attn[b]), packed bf16 pairs ------------
__global__ void buildM_kernel(const float* __restrict__ ao_w) {
    int h = blockIdx.x, b = blockIdx.y;
    int tid = threadIdx.x;
    __shared__ float sa[32][33];
#pragma unroll
    for (int t = 0; t < 4; t++) {
        int idx = tid + t * 256;
        sa[idx >> 5][idx & 31] = g_attn[(b * HEADS_ + h) * 1024 + idx];
    }
    __syncthreads();
    float wreg[32];
#pragma unroll
    for (int c = 0; c < 32; c++) wreg[c] = ao_w[(size_t)tid * C_ + h * HD_ + c];
    float m[32];
#pragma unroll 4
    for (int d = 0; d < 32; d++) {
        float s = 0.f;
#pragma unroll
        for (int c = 0; c < 32; c++) s += wreg[c] * sa[c][d];
        m[d] = s;
    }
    unsigned* Mo = g_Mh + ((size_t)(b * C_) + tid) * 128 + h * 16;
#pragma unroll
    for (int j = 0; j < 16; j++) Mo[j] = packbf(m[2 * j], m[2 * j + 1]);
}

// ======= final GEMM: out = M@v + ao_b + pemb + hx (bf16 mma + ldmatrix) ======
__global__ __launch_bounds__(256, 2) void gemm_outh_kernel(const float* __restrict__ bias,
                                                           const float* __restrict__ hx,
                                                           float* __restrict__ out) {
    __shared__ unsigned sm[2 * STG_U];
    int b = blockIdx.z;
    int oBase = blockIdx.x * 128;
    int pBase = blockIdx.y * 128;
    int tid = threadIdx.x;
    int wid = tid >> 5, lane = tid & 31;
    int g = lane >> 2, tig = lane & 3;
    int oW = (wid >> 2) * 64;
    int pW = (wid & 3) * 32;
    uint32_t smBase = smem_u32(sm);
    uint32_t aRowOff = (uint32_t)((lane & 15) * SA_U * 4 + (lane >> 4) * 16);

    const unsigned* Mb = g_Mh + (size_t)b * C_ * 128;
    const bf16* Vb = g_v + (size_t)b * C_ * HW_;

    int lk2 = tid >> 4;
    int lp8 = (tid & 15) * 8;

    uint4 aR[2];
    uint4 vA, vB;
    auto ldg = [&](int kc) {
        int k0 = kc * 32;
#pragma unroll
        for (int i = 0; i < 2; i++) {
            int idx = tid + i * 256;
            int o = idx >> 2, q = idx & 3;
            aR[i] = *reinterpret_cast<const uint4*>(Mb + (size_t)(oBase + o) * 128 + k0 / 2 + q * 4);
        }
        int kk = k0 + 2 * lk2;
        vA = *reinterpret_cast<const uint4*>(Vb + (size_t)kk * HW_ + pBase + lp8);
        vB = *reinterpret_cast<const uint4*>(Vb + (size_t)(kk + 1) * HW_ + pBase + lp8);
    };
    auto sts = [&](int st) {
        unsigned* sA = sm + st * STG_U;
        unsigned* sB = sA + 128 * SA_U;
#pragma unroll
        for (int i = 0; i < 2; i++) {
            int idx = tid + i * 256;
            int o = idx >> 2, q = idx & 3;
            *reinterpret_cast<uint4*>(sA + o * SA_U + q * 4) = aR[i];
        }
        uint4 o0, o1;
        o0.x = __byte_perm(vA.x, vB.x, 0x5410);
        o0.y = __byte_perm(vA.x, vB.x, 0x7632);
        o0.z = __byte_perm(vA.y, vB.y, 0x5410);
        o0.w = __byte_perm(vA.y, vB.y, 0x7632);
        o1.x = __byte_perm(vA.z, vB.z, 0x5410);
        o1.y = __byte_perm(vA.z, vB.z, 0x7632);
        o1.z = __byte_perm(vA.w, vB.w, 0x5410);
        o1.w = __byte_perm(vA.w, vB.w, 0x7632);
        *reinterpret_cast<uint4*>(sB + lk2 * SB_U + lp8) = o0;
        *reinterpret_cast<uint4*>(sB + lk2 * SB_U + lp8 + 4) = o1;
    };

    float acc[4][4][4] = {};
    ldg(0);
    for (int kc = 0; kc < 8; kc++) {
        sts(kc & 1);
        __syncthreads();
        if (kc < 7) ldg(kc + 1);
        uint32_t sAaddr = smBase + (kc & 1) * STG_U * 4;
        unsigned* sB = sm + (kc & 1) * STG_U + 128 * SA_U;
#pragma unroll
        for (int s2 = 0; s2 < 16; s2 += 8) {
            unsigned afr[4][4];
#pragma unroll
            for (int mt = 0; mt < 4; mt++)
                ldsm_x4(afr[mt], sAaddr + (uint32_t)((oW + mt * 16) * SA_U + s2) * 4 + aRowOff);
#pragma unroll
            for (int nt = 0; nt < 4; nt++) {
                int cp = pW + nt * 8 + g;
                unsigned b0 = sB[(s2 + tig) * SB_U + cp];
                unsigned b1 = sB[(s2 + 4 + tig) * SB_U + cp];
#pragma unroll
                for (int mt = 0; mt < 4; mt++)
                    mma_bf16(acc[mt][nt], afr[mt], b0, b1);
            }
        }
        __syncthreads();
    }

    const bf16* PEb = g_pe + (size_t)b * C_ * HW_;
    const float* HXb = hx + (size_t)b * C_ * HW_;
#pragma unroll
    for (int mt = 0; mt < 4; mt++) {
        int o0 = oBase + oW + mt * 16 + g;
        int o1 = o0 + 8;
        float b0v = bias[o0], b1v = bias[o1];
#pragma unroll
        for (int nt = 0; nt < 4; nt++) {
            int p = pBase + pW + nt * 8 + 2 * tig;
            float2 h0 = *reinterpret_cast<const float2*>(HXb + (size_t)o0 * HW_ + p);
            float2 h1 = *reinterpret_cast<const float2*>(HXb + (size_t)o1 * HW_ + p);
            float2 pf0 = __bfloat1622float2(
                *reinterpret_cast<const bf162*>(PEb + (size_t)o0 * HW_ + p));
            float2 pf1 = __bfloat1622float2(
                *reinterpret_cast<const bf162*>(PEb + (size_t)o1 * HW_ + p));
            float2 r0, r1;
            r0.x = acc[mt][nt][0] + b0v + pf0.x + h0.x;
            r0.y = acc[mt][nt][1] + b0v + pf0.y + h0.y;
            r1.x = acc[mt][nt][2] + b1v + pf1.x + h1.x;
            r1.y = acc[mt][nt][3] + b1v + pf1.y + h1.y;
            *reinterpret_cast<float2*>(out + ((size_t)b * C_ + o0) * HW_ + p) = r0;
            *reinterpret_cast<float2*>(out + ((size_t)b * C_ + o1) * HW_ + p) = r1;
        }
    }
}

// -----------------------------------------------------------------------------
extern "C" void kernel_launch(void* const* d_in, const int* in_sizes, int n_in,
                              void* d_out, int out_size) {
    const float* x = (const float*)d_in[0];
    const float* hx = (const float*)d_in[1];
    const float* ln1_w = (const float*)d_in[2];
    const float* ln1_b = (const float*)d_in[3];
    const float* ln2_w = (const float*)d_in[4];
    const float* ln2_b = (const float*)d_in[5];
    const float* q_w = (const float*)d_in[6];
    const float* q_b = (const float*)d_in[7];
    const float* q_dw_w = (const float*)d_in[8];
    const float* q_dw_b = (const float*)d_in[9];
    const float* kv_w = (const float*)d_in[10];
    const float* kv_b = (const float*)d_in[11];
    const float* kv_dw_w = (const float*)d_in[12];
    const float* kv_dw_b = (const float*)d_in[13];
    const float* ao_w = (const float*)d_in[14];
    const float* ao_b = (const float*)d_in[15];
    const float* pe1_w = (const float*)d_in[16];
    const float* pe2_w = (const float*)d_in[17];
    const float* temperature = (const float*)d_in[18];
    float* out = (float*)d_out;

    unsigned *p_Wqh, *p_Wkvh;
    float *p_bq, *p_bkv, *p_rsq, *p_rskv;
    bf16 *p_bufA, *p_bufB;
    cudaGetSymbolAddress((void**)&p_Wqh, g_Wqh);
    cudaGetSymbolAddress((void**)&p_Wkvh, g_Wkvh);
    cudaGetSymbolAddress((void**)&p_bq, g_bq);
    cudaGetSymbolAddress((void**)&p_bkv, g_bkv);
    cudaGetSymbolAddress((void**)&p_rsq, g_rsq);
    cudaGetSymbolAddress((void**)&p_rskv, g_rskv);
    cudaGetSymbolAddress((void**)&p_bufA, g_bufA);
    cudaGetSymbolAddress((void**)&p_bufB, g_bufB);

    // 1. fold LN into weights (pack bf16 pairs); zero sumsq accumulators
    prep_w_kernel<<<3 * C_, 256>>>(q_w, q_b, ln1_w, ln1_b, kv_w, kv_b, ln2_w, ln2_b);

    // 2. q_pre = conv1x1(ln(x)) -> bufA ; kv_pre = conv1x1(ln(hx)) -> bufB
    {
        GemmArgs ga{};
        ga.X = x; ga.Wh = p_Wqh; ga.bias = p_bq; ga.rsum = p_rsq;
        ga.Yh = p_bufA; ga.O = C_;
        gemm_lnh_kernel<<<dim3(C_ / 128, HW_ / 128, B_), 256>>>(ga);
    }
    {
        GemmArgs ga{};
        ga.X = hx; ga.Wh = p_Wkvh; ga.bias = p_bkv; ga.rsum = p_rskv;
        ga.Yh = p_bufB; ga.O = 2 * C_;
        gemm_lnh_kernel<<<dim3(2 * C_ / 128, HW_ / 128, B_), 256>>>(ga);
    }

    // 3. merged q+k dwconvs (register-strip, 4-row patches) -> g_q, g_k (+sumsq)
    dwqk_kernel<<<dim3(2, 2 * C_, B_), 256>>>(q_dw_w, q_dw_b, kv_dw_w, kv_dw_b);

    // 4. v dwconv + positional branch -> g_v, g_pe
    vpe_kernel<<<dim3(8, C_, B_), 256>>>(kv_dw_w, kv_dw_b, pe1_w, pe2_w);

    // 5. gram (bf16 mma, split-K=4), softmax with fused norms
    gram_mma<<<dim3(GSEG, HEADS_, B_), 256>>>();
    softmax_kernel<<<B_ * HEADS_, 32>>>(temperature);

    // 6. fold attn into output projection; final fused GEMM
    buildM_kernel<<<dim3(HEADS_, B_), 256>>>(ao_w);
    gemm_outh_kernel<<<dim3(C_ / 128, HW_ / 128, B_), 256>>>(ao_b, hx, out);
}

// round 13
// speedup vs baseline: 1.1085x; 1.0420x over previous
#include <cuda_runtime.h>
#include <cuda_bf16.h>
#include <math.h>
#include <stdint.h>

#define B_ 8
#define C_ 256
#define H_ 128
#define W_ 128
#define HW_ 16384
#define HEADS_ 8
#define HD_ 32
#define GSEG 4

typedef __nv_bfloat16 bf16;
typedef __nv_bfloat162 bf162;

// ---------------- scratch (device globals; no allocation allowed) ------------
__device__ bf16 g_bufA[B_ * C_ * HW_];           // q_pre
__device__ bf16 g_bufB[B_ * 2 * C_ * HW_];       // kv_pre
__device__ bf16 g_q[B_ * C_ * HW_];
__device__ bf16 g_k[B_ * C_ * HW_];
__device__ bf16 g_v[B_ * C_ * HW_];
__device__ bf16 g_pe[B_ * C_ * HW_];             // pemb (WITHOUT hx)
__device__ unsigned g_Wqh[C_ * 128];             // bf16-pair packed folded weights
__device__ unsigned g_Wkvh[2 * C_ * 128];
__device__ unsigned g_Mh[B_ * C_ * 128];         // packed M = ao_w @ blockdiag(attn)
__device__ float g_bq[C_];
__device__ float g_bkv[2 * C_];
__device__ float g_rsq[C_];
__device__ float g_rskv[2 * C_];
__device__ float g_ss[2 * B_ * C_];
__device__ float g_part[B_ * HEADS_ * GSEG * 1024];
__device__ float g_attn[B_ * HEADS_ * 1024];

// ---------------- helpers ------------------------------------------------
__device__ __forceinline__ void mma_bf16(float* c, const unsigned* a, unsigned b0, unsigned b1) {
    asm volatile(
        "mma.sync.aligned.m16n8k16.row.col.f32.bf16.bf16.f32 "
        "{%0,%1,%2,%3}, {%4,%5,%6,%7}, {%8,%9}, {%0,%1,%2,%3};\n"
        : "+f"(c[0]), "+f"(c[1]), "+f"(c[2]), "+f"(c[3])
        : "r"(a[0]), "r"(a[1]), "r"(a[2]), "r"(a[3]), "r"(b0), "r"(b1));
}
__device__ __forceinline__ void ldsm_x4(unsigned* r, uint32_t addr) {
    asm volatile("ldmatrix.sync.aligned.m8n8.x4.shared.b16 {%0,%1,%2,%3}, [%4];"
                 : "=r"(r[0]), "=r"(r[1]), "=r"(r[2]), "=r"(r[3])
                 : "r"(addr));
}
__device__ __forceinline__ uint32_t smem_u32(const void* p) {
    return (uint32_t)__cvta_generic_to_shared(p);
}
__device__ __forceinline__ unsigned packbf(float lo, float hi) {
    bf162 t = __floats2bfloat162_rn(lo, hi);
    return *reinterpret_cast<unsigned*>(&t);
}
__device__ __forceinline__ float gelu_tanh(float s) {
    float x3 = s * s * s;
    return 0.5f * s * (1.f + tanhf(0.7978845608028654f * (s + 0.044715f * x3)));
}
__device__ __forceinline__ void u4_to_f8(uint4 u, float4& lo, float4& hi) {
    bf162 h0 = *reinterpret_cast<bf162*>(&u.x);
    bf162 h1 = *reinterpret_cast<bf162*>(&u.y);
    bf162 h2 = *reinterpret_cast<bf162*>(&u.z);
    bf162 h3 = *reinterpret_cast<bf162*>(&u.w);
    float2 f0 = __bfloat1622float2(h0), f1 = __bfloat1622float2(h1);
    float2 f2 = __bfloat1622float2(h2), f3 = __bfloat1622float2(h3);
    lo = make_float4(f0.x, f0.y, f1.x, f1.y);
    hi = make_float4(f2.x, f2.y, f3.x, f3.y);
}
__device__ __forceinline__ uint4 f8_to_u4(const float* o) {
    uint4 r;
    r.x = packbf(o[0], o[1]);
    r.y = packbf(o[2], o[3]);
    r.z = packbf(o[4], o[5]);
    r.w = packbf(o[6], o[7]);
    return r;
}

// 8-wide 3-tap over a padded smem row (data at +4; pads zero at 0..3 / 132..135)
__device__ __forceinline__ void stencil8(const float* R, int s, float w0, float w1, float w2,
                                         float* o) {
    float4 m0 = *reinterpret_cast<const float4*>(R + 4 + s);
    float4 m1 = *reinterpret_cast<const float4*>(R + 8 + s);
    float l = R[3 + s], r = R[12 + s];
    o[0] += w0 * l    + w1 * m0.x + w2 * m0.y;
    o[1] += w0 * m0.x + w1 * m0.y + w2 * m0.z;
    o[2] += w0 * m0.y + w1 * m0.z + w2 * m0.w;
    o[3] += w0 * m0.z + w1 * m0.w + w2 * m1.x;
    o[4] += w0 * m0.w + w1 * m1.x + w2 * m1.y;
    o[5] += w0 * m1.x + w1 * m1.y + w2 * m1.z;
    o[6] += w0 * m1.y + w1 * m1.z + w2 * m1.w;
    o[7] += w0 * m1.z + w1 * m1.w + w2 * r;
}

// single-pass fill of N padded rows from bf16 global
template <int NROWS>
__device__ __forceinline__ void fill_rows(float (*dst)[136], const bf16* src, int r0, int roff,
                                          int tid) {
    float4 z4 = make_float4(0.f, 0.f, 0.f, 0.f);
    for (int i = tid; i < NROWS * 16; i += 256) {
        int row = i >> 4, c8 = (i & 15) * 8;
        int gr = r0 + roff + row;
        float4 lo = z4, hi = z4;
        if (gr >= 0 && gr < H_) {
            uint4 u = *reinterpret_cast<const uint4*>(src + (size_t)gr * W_ + c8);
            u4_to_f8(u, lo, hi);
        }
        *reinterpret_cast<float4*>(&dst[row][4 + c8]) = lo;
        *reinterpret_cast<float4*>(&dst[row][8 + c8]) = hi;
    }
    for (int i = tid; i < NROWS * 2; i += 256) {
        int row = i >> 1;
        *reinterpret_cast<float4*>(&dst[row][(i & 1) ? 132 : 0]) = z4;
    }
}

// ---------------- weight prep: fold LN gamma/beta, pack to bf16 pairs --------
__global__ void prep_w_kernel(const float* __restrict__ qw, const float* __restrict__ qb,
                              const float* __restrict__ ln1w, const float* __restrict__ ln1b,
                              const float* __restrict__ kvw, const float* __restrict__ kvb,
                              const float* __restrict__ ln2w, const float* __restrict__ ln2b) {
    int r = blockIdx.x;
    int tid = threadIdx.x;
    if (r < 16) g_ss[r * 256 + tid] = 0.f;
    const float *w, *lnw, *lnb;
    float cb;
    unsigned* dWh;
    float *dB, *dR;
    if (r < C_) {
        int o = r;
        w = qw + (size_t)o * C_; lnw = ln1w; lnb = ln1b; cb = qb[o];
        dWh = g_Wqh + (size_t)o * 128; dB = g_bq + o; dR = g_rsq + o;
    } else {
        int o = r - C_;
        w = kvw + (size_t)o * C_; lnw = ln2w; lnb = ln2b; cb = kvb[o];
        dWh = g_Wkvh + (size_t)o * 128; dB = g_bkv + o; dR = g_rskv + o;
    }
    float wv = w[tid];
    float we = wv * lnw[tid];
    float we_r = __bfloat162float(__float2bfloat16(we));
    __shared__ float shw[256], sh1[256], sh2[256];
    shw[tid] = we_r;
    sh1[tid] = we_r;
    sh2[tid] = wv * lnb[tid];
    __syncthreads();
    if (tid < 128) dWh[tid] = packbf(shw[2 * tid], shw[2 * tid + 1]);
    for (int s = 128; s > 0; s >>= 1) {
        if (tid < s) { sh1[tid] += sh1[tid + s]; sh2[tid] += sh2[tid + s]; }
        __syncthreads();
    }
    if (tid == 0) { *dR = sh1[0]; *dB = cb + sh2[0]; }
}

// ========= LN-fused GEMM: bf16 m16n8k16 + ldmatrix, fp32 X pack ==============
struct GemmArgs {
    const float* X;
    const unsigned* Wh;
    const float* bias;
    const float* rsum;
    bf16* Yh;
    int O;
};

#define SA_U 20
#define SB_U 136
#define STG_U (128 * SA_U + 16 * SB_U)   // 4736 uints / stage

__global__ __launch_bounds__(256, 2) void gemm_lnh_kernel(GemmArgs ga) {
    __shared__ unsigned sm[2 * STG_U];
    __shared__ float sS[8][128], sQ[8][128];
    int b = blockIdx.z;
    int oBase = blockIdx.x * 128;
    int pBase = blockIdx.y * 128;
    int tid = threadIdx.x;
    int wid = tid >> 5, lane = tid & 31;
    int g = lane >> 2, tig = lane & 3;
    int oW = (wid >> 2) * 64;
    int pW = (wid & 3) * 32;
    uint32_t smBase = smem_u32(sm);
    uint32_t aRowOff = (uint32_t)((lane & 15) * SA_U * 4 + (lane >> 4) * 16);

    const float* Xb = ga.X + (size_t)b * C_ * HW_;
    const unsigned* Wb = ga.Wh;

    int lk2 = tid >> 5;
    int lp0 = (tid & 31) * 4;

    uint4 wR[2];
    float4 xR[2][2];
    auto ldg = [&](int kc) {
        int k0 = kc * 32;
#pragma unroll
        for (int i = 0; i < 2; i++) {
            int idx = tid + i * 256;
            int o = idx >> 2, q = idx & 3;
            wR[i] = *reinterpret_cast<const uint4*>(Wb + (size_t)(oBase + o) * 128 + k0 / 2 + q * 4);
        }
#pragma unroll
        for (int i = 0; i < 2; i++) {
            int kk = k0 + 2 * (lk2 + i * 8);
            xR[i][0] = *reinterpret_cast<const float4*>(Xb + (size_t)kk * HW_ + pBase + lp0);
            xR[i][1] = *reinterpret_cast<const float4*>(Xb + (size_t)(kk + 1) * HW_ + pBase + lp0);
        }
    };
    float stS[4] = {}, stQ[4] = {};
    auto sts = [&](int st) {
        unsigned* sA = sm + st * STG_U;
        unsigned* sB = sA + 128 * SA_U;
#pragma unroll
        for (int i = 0; i < 2; i++) {
            int idx = tid + i * 256;
            int o = idx >> 2, q = idx & 3;
            *reinterpret_cast<uint4*>(sA + o * SA_U + q * 4) = wR[i];
        }
#pragma unroll
        for (int i = 0; i < 2; i++) {
            float4 a = xR[i][0], c = xR[i][1];
            stS[0] += a.x + c.x; stQ[0] += a.x * a.x + c.x * c.x;
            stS[1] += a.y + c.y; stQ[1] += a.y * a.y + c.y * c.y;
            stS[2] += a.z + c.z; stQ[2] += a.z * a.z + c.z * c.z;
            stS[3] += a.w + c.w; stQ[3] += a.w * a.w + c.w * c.w;
            uint4 u;
            u.x = packbf(a.x, c.x);
            u.y = packbf(a.y, c.y);
            u.z = packbf(a.z, c.z);
            u.w = packbf(a.w, c.w);
            *reinterpret_cast<uint4*>(sB + (lk2 + i * 8) * SB_U + lp0) = u;
        }
    };

    float acc[4][4][4] = {};
    ldg(0);
    for (int kc = 0; kc < 8; kc++) {
        sts(kc & 1);
        __syncthreads();
        if (kc < 7) ldg(kc + 1);
        uint32_t sAaddr = smBase + (kc & 1) * STG_U * 4;
        unsigned* sB = sm + (kc & 1) * STG_U + 128 * SA_U;
#pragma unroll
        for (int s2 = 0; s2 < 16; s2 += 8) {
            unsigned afr[4][4];
#pragma unroll
            for (int mt = 0; mt < 4; mt++)
                ldsm_x4(afr[mt], sAaddr + (uint32_t)((oW + mt * 16) * SA_U + s2) * 4 + aRowOff);
#pragma unroll
            for (int nt = 0; nt < 4; nt++) {
                int cp = pW + nt * 8 + g;
                unsigned b0 = sB[(s2 + tig) * SB_U + cp];
                unsigned b1 = sB[(s2 + 4 + tig) * SB_U + cp];
#pragma unroll
                for (int mt = 0; mt < 4; mt++)
                    mma_bf16(acc[mt][nt], afr[mt], b0, b1);
            }
        }
        // NOTE: no trailing sync — ping-pong buffers make it redundant
        // (sts(kc+1) writes the buffer last read at compute(kc-1), which all
        //  warps finished before passing the sync above).
    }

    __syncthreads();
    *reinterpret_cast<float4*>(&sS[lk2][lp0]) = make_float4(stS[0], stS[1], stS[2], stS[3]);
    *reinterpret_cast<float4*>(&sQ[lk2][lp0]) = make_float4(stQ[0], stQ[1], stQ[2], stQ[3]);
    __syncthreads();
    float mu[4][2], iv[4][2];
#pragma unroll
    for (int nt = 0; nt < 4; nt++) {
#pragma unroll
        for (int u = 0; u < 2; u++) {
            int pl = pW + nt * 8 + 2 * tig + u;
            float s0 = 0.f, q0 = 0.f;
#pragma unroll
            for (int wrow = 0; wrow < 8; wrow++) { s0 += sS[wrow][pl]; q0 += sQ[wrow][pl]; }
            float m = s0 * (1.f / 256.f);
            float var = q0 * (1.f / 256.f) - m * m;
            mu[nt][u] = m;
            iv[nt][u] = rsqrtf(var + 1e-5f);
        }
    }
#pragma unroll
    for (int mt = 0; mt < 4; mt++) {
        int o0 = oBase + oW + mt * 16 + g;
        int o1 = o0 + 8;
        float rs0 = ga.rsum[o0], b0v = ga.bias[o0];
        float rs1 = ga.rsum[o1], b1v = ga.bias[o1];
#pragma unroll
        for (int nt = 0; nt < 4; nt++) {
            int p = pBase + pW + nt * 8 + 2 * tig;
            bf162 r0 = __floats2bfloat162_rn(
                iv[nt][0] * (acc[mt][nt][0] - mu[nt][0] * rs0) + b0v,
                iv[nt][1] * (acc[mt][nt][1] - mu[nt][1] * rs0) + b0v);
            bf162 r1 = __floats2bfloat162_rn(
                iv[nt][0] * (acc[mt][nt][2] - mu[nt][0] * rs1) + b1v,
                iv[nt][1] * (acc[mt][nt][3] - mu[nt][1] * rs1) + b1v);
            *reinterpret_cast<bf162*>(ga.Yh + ((size_t)b * ga.O + o0) * HW_ + p) = r0;
            *reinterpret_cast<bf162*>(ga.Yh + ((size_t)b * ga.O + o1) * HW_ + p) = r1;
        }
    }
}

// ===== merged q+k register-strip depthwise 3x3 (+bias, +sumsq), no smem =======
__global__ __launch_bounds__(256, 4) void dwqk_kernel(const float* __restrict__ qw9,
                                                      const float* __restrict__ qb,
                                                      const float* __restrict__ kvw9,
                                                      const float* __restrict__ kvb) {
    int b = blockIdx.z, ci = blockIdx.y;
    int tid = threadIdx.x;
    int cg = tid & 15, rg = tid >> 4;
    int c0 = cg * 8, r0 = blockIdx.x * 64 + rg * 4;

    const bf16* Xc;
    const float* w9;
    const float* bp;
    bf16* D;
    float* ssq;
    if (ci < C_) {
        Xc = g_bufA + ((size_t)(b * C_ + ci)) * HW_;
        w9 = qw9 + (size_t)ci * 9;
        bp = qb + ci;
        D = g_q + ((size_t)(b * C_ + ci)) * HW_;
        ssq = &g_ss[b * C_ + ci];
    } else {
        int c = ci - C_;
        Xc = g_bufB + ((size_t)(b * 2 * C_ + c)) * HW_;
        w9 = kvw9 + (size_t)c * 9;
        bp = kvb + c;
        D = g_k + ((size_t)(b * C_ + c)) * HW_;
        ssq = &g_ss[B_ * C_ + b * C_ + c];
    }
    float wk[9];
#pragma unroll
    for (int t = 0; t < 9; t++) wk[t] = __ldg(w9 + t);
    float bv = __ldg(bp);

    float acc[4][8];
#pragma unroll
    for (int r = 0; r < 4; r++)
#pragma unroll
        for (int u = 0; u < 8; u++) acc[r][u] = bv;
#pragma unroll
    for (int t = 0; t < 6; t++) {
        int ir = r0 - 1 + t;
        float f[10];
#pragma unroll
        for (int u = 0; u < 10; u++) f[u] = 0.f;
        if (ir >= 0 && ir < H_) {
            uint4 u4 = *reinterpret_cast<const uint4*>(Xc + (size_t)ir * W_ + c0);
            float4 lo, hi;
            u4_to_f8(u4, lo, hi);
            f[1] = lo.x; f[2] = lo.y; f[3] = lo.z; f[4] = lo.w;
            f[5] = hi.x; f[6] = hi.y; f[7] = hi.z; f[8] = hi.w;
            if (c0 > 0) f[0] = __bfloat162float(__ldg(Xc + (size_t)ir * W_ + c0 - 1));
            if (c0 + 8 < W_) f[9] = __bfloat162float(__ldg(Xc + (size_t)ir * W_ + c0 + 8));
        }
        if (t >= 2) {
#pragma unroll
            for (int u = 0; u < 8; u++)
                acc[t - 2][u] += wk[6] * f[u] + wk[7] * f[u + 1] + wk[8] * f[u + 2];
        }
        if (t >= 1 && t <= 4) {
#pragma unroll
            for (int u = 0; u < 8; u++)
                acc[t - 1][u] += wk[3] * f[u] + wk[4] * f[u + 1] + wk[5] * f[u + 2];
        }
        if (t <= 3) {
#pragma unroll
            for (int u = 0; u < 8; u++)
                acc[t][u] += wk[0] * f[u] + wk[1] * f[u + 1] + wk[2] * f[u + 2];
        }
    }
    float ss = 0.f;
#pragma unroll
    for (int r = 0; r < 4; r++) {
        *reinterpret_cast<uint4*>(D + (size_t)(r0 + r) * W_ + c0) = f8_to_u4(acc[r]);
#pragma unroll
        for (int u = 0; u < 8; u++) ss += acc[r][u] * acc[r][u];
    }
#pragma unroll
    for (int d = 16; d > 0; d >>= 1) ss += __shfl_down_sync(0xffffffffu, ss, d);
    if ((tid & 31) == 0) atomicAdd(ssq, ss);
}

// ------------- v dwconv + positional branch (32-row tiles) --------------------
__global__ __launch_bounds__(256) void vpe_kernel(const float* __restrict__ kvw9,
                                                  const float* __restrict__ kvb,
                                                  const float* __restrict__ pe1,
                                                  const float* __restrict__ pe2) {
    __shared__ float sbuf[(38 + 36) * 136];
    float (*svi)[136] = reinterpret_cast<float(*)[136]>(sbuf);            // 38 rows
    float (*sv)[136]  = reinterpret_cast<float(*)[136]>(sbuf + 38 * 136); // 36 rows
    float (*st1)[136] = svi;                                              // alias (34 rows)
    int b = blockIdx.z, c = blockIdx.y, r0 = blockIdx.x * 32;
    int tid = threadIdx.x;
    const bf16* Vc = g_bufB + ((size_t)(b * 2 * C_ + C_ + c)) * HW_;
    fill_rows<38>(svi, Vc, r0, -3, tid);
    {
        float4 z4 = make_float4(0.f, 0.f, 0.f, 0.f);
        for (int i = tid; i < 36 * 2; i += 256)
            *reinterpret_cast<float4*>(&sv[i >> 1][(i & 1) ? 132 : 0]) = z4;
    }
    float wkv[9], w1[9], w2[9];
#pragma unroll
    for (int t = 0; t < 9; t++) {
        wkv[t] = __ldg(kvw9 + (size_t)(C_ + c) * 9 + t);
        w1[t] = __ldg(pe1 + (size_t)c * 9 + t);
        w2[t] = __ldg(pe2 + (size_t)c * 9 + t);
    }
    float bvv = __ldg(kvb + C_ + c);
    __syncthreads();

    int row0 = tid >> 4, s0 = (tid & 15) * 8;

    // v: 36 rows (incl. 2-row halo each side); write global rows r0..r0+31
    bf16* Dv = g_v + ((size_t)(b * C_ + c)) * HW_;
    for (int i = tid; i < 36 * 16; i += 256) {
        int row = i >> 4, cc = (i & 15) * 8;
        int gr = r0 - 2 + row;
        float o[8] = {};
        if (gr >= 0 && gr < H_) {
#pragma unroll
            for (int u = 0; u < 8; u++) o[u] = bvv;
#pragma unroll
            for (int dr = 0; dr < 3; dr++)
                stencil8(svi[row + dr], cc, wkv[dr * 3], wkv[dr * 3 + 1], wkv[dr * 3 + 2], o);
        }
        *reinterpret_cast<float4*>(&sv[row][4 + cc]) = make_float4(o[0], o[1], o[2], o[3]);
        *reinterpret_cast<float4*>(&sv[row][8 + cc]) = make_float4(o[4], o[5], o[6], o[7]);
        if (row >= 2 && row < 34)
            *reinterpret_cast<uint4*>(Dv + (size_t)gr * W_ + cc) = f8_to_u4(o);
    }
    __syncthreads();

    // t1 = gelu(dw(v, pe1)): 34 rows (incl. 1-row halo) -> st1 (aliases svi)
    for (int i = tid; i < 34 * 16; i += 256) {
        int row = i >> 4, cc = (i & 15) * 8;
        int gr = r0 - 1 + row;
        float o[8] = {};
        if (gr >= 0 && gr < H_) {
#pragma unroll
            for (int dr = 0; dr < 3; dr++)
                stencil8(sv[row + dr], cc, w1[dr * 3], w1[dr * 3 + 1], w1[dr * 3 + 2], o);
#pragma unroll
            for (int u = 0; u < 8; u++) o[u] = gelu_tanh(o[u]);
        }
        *reinterpret_cast<float4*>(&st1[row][4 + cc]) = make_float4(o[0], o[1], o[2], o[3]);
        *reinterpret_cast<float4*>(&st1[row][8 + cc]) = make_float4(o[4], o[5], o[6], o[7]);
    }
    __syncthreads();

    // pe: 32 rows, 2 per thread
    bf16* Dp = g_pe + ((size_t)(b * C_ + c)) * HW_;
#pragma unroll
    for (int it = 0; it < 2; it++) {
        int row = row0 + it * 16;
        float o[8] = {};
#pragma unroll
        for (int dr = 0; dr < 3; dr++)
            stencil8(st1[row + dr], s0, w2[dr * 3], w2[dr * 3 + 1], w2[dr * 3 + 2], o);
        *reinterpret_cast<uint4*>(Dp + (size_t)(r0 + row) * W_ + s0) = f8_to_u4(o);
    }
}

// ---------------- gram via bf16 mma m16n8k16, double-buffered, split-K=4 ------
__global__ __launch_bounds__(256) void gram_mma() {
    __shared__ float sbuf[8704];   // 34816 B: 2 stages of (q 32x136 + k 32x136) bf16
    bf16* tile = reinterpret_cast<bf16*>(sbuf);
    // stage s: q at tile + s*2*4352, k at tile + s*2*4352 + 4352
    int seg = blockIdx.x, h = blockIdx.y, b = blockIdx.z;
    const bf16* Q = g_q + ((size_t)(b * C_ + h * HD_)) * HW_;
    const bf16* K = g_k + ((size_t)(b * C_ + h * HD_)) * HW_;
    int tid = threadIdx.x, wid = tid >> 5, lane = tid & 31;
    int g = lane >> 2, tig = lane & 3;
    float acc[2][4][4] = {};
    int n0 = seg * (HW_ / GSEG);
    int klu = wid * 8;

    auto load = [&](int ch, int st) {
        int base = n0 + ch * 128;
        bf16* sq = tile + st * 8704;
        bf16* sk = sq + 4352;
        for (int i = tid; i < 32 * 16; i += 256) {
            int row = i >> 4, c8 = (i & 15) * 8;
            *reinterpret_cast<uint4*>(sq + row * 136 + c8) =
                *reinterpret_cast<const uint4*>(Q + (size_t)row * HW_ + base + c8);
            *reinterpret_cast<uint4*>(sk + row * 136 + c8) =
                *reinterpret_cast<const uint4*>(K + (size_t)row * HW_ + base + c8);
        }
    };

    load(0, 0);
    const int NCH = (HW_ / GSEG) / 128;   // 32
    for (int ch = 0; ch < NCH; ch++) {
        __syncthreads();
        if (ch + 1 < NCH) load(ch + 1, (ch + 1) & 1);
        unsigned* squ = reinterpret_cast<unsigned*>(tile + (ch & 1) * 8704);
        unsigned* sku = squ + 2176;
        unsigned afr[2][4];
#pragma unroll
        for (int mt = 0; mt < 2; mt++) {
            int r = mt * 16 + g;
            afr[mt][0] = squ[r * 68 + klu + tig];
            afr[mt][1] = squ[(r + 8) * 68 + klu + tig];
            afr[mt][2] = squ[r * 68 + klu + 4 + tig];
            afr[mt][3] = squ[(r + 8) * 68 + klu + 4 + tig];
        }
#pragma unroll
        for (int nt = 0; nt < 4; nt++) {
            unsigned b0 = sku[(nt * 8 + g) * 68 + klu + tig];
            unsigned b1 = sku[(nt * 8 + g) * 68 + klu + 4 + tig];
#pragma unroll
            for (int mt = 0; mt < 2; mt++)
                mma_bf16(acc[mt][nt], afr[mt], b0, b1);
        }
    }
    __syncthreads();
    float* red = sbuf;
#pragma unroll
    for (int mt = 0; mt < 2; mt++)
#pragma unroll
        for (int nt = 0; nt < 4; nt++) {
            int r = mt * 16 + g, cl = nt * 8 + 2 * tig;
            red[wid * 1024 + r * 32 + cl] = acc[mt][nt][0];
            red[wid * 1024 + r * 32 + cl + 1] = acc[mt][nt][1];
            red[wid * 1024 + (r + 8) * 32 + cl] = acc[mt][nt][2];
            red[wid * 1024 + (r + 8) * 32 + cl + 1] = acc[mt][nt][3];
        }
    __syncthreads();
    float* outp = g_part + ((size_t)(b * HEADS_ + h) * GSEG + seg) * 1024;
    for (int i = tid; i < 1024; i += 256) {
        float s = 0.f;
#pragma unroll
        for (int w = 0; w < 8; w++) s += red[w * 1024 + i];
        outp[i] = s;
    }
}

// ---------------- softmax with fused q/k norm scales + temperature -----------
__global__ void softmax_kernel(const float* __restrict__ temp) {
    int bh = blockIdx.x;
    int b = bh >> 3, h = bh & 7;
    int i = threadIdx.x;
    float qs = 1.f / fmaxf(sqrtf(g_ss[b * C_ + h * HD_ + i]), 1e-12f);
    float T = __ldg(temp + h);
    float v[32];
    float mx = -1e30f;
#pragma unroll 4
    for (int j = 0; j < 32; j++) {
        float s = 0.f;
#pragma unroll
        for (int seg = 0; seg < GSEG; seg++)
            s += g_part[((size_t)bh * GSEG + seg) * 1024 + i * 32 + j];
        float ks = 1.f / fmaxf(sqrtf(g_ss[B_ * C_ + b * C_ + h * HD_ + j]), 1e-12f);
        float val = s * qs * ks * T;
        v[j] = val;
        mx = fmaxf(mx, val);
    }
    float sum = 0.f;
#pragma unroll
    for (int j = 0; j < 32; j++) {
        v[j] = expf(v[j] - mx);
        sum += v[j];
    }
    float inv = 1.f / sum;
#pragma unroll
    for (int j = 0; j < 32; j++) g_attn[bh * 1024 + i * 32 + j] = v[j] * inv;
}

// ------------ M[b] = ao_w @ blockdiag(attn[b]), packed bf16 pairs ------------
__global__ void buildM_kernel(const float* __restrict__ ao_w) {
    int h = blockIdx.x, b = blockIdx.y;
    int tid = threadIdx.x;
    __shared__ float sa[32][33];
#pragma unroll
    for (int t = 0; t < 4; t++) {
        int idx = tid + t * 256;
        sa[idx >> 5][idx & 31] = g_attn[(b * HEADS_ + h) * 1024 + idx];
    }
    __syncthreads();
    float wreg[32];
#pragma unroll
    for (int c = 0; c < 32; c++) wreg[c] = ao_w[(size_t)tid * C_ + h * HD_ + c];
    float m[32];
#pragma unroll 4
    for (int d = 0; d < 32; d++) {
        float s = 0.f;
#pragma unroll
        for (int c = 0; c < 32; c++) s += wreg[c] * sa[c][d];
        m[d] = s;
    }
    unsigned* Mo = g_Mh + ((size_t)(b * C_) + tid) * 128 + h * 16;
#pragma unroll
    for (int j = 0; j < 16; j++) Mo[j] = packbf(m[2 * j], m[2 * j + 1]);
}

// ======= final GEMM: out = M@v + ao_b + pemb + hx (bf16 mma + ldmatrix) ======
__global__ __launch_bounds__(256, 2) void gemm_outh_kernel(const float* __restrict__ bias,
                                                           const float* __restrict__ hx,
                                                           float* __restrict__ out) {
    __shared__ unsigned sm[2 * STG_U];
    int b = blockIdx.z;
    int oBase = blockIdx.x * 128;
    int pBase = blockIdx.y * 128;
    int tid = threadIdx.x;
    int wid = tid >> 5, lane = tid & 31;
    int g = lane >> 2, tig = lane & 3;
    int oW = (wid >> 2) * 64;
    int pW = (wid & 3) * 32;
    uint32_t smBase = smem_u32(sm);
    uint32_t aRowOff = (uint32_t)((lane & 15) * SA_U * 4 + (lane >> 4) * 16);

    const unsigned* Mb = g_Mh + (size_t)b * C_ * 128;
    const bf16* Vb = g_v + (size_t)b * C_ * HW_;

    int lk2 = tid >> 4;
    int lp8 = (tid & 15) * 8;

    uint4 aR[2];
    uint4 vA, vB;
    auto ldg = [&](int kc) {
        int k0 = kc * 32;
#pragma unroll
        for (int i = 0; i < 2; i++) {
            int idx = tid + i * 256;
            int o = idx >> 2, q = idx & 3;
            aR[i] = *reinterpret_cast<const uint4*>(Mb + (size_t)(oBase + o) * 128 + k0 / 2 + q * 4);
        }
        int kk = k0 + 2 * lk2;
        vA = *reinterpret_cast<const uint4*>(Vb + (size_t)kk * HW_ + pBase + lp8);
        vB = *reinterpret_cast<const uint4*>(Vb + (size_t)(kk + 1) * HW_ + pBase + lp8);
    };
    auto sts = [&](int st) {
        unsigned* sA = sm + st * STG_U;
        unsigned* sB = sA + 128 * SA_U;
#pragma unroll
        for (int i = 0; i < 2; i++) {
            int idx = tid + i * 256;
            int o = idx >> 2, q = idx & 3;
            *reinterpret_cast<uint4*>(sA + o * SA_U + q * 4) = aR[i];
        }
        uint4 o0, o1;
        o0.x = __byte_perm(vA.x, vB.x, 0x5410);
        o0.y = __byte_perm(vA.x, vB.x, 0x7632);
        o0.z = __byte_perm(vA.y, vB.y, 0x5410);
        o0.w = __byte_perm(vA.y, vB.y, 0x7632);
        o1.x = __byte_perm(vA.z, vB.z, 0x5410);
        o1.y = __byte_perm(vA.z, vB.z, 0x7632);
        o1.z = __byte_perm(vA.w, vB.w, 0x5410);
        o1.w = __byte_perm(vA.w, vB.w, 0x7632);
        *reinterpret_cast<uint4*>(sB + lk2 * SB_U + lp8) = o0;
        *reinterpret_cast<uint4*>(sB + lk2 * SB_U + lp8 + 4) = o1;
    };

    float acc[4][4][4] = {};
    ldg(0);
    for (int kc = 0; kc < 8; kc++) {
        sts(kc & 1);
        __syncthreads();
        if (kc < 7) ldg(kc + 1);
        uint32_t sAaddr = smBase + (kc & 1) * STG_U * 4;
        unsigned* sB = sm + (kc & 1) * STG_U + 128 * SA_U;
#pragma unroll
        for (int s2 = 0; s2 < 16; s2 += 8) {
            unsigned afr[4][4];
#pragma unroll
            for (int mt = 0; mt < 4; mt++)
                ldsm_x4(afr[mt], sAaddr + (uint32_t)((oW + mt * 16) * SA_U + s2) * 4 + aRowOff);
#pragma unroll
            for (int nt = 0; nt < 4; nt++) {
                int cp = pW + nt * 8 + g;
                unsigned b0 = sB[(s2 + tig) * SB_U + cp];
                unsigned b1 = sB[(s2 + 4 + tig) * SB_U + cp];
#pragma unroll
                for (int mt = 0; mt < 4; mt++)
                    mma_bf16(acc[mt][nt], afr[mt], b0, b1);
            }
        }
        // no trailing sync (ping-pong safe; see gemm_lnh_kernel)
    }

    const bf16* PEb = g_pe + (size_t)b * C_ * HW_;
    const float* HXb = hx + (size_t)b * C_ * HW_;
#pragma unroll
    for (int mt = 0; mt < 4; mt++) {
        int o0 = oBase + oW + mt * 16 + g;
        int o1 = o0 + 8;
        float b0v = bias[o0], b1v = bias[o1];
#pragma unroll
        for (int nt = 0; nt < 4; nt++) {
            int p = pBase + pW + nt * 8 + 2 * tig;
            float2 h0 = *reinterpret_cast<const float2*>(HXb + (size_t)o0 * HW_ + p);
            float2 h1 = *reinterpret_cast<const float2*>(HXb + (size_t)o1 * HW_ + p);
            float2 pf0 = __bfloat1622float2(
                *reinterpret_cast<const bf162*>(PEb + (size_t)o0 * HW_ + p));
            float2 pf1 = __bfloat1622float2(
                *reinterpret_cast<const bf162*>(PEb + (size_t)o1 * HW_ + p));
            float2 r0, r1;
            r0.x = acc[mt][nt][0] + b0v + pf0.x + h0.x;
            r0.y = acc[mt][nt][1] + b0v + pf0.y + h0.y;
            r1.x = acc[mt][nt][2] + b1v + pf1.x + h1.x;
            r1.y = acc[mt][nt][3] + b1v + pf1.y + h1.y;
            *reinterpret_cast<float2*>(out + ((size_t)b * C_ + o0) * HW_ + p) = r0;
            *reinterpret_cast<float2*>(out + ((size_t)b * C_ + o1) * HW_ + p) = r1;
        }
    }
}

// -----------------------------------------------------------------------------
extern "C" void kernel_launch(void* const* d_in, const int* in_sizes, int n_in,
                              void* d_out, int out_size) {
    const float* x = (const float*)d_in[0];
    const float* hx = (const float*)d_in[1];
    const float* ln1_w = (const float*)d_in[2];
    const float* ln1_b = (const float*)d_in[3];
    const float* ln2_w = (const float*)d_in[4];
    const float* ln2_b = (const float*)d_in[5];
    const float* q_w = (const float*)d_in[6];
    const float* q_b = (const float*)d_in[7];
    const float* q_dw_w = (const float*)d_in[8];
    const float* q_dw_b = (const float*)d_in[9];
    const float* kv_w = (const float*)d_in[10];
    const float* kv_b = (const float*)d_in[11];
    const float* kv_dw_w = (const float*)d_in[12];
    const float* kv_dw_b = (const float*)d_in[13];
    const float* ao_w = (const float*)d_in[14];
    const float* ao_b = (const float*)d_in[15];
    const float* pe1_w = (const float*)d_in[16];
    const float* pe2_w = (const float*)d_in[17];
    const float* temperature = (const float*)d_in[18];
    float* out = (float*)d_out;

    unsigned *p_Wqh, *p_Wkvh;
    float *p_bq, *p_bkv, *p_rsq, *p_rskv;
    bf16 *p_bufA, *p_bufB;
    cudaGetSymbolAddress((void**)&p_Wqh, g_Wqh);
    cudaGetSymbolAddress((void**)&p_Wkvh, g_Wkvh);
    cudaGetSymbolAddress((void**)&p_bq, g_bq);
    cudaGetSymbolAddress((void**)&p_bkv, g_bkv);
    cudaGetSymbolAddress((void**)&p_rsq, g_rsq);
    cudaGetSymbolAddress((void**)&p_rskv, g_rskv);
    cudaGetSymbolAddress((void**)&p_bufA, g_bufA);
    cudaGetSymbolAddress((void**)&p_bufB, g_bufB);

    // 1. fold LN into weights (pack bf16 pairs); zero sumsq accumulators
    prep_w_kernel<<<3 * C_, 256>>>(q_w, q_b, ln1_w, ln1_b, kv_w, kv_b, ln2_w, ln2_b);

    // 2. q_pre = conv1x1(ln(x)) -> bufA ; kv_pre = conv1x1(ln(hx)) -> bufB
    {
        GemmArgs ga{};
        ga.X = x; ga.Wh = p_Wqh; ga.bias = p_bq; ga.rsum = p_rsq;
        ga.Yh = p_bufA; ga.O = C_;
        gemm_lnh_kernel<<<dim3(C_ / 128, HW_ / 128, B_), 256>>>(ga);
    }
    {
        GemmArgs ga{};
        ga.X = hx; ga.Wh = p_Wkvh; ga.bias = p_bkv; ga.rsum = p_rskv;
        ga.Yh = p_bufB; ga.O = 2 * C_;
        gemm_lnh_kernel<<<dim3(2 * C_ / 128, HW_ / 128, B_), 256>>>(ga);
    }

    // 3. merged q+k dwconvs (register-strip, 4-row patches) -> g_q, g_k (+sumsq)
    dwqk_kernel<<<dim3(2, 2 * C_, B_), 256>>>(q_dw_w, q_dw_b, kv_dw_w, kv_dw_b);

    // 4. v dwconv + positional branch (32-row tiles) -> g_v, g_pe
    vpe_kernel<<<dim3(4, C_, B_), 256>>>(kv_dw_w, kv_dw_b, pe1_w, pe2_w);

    // 5. gram (bf16 mma, double-buffered, split-K=4), softmax with fused norms
    gram_mma<<<dim3(GSEG, HEADS_, B_), 256>>>();
    softmax_kernel<<<B_ * HEADS_, 32>>>(temperature);

    // 6. fold attn into output projection; final fused GEMM
    buildM_kernel<<<dim3(HEADS_, B_), 256>>>(ao_w);
    gemm_outh_kernel<<<dim3(C_ / 128, HW_ / 128, B_), 256>>>(ao_b, hx, out);
}

// round 14
// speedup vs baseline: 1.1116x; 1.0028x over previous
#include <cuda_runtime.h>
#include <cuda_bf16.h>
#include <math.h>
#include <stdint.h>

#define B_ 8
#define C_ 256
#define H_ 128
#define W_ 128
#define HW_ 16384
#define HEADS_ 8
#define HD_ 32
#define GSEG 8

typedef __nv_bfloat16 bf16;
typedef __nv_bfloat162 bf162;

// ---------------- scratch (device globals; no allocation allowed) ------------
__device__ bf16 g_bufA[B_ * C_ * HW_];           // q_pre
__device__ bf16 g_bufB[B_ * 2 * C_ * HW_];       // kv_pre
__device__ bf16 g_q[B_ * C_ * HW_];
__device__ bf16 g_k[B_ * C_ * HW_];
__device__ bf16 g_v[B_ * C_ * HW_];
__device__ bf16 g_pe[B_ * C_ * HW_];             // pemb (WITHOUT hx)
__device__ unsigned g_Wqh[C_ * 128];             // bf16-pair packed folded weights
__device__ unsigned g_Wkvh[2 * C_ * 128];
__device__ unsigned g_Mh[B_ * C_ * 128];         // packed M = ao_w @ blockdiag(attn)
__device__ float g_bq[C_];
__device__ float g_bkv[2 * C_];
__device__ float g_rsq[C_];
__device__ float g_rskv[2 * C_];
__device__ float g_ss[2 * B_ * C_];
__device__ float g_part[B_ * HEADS_ * GSEG * 1024];

// ---------------- helpers ------------------------------------------------
__device__ __forceinline__ void mma_bf16(float* c, const unsigned* a, unsigned b0, unsigned b1) {
    asm volatile(
        "mma.sync.aligned.m16n8k16.row.col.f32.bf16.bf16.f32 "
        "{%0,%1,%2,%3}, {%4,%5,%6,%7}, {%8,%9}, {%0,%1,%2,%3};\n"
        : "+f"(c[0]), "+f"(c[1]), "+f"(c[2]), "+f"(c[3])
        : "r"(a[0]), "r"(a[1]), "r"(a[2]), "r"(a[3]), "r"(b0), "r"(b1));
}
__device__ __forceinline__ void ldsm_x4(unsigned* r, uint32_t addr) {
    asm volatile("ldmatrix.sync.aligned.m8n8.x4.shared.b16 {%0,%1,%2,%3}, [%4];"
                 : "=r"(r[0]), "=r"(r[1]), "=r"(r[2]), "=r"(r[3])
                 : "r"(addr));
}
__device__ __forceinline__ uint32_t smem_u32(const void* p) {
    return (uint32_t)__cvta_generic_to_shared(p);
}
__device__ __forceinline__ unsigned packbf(float lo, float hi) {
    bf162 t = __floats2bfloat162_rn(lo, hi);
    return *reinterpret_cast<unsigned*>(&t);
}
__device__ __forceinline__ float gelu_tanh(float s) {
    float x3 = s * s * s;
    return 0.5f * s * (1.f + tanhf(0.7978845608028654f * (s + 0.044715f * x3)));
}
__device__ __forceinline__ void u4_to_f8(uint4 u, float4& lo, float4& hi) {
    bf162 h0 = *reinterpret_cast<bf162*>(&u.x);
    bf162 h1 = *reinterpret_cast<bf162*>(&u.y);
    bf162 h2 = *reinterpret_cast<bf162*>(&u.z);
    bf162 h3 = *reinterpret_cast<bf162*>(&u.w);
    float2 f0 = __bfloat1622float2(h0), f1 = __bfloat1622float2(h1);
    float2 f2 = __bfloat1622float2(h2), f3 = __bfloat1622float2(h3);
    lo = make_float4(f0.x, f0.y, f1.x, f1.y);
    hi = make_float4(f2.x, f2.y, f3.x, f3.y);
}
__device__ __forceinline__ uint4 f8_to_u4(const float* o) {
    uint4 r;
    r.x = packbf(o[0], o[1]);
    r.y = packbf(o[2], o[3]);
    r.z = packbf(o[4], o[5]);
    r.w = packbf(o[6], o[7]);
    return r;
}

// 8-wide 3-tap over a padded smem row (data at +4; pads zero at 0..3 / 132..135)
__device__ __forceinline__ void stencil8(const float* R, int s, float w0, float w1, float w2,
                                         float* o) {
    float4 m0 = *reinterpret_cast<const float4*>(R + 4 + s);
    float4 m1 = *reinterpret_cast<const float4*>(R + 8 + s);
    float l = R[3 + s], r = R[12 + s];
    o[0] += w0 * l    + w1 * m0.x + w2 * m0.y;
    o[1] += w0 * m0.x + w1 * m0.y + w2 * m0.z;
    o[2] += w0 * m0.y + w1 * m0.z + w2 * m0.w;
    o[3] += w0 * m0.z + w1 * m0.w + w2 * m1.x;
    o[4] += w0 * m0.w + w1 * m1.x + w2 * m1.y;
    o[5] += w0 * m1.x + w1 * m1.y + w2 * m1.z;
    o[6] += w0 * m1.y + w1 * m1.z + w2 * m1.w;
    o[7] += w0 * m1.z + w1 * m1.w + w2 * r;
}

// single-pass fill of N padded rows from bf16 global
template <int NROWS>
__device__ __forceinline__ void fill_rows(float (*dst)[136], const bf16* src, int r0, int roff,
                                          int tid) {
    float4 z4 = make_float4(0.f, 0.f, 0.f, 0.f);
    for (int i = tid; i < NROWS * 16; i += 256) {
        int row = i >> 4, c8 = (i & 15) * 8;
        int gr = r0 + roff + row;
        float4 lo = z4, hi = z4;
        if (gr >= 0 && gr < H_) {
            uint4 u = *reinterpret_cast<const uint4*>(src + (size_t)gr * W_ + c8);
            u4_to_f8(u, lo, hi);
        }
        *reinterpret_cast<float4*>(&dst[row][4 + c8]) = lo;
        *reinterpret_cast<float4*>(&dst[row][8 + c8]) = hi;
    }
    for (int i = tid; i < NROWS * 2; i += 256) {
        int row = i >> 1;
        *reinterpret_cast<float4*>(&dst[row][(i & 1) ? 132 : 0]) = z4;
    }
}

// ---------------- weight prep: fold LN gamma/beta, pack to bf16 pairs --------
__global__ void prep_w_kernel(const float* __restrict__ qw, const float* __restrict__ qb,
                              const float* __restrict__ ln1w, const float* __restrict__ ln1b,
                              const float* __restrict__ kvw, const float* __restrict__ kvb,
                              const float* __restrict__ ln2w, const float* __restrict__ ln2b) {
    int r = blockIdx.x;
    int tid = threadIdx.x;
    if (r < 16) g_ss[r * 256 + tid] = 0.f;
    const float *w, *lnw, *lnb;
    float cb;
    unsigned* dWh;
    float *dB, *dR;
    if (r < C_) {
        int o = r;
        w = qw + (size_t)o * C_; lnw = ln1w; lnb = ln1b; cb = qb[o];
        dWh = g_Wqh + (size_t)o * 128; dB = g_bq + o; dR = g_rsq + o;
    } else {
        int o = r - C_;
        w = kvw + (size_t)o * C_; lnw = ln2w; lnb = ln2b; cb = kvb[o];
        dWh = g_Wkvh + (size_t)o * 128; dB = g_bkv + o; dR = g_rskv + o;
    }
    float wv = w[tid];
    float we = wv * lnw[tid];
    float we_r = __bfloat162float(__float2bfloat16(we));
    __shared__ float shw[256], sh1[256], sh2[256];
    shw[tid] = we_r;
    sh1[tid] = we_r;
    sh2[tid] = wv * lnb[tid];
    __syncthreads();
    if (tid < 128) dWh[tid] = packbf(shw[2 * tid], shw[2 * tid + 1]);
    for (int s = 128; s > 0; s >>= 1) {
        if (tid < s) { sh1[tid] += sh1[tid + s]; sh2[tid] += sh2[tid + s]; }
        __syncthreads();
    }
    if (tid == 0) { *dR = sh1[0]; *dB = cb + sh2[0]; }
}

// ===== combined LN-fused GEMM (q + kv in ONE launch): bf16 mma + ldmatrix =====
// grid (6, HW/128, B): ot 0-1 -> q path (x, Wq, bufA); ot 2-5 -> kv path.
#define SA_U 20
#define SB_U 136
#define STG_U (128 * SA_U + 16 * SB_U)   // 4736 uints / stage

__global__ __launch_bounds__(256, 2) void gemm_ln2_kernel(
    const float* __restrict__ x, const float* __restrict__ hx) {
    __shared__ unsigned sm[2 * STG_U];
    __shared__ float sS[8][128], sQ[8][128];
    int b = blockIdx.z;
    int ot = blockIdx.x;
    int pBase = blockIdx.y * 128;

    const float* X;
    const unsigned* Wb;
    const float* bias;
    const float* rsum;
    bf16* Yh;
    int O, oBase;
    if (ot < 2) {
        X = x; Wb = g_Wqh; bias = g_bq; rsum = g_rsq;
        Yh = g_bufA; O = C_; oBase = ot * 128;
    } else {
        X = hx; Wb = g_Wkvh; bias = g_bkv; rsum = g_rskv;
        Yh = g_bufB; O = 2 * C_; oBase = (ot - 2) * 128;
    }

    int tid = threadIdx.x;
    int wid = tid >> 5, lane = tid & 31;
    int g = lane >> 2, tig = lane & 3;
    int oW = (wid >> 2) * 64;
    int pW = (wid & 3) * 32;
    uint32_t smBase = smem_u32(sm);
    uint32_t aRowOff = (uint32_t)((lane & 15) * SA_U * 4 + (lane >> 4) * 16);

    const float* Xb = X + (size_t)b * C_ * HW_;

    int lk2 = tid >> 5;
    int lp0 = (tid & 31) * 4;

    uint4 wR[2];
    float4 xR[2][2];
    auto ldg = [&](int kc) {
        int k0 = kc * 32;
#pragma unroll
        for (int i = 0; i < 2; i++) {
            int idx = tid + i * 256;
            int o = idx >> 2, q = idx & 3;
            wR[i] = *reinterpret_cast<const uint4*>(Wb + (size_t)(oBase + o) * 128 + k0 / 2 + q * 4);
        }
#pragma unroll
        for (int i = 0; i < 2; i++) {
            int kk = k0 + 2 * (lk2 + i * 8);
            xR[i][0] = *reinterpret_cast<const float4*>(Xb + (size_t)kk * HW_ + pBase + lp0);
            xR[i][1] = *reinterpret_cast<const float4*>(Xb + (size_t)(kk + 1) * HW_ + pBase + lp0);
        }
    };
    float stS[4] = {}, stQ[4] = {};
    auto sts = [&](int st) {
        unsigned* sA = sm + st * STG_U;
        unsigned* sB = sA + 128 * SA_U;
#pragma unroll
        for (int i = 0; i < 2; i++) {
            int idx = tid + i * 256;
            int o = idx >> 2, q = idx & 3;
            *reinterpret_cast<uint4*>(sA + o * SA_U + q * 4) = wR[i];
        }
#pragma unroll
        for (int i = 0; i < 2; i++) {
            float4 a = xR[i][0], c = xR[i][1];
            stS[0] += a.x + c.x; stQ[0] += a.x * a.x + c.x * c.x;
            stS[1] += a.y + c.y; stQ[1] += a.y * a.y + c.y * c.y;
            stS[2] += a.z + c.z; stQ[2] += a.z * a.z + c.z * c.z;
            stS[3] += a.w + c.w; stQ[3] += a.w * a.w + c.w * c.w;
            uint4 u;
            u.x = packbf(a.x, c.x);
            u.y = packbf(a.y, c.y);
            u.z = packbf(a.z, c.z);
            u.w = packbf(a.w, c.w);
            *reinterpret_cast<uint4*>(sB + (lk2 + i * 8) * SB_U + lp0) = u;
        }
    };

    float acc[4][4][4] = {};
    ldg(0);
    for (int kc = 0; kc < 8; kc++) {
        sts(kc & 1);
        __syncthreads();
        if (kc < 7) ldg(kc + 1);
        uint32_t sAaddr = smBase + (kc & 1) * STG_U * 4;
        unsigned* sB = sm + (kc & 1) * STG_U + 128 * SA_U;
#pragma unroll
        for (int s2 = 0; s2 < 16; s2 += 8) {
            unsigned afr[4][4];
#pragma unroll
            for (int mt = 0; mt < 4; mt++)
                ldsm_x4(afr[mt], sAaddr + (uint32_t)((oW + mt * 16) * SA_U + s2) * 4 + aRowOff);
#pragma unroll
            for (int nt = 0; nt < 4; nt++) {
                int cp = pW + nt * 8 + g;
                unsigned b0 = sB[(s2 + tig) * SB_U + cp];
                unsigned b1 = sB[(s2 + 4 + tig) * SB_U + cp];
#pragma unroll
                for (int mt = 0; mt < 4; mt++)
                    mma_bf16(acc[mt][nt], afr[mt], b0, b1);
            }
        }
        // no trailing sync — ping-pong buffers make it redundant
    }

    __syncthreads();
    *reinterpret_cast<float4*>(&sS[lk2][lp0]) = make_float4(stS[0], stS[1], stS[2], stS[3]);
    *reinterpret_cast<float4*>(&sQ[lk2][lp0]) = make_float4(stQ[0], stQ[1], stQ[2], stQ[3]);
    __syncthreads();
    float mu[4][2], iv[4][2];
#pragma unroll
    for (int nt = 0; nt < 4; nt++) {
#pragma unroll
        for (int u = 0; u < 2; u++) {
            int pl = pW + nt * 8 + 2 * tig + u;
            float s0 = 0.f, q0 = 0.f;
#pragma unroll
            for (int wrow = 0; wrow < 8; wrow++) { s0 += sS[wrow][pl]; q0 += sQ[wrow][pl]; }
            float m = s0 * (1.f / 256.f);
            float var = q0 * (1.f / 256.f) - m * m;
            mu[nt][u] = m;
            iv[nt][u] = rsqrtf(var + 1e-5f);
        }
    }
#pragma unroll
    for (int mt = 0; mt < 4; mt++) {
        int o0 = oBase + oW + mt * 16 + g;
        int o1 = o0 + 8;
        float rs0 = rsum[o0], b0v = bias[o0];
        float rs1 = rsum[o1], b1v = bias[o1];
#pragma unroll
        for (int nt = 0; nt < 4; nt++) {
            int p = pBase + pW + nt * 8 + 2 * tig;
            bf162 r0 = __floats2bfloat162_rn(
                iv[nt][0] * (acc[mt][nt][0] - mu[nt][0] * rs0) + b0v,
                iv[nt][1] * (acc[mt][nt][1] - mu[nt][1] * rs0) + b0v);
            bf162 r1 = __floats2bfloat162_rn(
                iv[nt][0] * (acc[mt][nt][2] - mu[nt][0] * rs1) + b1v,
                iv[nt][1] * (acc[mt][nt][3] - mu[nt][1] * rs1) + b1v);
            *reinterpret_cast<bf162*>(Yh + ((size_t)b * O + o0) * HW_ + p) = r0;
            *reinterpret_cast<bf162*>(Yh + ((size_t)b * O + o1) * HW_ + p) = r1;
        }
    }
}

// ===== merged q+k register-strip depthwise 3x3 (+bias, +sumsq), no smem =======
__global__ __launch_bounds__(256, 4) void dwqk_kernel(const float* __restrict__ qw9,
                                                      const float* __restrict__ qb,
                                                      const float* __restrict__ kvw9,
                                                      const float* __restrict__ kvb) {
    int b = blockIdx.z, ci = blockIdx.y;
    int tid = threadIdx.x;
    int cg = tid & 15, rg = tid >> 4;
    int c0 = cg * 8, r0 = blockIdx.x * 64 + rg * 4;

    const bf16* Xc;
    const float* w9;
    const float* bp;
    bf16* D;
    float* ssq;
    if (ci < C_) {
        Xc = g_bufA + ((size_t)(b * C_ + ci)) * HW_;
        w9 = qw9 + (size_t)ci * 9;
        bp = qb + ci;
        D = g_q + ((size_t)(b * C_ + ci)) * HW_;
        ssq = &g_ss[b * C_ + ci];
    } else {
        int c = ci - C_;
        Xc = g_bufB + ((size_t)(b * 2 * C_ + c)) * HW_;
        w9 = kvw9 + (size_t)c * 9;
        bp = kvb + c;
        D = g_k + ((size_t)(b * C_ + c)) * HW_;
        ssq = &g_ss[B_ * C_ + b * C_ + c];
    }
    float wk[9];
#pragma unroll
    for (int t = 0; t < 9; t++) wk[t] = __ldg(w9 + t);
    float bv = __ldg(bp);

    float acc[4][8];
#pragma unroll
    for (int r = 0; r < 4; r++)
#pragma unroll
        for (int u = 0; u < 8; u++) acc[r][u] = bv;
#pragma unroll
    for (int t = 0; t < 6; t++) {
        int ir = r0 - 1 + t;
        float f[10];
#pragma unroll
        for (int u = 0; u < 10; u++) f[u] = 0.f;
        if (ir >= 0 && ir < H_) {
            uint4 u4 = *reinterpret_cast<const uint4*>(Xc + (size_t)ir * W_ + c0);
            float4 lo, hi;
            u4_to_f8(u4, lo, hi);
            f[1] = lo.x; f[2] = lo.y; f[3] = lo.z; f[4] = lo.w;
            f[5] = hi.x; f[6] = hi.y; f[7] = hi.z; f[8] = hi.w;
            if (c0 > 0) f[0] = __bfloat162float(__ldg(Xc + (size_t)ir * W_ + c0 - 1));
            if (c0 + 8 < W_) f[9] = __bfloat162float(__ldg(Xc + (size_t)ir * W_ + c0 + 8));
        }
        if (t >= 2) {
#pragma unroll
            for (int u = 0; u < 8; u++)
                acc[t - 2][u] += wk[6] * f[u] + wk[7] * f[u + 1] + wk[8] * f[u + 2];
        }
        if (t >= 1 && t <= 4) {
#pragma unroll
            for (int u = 0; u < 8; u++)
                acc[t - 1][u] += wk[3] * f[u] + wk[4] * f[u + 1] + wk[5] * f[u + 2];
        }
        if (t <= 3) {
#pragma unroll
            for (int u = 0; u < 8; u++)
                acc[t][u] += wk[0] * f[u] + wk[1] * f[u + 1] + wk[2] * f[u + 2];
        }
    }
    float ss = 0.f;
#pragma unroll
    for (int r = 0; r < 4; r++) {
        *reinterpret_cast<uint4*>(D + (size_t)(r0 + r) * W_ + c0) = f8_to_u4(acc[r]);
#pragma unroll
        for (int u = 0; u < 8; u++) ss += acc[r][u] * acc[r][u];
    }
#pragma unroll
    for (int d = 16; d > 0; d >>= 1) ss += __shfl_down_sync(0xffffffffu, ss, d);
    if ((tid & 31) == 0) atomicAdd(ssq, ss);
}

// ------------- v dwconv + positional branch (32-row tiles) --------------------
__global__ __launch_bounds__(256) void vpe_kernel(const float* __restrict__ kvw9,
                                                  const float* __restrict__ kvb,
                                                  const float* __restrict__ pe1,
                                                  const float* __restrict__ pe2) {
    __shared__ float sbuf[(38 + 36) * 136];
    float (*svi)[136] = reinterpret_cast<float(*)[136]>(sbuf);            // 38 rows
    float (*sv)[136]  = reinterpret_cast<float(*)[136]>(sbuf + 38 * 136); // 36 rows
    float (*st1)[136] = svi;                                              // alias (34 rows)
    int b = blockIdx.z, c = blockIdx.y, r0 = blockIdx.x * 32;
    int tid = threadIdx.x;
    const bf16* Vc = g_bufB + ((size_t)(b * 2 * C_ + C_ + c)) * HW_;
    fill_rows<38>(svi, Vc, r0, -3, tid);
    {
        float4 z4 = make_float4(0.f, 0.f, 0.f, 0.f);
        for (int i = tid; i < 36 * 2; i += 256)
            *reinterpret_cast<float4*>(&sv[i >> 1][(i & 1) ? 132 : 0]) = z4;
    }
    float wkv[9], w1[9], w2[9];
#pragma unroll
    for (int t = 0; t < 9; t++) {
        wkv[t] = __ldg(kvw9 + (size_t)(C_ + c) * 9 + t);
        w1[t] = __ldg(pe1 + (size_t)c * 9 + t);
        w2[t] = __ldg(pe2 + (size_t)c * 9 + t);
    }
    float bvv = __ldg(kvb + C_ + c);
    __syncthreads();

    int row0 = tid >> 4, s0 = (tid & 15) * 8;

    bf16* Dv = g_v + ((size_t)(b * C_ + c)) * HW_;
    for (int i = tid; i < 36 * 16; i += 256) {
        int row = i >> 4, cc = (i & 15) * 8;
        int gr = r0 - 2 + row;
        float o[8] = {};
        if (gr >= 0 && gr < H_) {
#pragma unroll
            for (int u = 0; u < 8; u++) o[u] = bvv;
#pragma unroll
            for (int dr = 0; dr < 3; dr++)
                stencil8(svi[row + dr], cc, wkv[dr * 3], wkv[dr * 3 + 1], wkv[dr * 3 + 2], o);
        }
        *reinterpret_cast<float4*>(&sv[row][4 + cc]) = make_float4(o[0], o[1], o[2], o[3]);
        *reinterpret_cast<float4*>(&sv[row][8 + cc]) = make_float4(o[4], o[5], o[6], o[7]);
        if (row >= 2 && row < 34)
            *reinterpret_cast<uint4*>(Dv + (size_t)gr * W_ + cc) = f8_to_u4(o);
    }
    __syncthreads();

    for (int i = tid; i < 34 * 16; i += 256) {
        int row = i >> 4, cc = (i & 15) * 8;
        int gr = r0 - 1 + row;
        float o[8] = {};
        if (gr >= 0 && gr < H_) {
#pragma unroll
            for (int dr = 0; dr < 3; dr++)
                stencil8(sv[row + dr], cc, w1[dr * 3], w1[dr * 3 + 1], w1[dr * 3 + 2], o);
#pragma unroll
            for (int u = 0; u < 8; u++) o[u] = gelu_tanh(o[u]);
        }
        *reinterpret_cast<float4*>(&st1[row][4 + cc]) = make_float4(o[0], o[1], o[2], o[3]);
        *reinterpret_cast<float4*>(&st1[row][8 + cc]) = make_float4(o[4], o[5], o[6], o[7]);
    }
    __syncthreads();

    bf16* Dp = g_pe + ((size_t)(b * C_ + c)) * HW_;
#pragma unroll
    for (int it = 0; it < 2; it++) {
        int row = row0 + it * 16;
        float o[8] = {};
#pragma unroll
        for (int dr = 0; dr < 3; dr++)
            stencil8(st1[row + dr], s0, w2[dr * 3], w2[dr * 3 + 1], w2[dr * 3 + 2], o);
        *reinterpret_cast<uint4*>(Dp + (size_t)(r0 + row) * W_ + s0) = f8_to_u4(o);
    }
}

// ---------------- gram via bf16 mma m16n8k16, double-buffered, split-K=8 ------
__global__ __launch_bounds__(256) void gram_mma() {
    __shared__ float sbuf[8704];   // 2 stages of (q 32x136 + k 32x136) bf16
    bf16* tile = reinterpret_cast<bf16*>(sbuf);
    int seg = blockIdx.x, h = blockIdx.y, b = blockIdx.z;
    const bf16* Q = g_q + ((size_t)(b * C_ + h * HD_)) * HW_;
    const bf16* K = g_k + ((size_t)(b * C_ + h * HD_)) * HW_;
    int tid = threadIdx.x, wid = tid >> 5, lane = tid & 31;
    int g = lane >> 2, tig = lane & 3;
    float acc[2][4][4] = {};
    int n0 = seg * (HW_ / GSEG);
    int klu = wid * 8;

    auto load = [&](int ch, int st) {
        int base = n0 + ch * 128;
        bf16* sq = tile + st * 8704;
        bf16* sk = sq + 4352;
        for (int i = tid; i < 32 * 16; i += 256) {
            int row = i >> 4, c8 = (i & 15) * 8;
            *reinterpret_cast<uint4*>(sq + row * 136 + c8) =
                *reinterpret_cast<const uint4*>(Q + (size_t)row * HW_ + base + c8);
            *reinterpret_cast<uint4*>(sk + row * 136 + c8) =
                *reinterpret_cast<const uint4*>(K + (size_t)row * HW_ + base + c8);
        }
    };

    load(0, 0);
    const int NCH = (HW_ / GSEG) / 128;   // 16
    for (int ch = 0; ch < NCH; ch++) {
        __syncthreads();
        if (ch + 1 < NCH) load(ch + 1, (ch + 1) & 1);
        unsigned* squ = reinterpret_cast<unsigned*>(tile + (ch & 1) * 8704);
        unsigned* sku = squ + 2176;
        unsigned afr[2][4];
#pragma unroll
        for (int mt = 0; mt < 2; mt++) {
            int r = mt * 16 + g;
            afr[mt][0] = squ[r * 68 + klu + tig];
            afr[mt][1] = squ[(r + 8) * 68 + klu + tig];
            afr[mt][2] = squ[r * 68 + klu + 4 + tig];
            afr[mt][3] = squ[(r + 8) * 68 + klu + 4 + tig];
        }
#pragma unroll
        for (int nt = 0; nt < 4; nt++) {
            unsigned b0 = sku[(nt * 8 + g) * 68 + klu + tig];
            unsigned b1 = sku[(nt * 8 + g) * 68 + klu + 4 + tig];
#pragma unroll
            for (int mt = 0; mt < 2; mt++)
                mma_bf16(acc[mt][nt], afr[mt], b0, b1);
        }
    }
    __syncthreads();
    float* red = sbuf;
#pragma unroll
    for (int mt = 0; mt < 2; mt++)
#pragma unroll
        for (int nt = 0; nt < 4; nt++) {
            int r = mt * 16 + g, cl = nt * 8 + 2 * tig;
            red[wid * 1024 + r * 32 + cl] = acc[mt][nt][0];
            red[wid * 1024 + r * 32 + cl + 1] = acc[mt][nt][1];
            red[wid * 1024 + (r + 8) * 32 + cl] = acc[mt][nt][2];
            red[wid * 1024 + (r + 8) * 32 + cl + 1] = acc[mt][nt][3];
        }
    __syncthreads();
    float* outp = g_part + ((size_t)(b * HEADS_ + h) * GSEG + seg) * 1024;
    for (int i = tid; i < 1024; i += 256) {
        float s = 0.f;
#pragma unroll
        for (int w = 0; w < 8; w++) s += red[w * 1024 + i];
        outp[i] = s;
    }
}

// === fused: reduce partials + scales + temperature + softmax + M projection ===
__global__ void buildM_kernel(const float* __restrict__ ao_w,
                              const float* __restrict__ temp) {
    int h = blockIdx.x, b = blockIdx.y;
    int tid = threadIdx.x;
    __shared__ float sa[32][33];
    __shared__ float sqs[32], sks[32];

    if (tid < 32)
        sqs[tid] = 1.f / fmaxf(sqrtf(g_ss[b * C_ + h * HD_ + tid]), 1e-12f);
    else if (tid < 64)
        sks[tid - 32] = 1.f / fmaxf(sqrtf(g_ss[B_ * C_ + b * C_ + h * HD_ + tid - 32]), 1e-12f);

    // reduce split-K partials into smem (raw dot products)
#pragma unroll
    for (int t = 0; t < 4; t++) {
        int idx = tid + t * 256;
        float s = 0.f;
#pragma unroll
        for (int seg = 0; seg < GSEG; seg++)
            s += g_part[((size_t)(b * HEADS_ + h) * GSEG + seg) * 1024 + idx];
        sa[idx >> 5][idx & 31] = s;
    }
    __syncthreads();

    // warp 0: scale + softmax per row
    if (tid < 32) {
        int i = tid;
        float qs = sqs[i];
        float T = __ldg(temp + h);
        float v[32];
        float mx = -1e30f;
#pragma unroll
        for (int j = 0; j < 32; j++) {
            float val = sa[i][j] * qs * sks[j] * T;
            v[j] = val;
            mx = fmaxf(mx, val);
        }
        float sum = 0.f;
#pragma unroll
        for (int j = 0; j < 32; j++) {
            v[j] = expf(v[j] - mx);
            sum += v[j];
        }
        float inv = 1.f / sum;
#pragma unroll
        for (int j = 0; j < 32; j++) sa[i][j] = v[j] * inv;
    }
    __syncthreads();

    // M projection: o = tid
    float wreg[32];
#pragma unroll
    for (int c = 0; c < 32; c++) wreg[c] = ao_w[(size_t)tid * C_ + h * HD_ + c];
    float m[32];
#pragma unroll 4
    for (int d = 0; d < 32; d++) {
        float s = 0.f;
#pragma unroll
        for (int c = 0; c < 32; c++) s += wreg[c] * sa[c][d];
        m[d] = s;
    }
    unsigned* Mo = g_Mh + ((size_t)(b * C_) + tid) * 128 + h * 16;
#pragma unroll
    for (int j = 0; j < 16; j++) Mo[j] = packbf(m[2 * j], m[2 * j + 1]);
}

// ======= final GEMM: out = M@v + ao_b + pemb + hx (bf16 mma + ldmatrix) ======
__global__ __launch_bounds__(256, 2) void gemm_outh_kernel(const float* __restrict__ bias,
                                                           const float* __restrict__ hx,
                                                           float* __restrict__ out) {
    __shared__ unsigned sm[2 * STG_U];
    int b = blockIdx.z;
    int oBase = blockIdx.x * 128;
    int pBase = blockIdx.y * 128;
    int tid = threadIdx.x;
    int wid = tid >> 5, lane = tid & 31;
    int g = lane >> 2, tig = lane & 3;
    int oW = (wid >> 2) * 64;
    int pW = (wid & 3) * 32;
    uint32_t smBase = smem_u32(sm);
    uint32_t aRowOff = (uint32_t)((lane & 15) * SA_U * 4 + (lane >> 4) * 16);

    const unsigned* Mb = g_Mh + (size_t)b * C_ * 128;
    const bf16* Vb = g_v + (size_t)b * C_ * HW_;

    int lk2 = tid >> 4;
    int lp8 = (tid & 15) * 8;

    uint4 aR[2];
    uint4 vA, vB;
    auto ldg = [&](int kc) {
        int k0 = kc * 32;
#pragma unroll
        for (int i = 0; i < 2; i++) {
            int idx = tid + i * 256;
            int o = idx >> 2, q = idx & 3;
            aR[i] = *reinterpret_cast<const uint4*>(Mb + (size_t)(oBase + o) * 128 + k0 / 2 + q * 4);
        }
        int kk = k0 + 2 * lk2;
        vA = *reinterpret_cast<const uint4*>(Vb + (size_t)kk * HW_ + pBase + lp8);
        vB = *reinterpret_cast<const uint4*>(Vb + (size_t)(kk + 1) * HW_ + pBase + lp8);
    };
    auto sts = [&](int st) {
        unsigned* sA = sm + st * STG_U;
        unsigned* sB = sA + 128 * SA_U;
#pragma unroll
        for (int i = 0; i < 2; i++) {
            int idx = tid + i * 256;
            int o = idx >> 2, q = idx & 3;
            *reinterpret_cast<uint4*>(sA + o * SA_U + q * 4) = aR[i];
        }
        uint4 o0, o1;
        o0.x = __byte_perm(vA.x, vB.x, 0x5410);
        o0.y = __byte_perm(vA.x, vB.x, 0x7632);
        o0.z = __byte_perm(vA.y, vB.y, 0x5410);
        o0.w = __byte_perm(vA.y, vB.y, 0x7632);
        o1.x = __byte_perm(vA.z, vB.z, 0x5410);
        o1.y = __byte_perm(vA.z, vB.z, 0x7632);
        o1.z = __byte_perm(vA.w, vB.w, 0x5410);
        o1.w = __byte_perm(vA.w, vB.w, 0x7632);
        *reinterpret_cast<uint4*>(sB + lk2 * SB_U + lp8) = o0;
        *reinterpret_cast<uint4*>(sB + lk2 * SB_U + lp8 + 4) = o1;
    };

    float acc[4][4][4] = {};
    ldg(0);
    for (int kc = 0; kc < 8; kc++) {
        sts(kc & 1);
        __syncthreads();
        if (kc < 7) ldg(kc + 1);
        uint32_t sAaddr = smBase + (kc & 1) * STG_U * 4;
        unsigned* sB = sm + (kc & 1) * STG_U + 128 * SA_U;
#pragma unroll
        for (int s2 = 0; s2 < 16; s2 += 8) {
            unsigned afr[4][4];
#pragma unroll
            for (int mt = 0; mt < 4; mt++)
                ldsm_x4(afr[mt], sAaddr + (uint32_t)((oW + mt * 16) * SA_U + s2) * 4 + aRowOff);
#pragma unroll
            for (int nt = 0; nt < 4; nt++) {
                int cp = pW + nt * 8 + g;
                unsigned b0 = sB[(s2 + tig) * SB_U + cp];
                unsigned b1 = sB[(s2 + 4 + tig) * SB_U + cp];
#pragma unroll
                for (int mt = 0; mt < 4; mt++)
                    mma_bf16(acc[mt][nt], afr[mt], b0, b1);
            }
        }
        // no trailing sync (ping-pong safe)
    }

    const bf16* PEb = g_pe + (size_t)b * C_ * HW_;
    const float* HXb = hx + (size_t)b * C_ * HW_;
#pragma unroll
    for (int mt = 0; mt < 4; mt++) {
        int o0 = oBase + oW + mt * 16 + g;
        int o1 = o0 + 8;
        float b0v = bias[o0], b1v = bias[o1];
#pragma unroll
        for (int nt = 0; nt < 4; nt++) {
            int p = pBase + pW + nt * 8 + 2 * tig;
            float2 h0 = *reinterpret_cast<const float2*>(HXb + (size_t)o0 * HW_ + p);
            float2 h1 = *reinterpret_cast<const float2*>(HXb + (size_t)o1 * HW_ + p);
            float2 pf0 = __bfloat1622float2(
                *reinterpret_cast<const bf162*>(PEb + (size_t)o0 * HW_ + p));
            float2 pf1 = __bfloat1622float2(
                *reinterpret_cast<const bf162*>(PEb + (size_t)o1 * HW_ + p));
            float2 r0, r1;
            r0.x = acc[mt][nt][0] + b0v + pf0.x + h0.x;
            r0.y = acc[mt][nt][1] + b0v + pf0.y + h0.y;
            r1.x = acc[mt][nt][2] + b1v + pf1.x + h1.x;
            r1.y = acc[mt][nt][3] + b1v + pf1.y + h1.y;
            *reinterpret_cast<float2*>(out + ((size_t)b * C_ + o0) * HW_ + p) = r0;
            *reinterpret_cast<float2*>(out + ((size_t)b * C_ + o1) * HW_ + p) = r1;
        }
    }
}

// -----------------------------------------------------------------------------
extern "C" void kernel_launch(void* const* d_in, const int* in_sizes, int n_in,
                              void* d_out, int out_size) {
    const float* x = (const float*)d_in[0];
    const float* hx = (const float*)d_in[1];
    const float* ln1_w = (const float*)d_in[2];
    const float* ln1_b = (const float*)d_in[3];
    const float* ln2_w = (const float*)d_in[4];
    const float* ln2_b = (const float*)d_in[5];
    const float* q_w = (const float*)d_in[6];
    const float* q_b = (const float*)d_in[7];
    const float* q_dw_w = (const float*)d_in[8];
    const float* q_dw_b = (const float*)d_in[9];
    const float* kv_w = (const float*)d_in[10];
    const float* kv_b = (const float*)d_in[11];
    const float* kv_dw_w = (const float*)d_in[12];
    const float* kv_dw_b = (const float*)d_in[13];
    const float* ao_w = (const float*)d_in[14];
    const float* ao_b = (const float*)d_in[15];
    const float* pe1_w = (const float*)d_in[16];
    const float* pe2_w = (const float*)d_in[17];
    const float* temperature = (const float*)d_in[18];
    float* out = (float*)d_out;

    // 1. fold LN into weights (pack bf16 pairs); zero sumsq accumulators
    prep_w_kernel<<<3 * C_, 256>>>(q_w, q_b, ln1_w, ln1_b, kv_w, kv_b, ln2_w, ln2_b);

    // 2. both LN GEMMs in ONE launch: q_pre -> bufA, kv_pre -> bufB
    gemm_ln2_kernel<<<dim3(6, HW_ / 128, B_), 256>>>(x, hx);

    // 3. merged q+k dwconvs (register-strip, 4-row patches) -> g_q, g_k (+sumsq)
    dwqk_kernel<<<dim3(2, 2 * C_, B_), 256>>>(q_dw_w, q_dw_b, kv_dw_w, kv_dw_b);

    // 4. v dwconv + positional branch (32-row tiles) -> g_v, g_pe
    vpe_kernel<<<dim3(4, C_, B_), 256>>>(kv_dw_w, kv_dw_b, pe1_w, pe2_w);

    // 5. gram (bf16 mma, double-buffered, split-K=8)
    gram_mma<<<dim3(GSEG, HEADS_, B_), 256>>>();

    // 6. fused softmax + attn-fold into output projection; final fused GEMM
    buildM_kernel<<<dim3(HEADS_, B_), 256>>>(ao_w, temperature);
    gemm_outh_kernel<<<dim3(C_ / 128, HW_ / 128, B_), 256>>>(ao_b, hx, out);
}

// round 15
// speedup vs baseline: 1.1496x; 1.0341x over previous
#include <cuda_runtime.h>
#include <cuda_bf16.h>
#include <math.h>
#include <stdint.h>

#define B_ 8
#define C_ 256
#define H_ 128
#define W_ 128
#define HW_ 16384
#define HEADS_ 8
#define HD_ 32
#define GSEG 8

typedef __nv_bfloat16 bf16;
typedef __nv_bfloat162 bf162;

// ---------------- scratch (device globals; no allocation allowed) ------------
__device__ bf16 g_bufA[B_ * C_ * HW_];           // q_pre
__device__ bf16 g_bufB[B_ * 2 * C_ * HW_];       // kv_pre
__device__ bf16 g_q[B_ * C_ * HW_];
__device__ bf16 g_k[B_ * C_ * HW_];
__device__ bf16 g_v[B_ * C_ * HW_];
__device__ bf16 g_pe[B_ * C_ * HW_];             // pemb (WITHOUT hx)
__device__ unsigned g_Wqh[C_ * 128];             // bf16-pair packed folded weights
__device__ unsigned g_Wkvh[2 * C_ * 128];
__device__ unsigned g_Mh[B_ * C_ * 128];         // packed M = ao_w @ blockdiag(attn)
__device__ float g_bq[C_];
__device__ float g_bkv[2 * C_];
__device__ float g_rsq[C_];
__device__ float g_rskv[2 * C_];
__device__ float g_ss[2 * B_ * C_];
__device__ float g_part[B_ * HEADS_ * GSEG * 1024];

// ---------------- helpers ------------------------------------------------
__device__ __forceinline__ void mma_bf16(float* c, const unsigned* a, unsigned b0, unsigned b1) {
    asm volatile(
        "mma.sync.aligned.m16n8k16.row.col.f32.bf16.bf16.f32 "
        "{%0,%1,%2,%3}, {%4,%5,%6,%7}, {%8,%9}, {%0,%1,%2,%3};\n"
        : "+f"(c[0]), "+f"(c[1]), "+f"(c[2]), "+f"(c[3])
        : "r"(a[0]), "r"(a[1]), "r"(a[2]), "r"(a[3]), "r"(b0), "r"(b1));
}
__device__ __forceinline__ void ldsm_x4(unsigned* r, uint32_t addr) {
    asm volatile("ldmatrix.sync.aligned.m8n8.x4.shared.b16 {%0,%1,%2,%3}, [%4];"
                 : "=r"(r[0]), "=r"(r[1]), "=r"(r[2]), "=r"(r[3])
                 : "r"(addr));
}
__device__ __forceinline__ uint32_t smem_u32(const void* p) {
    return (uint32_t)__cvta_generic_to_shared(p);
}
__device__ __forceinline__ unsigned packbf(float lo, float hi) {
    bf162 t = __floats2bfloat162_rn(lo, hi);
    return *reinterpret_cast<unsigned*>(&t);
}
__device__ __forceinline__ float gelu_tanh(float s) {
    float x3 = s * s * s;
    return 0.5f * s * (1.f + tanhf(0.7978845608028654f * (s + 0.044715f * x3)));
}
__device__ __forceinline__ void u4_to_f8(uint4 u, float4& lo, float4& hi) {
    bf162 h0 = *reinterpret_cast<bf162*>(&u.x);
    bf162 h1 = *reinterpret_cast<bf162*>(&u.y);
    bf162 h2 = *reinterpret_cast<bf162*>(&u.z);
    bf162 h3 = *reinterpret_cast<bf162*>(&u.w);
    float2 f0 = __bfloat1622float2(h0), f1 = __bfloat1622float2(h1);
    float2 f2 = __bfloat1622float2(h2), f3 = __bfloat1622float2(h3);
    lo = make_float4(f0.x, f0.y, f1.x, f1.y);
    hi = make_float4(f2.x, f2.y, f3.x, f3.y);
}
__device__ __forceinline__ uint4 f8_to_u4(const float* o) {
    uint4 r;
    r.x = packbf(o[0], o[1]);
    r.y = packbf(o[2], o[3]);
    r.z = packbf(o[4], o[5]);
    r.w = packbf(o[6], o[7]);
    return r;
}

// row view for register-streamed stencils: 10 floats (8 data + 2 halos)
struct Row8 { float v[10]; };
__device__ __forceinline__ Row8 load_row8(const float* R, int s) {
    Row8 r;
    float4 m0 = *reinterpret_cast<const float4*>(R + 4 + s);
    float4 m1 = *reinterpret_cast<const float4*>(R + 8 + s);
    r.v[0] = R[3 + s];
    r.v[1] = m0.x; r.v[2] = m0.y; r.v[3] = m0.z; r.v[4] = m0.w;
    r.v[5] = m1.x; r.v[6] = m1.y; r.v[7] = m1.z; r.v[8] = m1.w;
    r.v[9] = R[12 + s];
    return r;
}
__device__ __forceinline__ void apply_row8(float* o, const Row8& r, float w0, float w1, float w2) {
#pragma unroll
    for (int u = 0; u < 8; u++) o[u] += w0 * r.v[u] + w1 * r.v[u + 1] + w2 * r.v[u + 2];
}

// 8-wide 3-tap over a padded smem row (data at +4; pads zero at 0..3 / 132..135)
__device__ __forceinline__ void stencil8(const float* R, int s, float w0, float w1, float w2,
                                         float* o) {
    Row8 r = load_row8(R, s);
    apply_row8(o, r, w0, w1, w2);
}

// single-pass fill of N padded rows from bf16 global
template <int NROWS>
__device__ __forceinline__ void fill_rows(float (*dst)[136], const bf16* src, int r0, int roff,
                                          int tid) {
    float4 z4 = make_float4(0.f, 0.f, 0.f, 0.f);
    for (int i = tid; i < NROWS * 16; i += 256) {
        int row = i >> 4, c8 = (i & 15) * 8;
        int gr = r0 + roff + row;
        float4 lo = z4, hi = z4;
        if (gr >= 0 && gr < H_) {
            uint4 u = *reinterpret_cast<const uint4*>(src + (size_t)gr * W_ + c8);
            u4_to_f8(u, lo, hi);
        }
        *reinterpret_cast<float4*>(&dst[row][4 + c8]) = lo;
        *reinterpret_cast<float4*>(&dst[row][8 + c8]) = hi;
    }
    for (int i = tid; i < NROWS * 2; i += 256) {
        int row = i >> 1;
        *reinterpret_cast<float4*>(&dst[row][(i & 1) ? 132 : 0]) = z4;
    }
}

// ---------------- weight prep: fold LN gamma/beta, pack to bf16 pairs --------
__global__ void prep_w_kernel(const float* __restrict__ qw, const float* __restrict__ qb,
                              const float* __restrict__ ln1w, const float* __restrict__ ln1b,
                              const float* __restrict__ kvw, const float* __restrict__ kvb,
                              const float* __restrict__ ln2w, const float* __restrict__ ln2b) {
    int r = blockIdx.x;
    int tid = threadIdx.x;
    if (r < 16) g_ss[r * 256 + tid] = 0.f;
    const float *w, *lnw, *lnb;
    float cb;
    unsigned* dWh;
    float *dB, *dR;
    if (r < C_) {
        int o = r;
        w = qw + (size_t)o * C_; lnw = ln1w; lnb = ln1b; cb = qb[o];
        dWh = g_Wqh + (size_t)o * 128; dB = g_bq + o; dR = g_rsq + o;
    } else {
        int o = r - C_;
        w = kvw + (size_t)o * C_; lnw = ln2w; lnb = ln2b; cb = kvb[o];
        dWh = g_Wkvh + (size_t)o * 128; dB = g_bkv + o; dR = g_rskv + o;
    }
    float wv = w[tid];
    float we = wv * lnw[tid];
    float we_r = __bfloat162float(__float2bfloat16(we));
    __shared__ float shw[256], sh1[256], sh2[256];
    shw[tid] = we_r;
    sh1[tid] = we_r;
    sh2[tid] = wv * lnb[tid];
    __syncthreads();
    if (tid < 128) dWh[tid] = packbf(shw[2 * tid], shw[2 * tid + 1]);
    for (int s = 128; s > 0; s >>= 1) {
        if (tid < s) { sh1[tid] += sh1[tid + s]; sh2[tid] += sh2[tid + s]; }
        __syncthreads();
    }
    if (tid == 0) { *dR = sh1[0]; *dB = cb + sh2[0]; }
}

// ===== combined LN-fused GEMM (q + kv in ONE launch): bf16 mma + ldmatrix =====
#define SA_U 20
#define SB_U 136
#define STG_U (128 * SA_U + 16 * SB_U)   // 4736 uints / stage

__global__ __launch_bounds__(256, 2) void gemm_ln2_kernel(
    const float* __restrict__ x, const float* __restrict__ hx) {
    __shared__ unsigned sm[2 * STG_U];
    __shared__ float sS[8][128], sQ[8][128];
    int b = blockIdx.z;
    int ot = blockIdx.x;
    int pBase = blockIdx.y * 128;

    const float* X;
    const unsigned* Wb;
    const float* bias;
    const float* rsum;
    bf16* Yh;
    int O, oBase;
    if (ot < 2) {
        X = x; Wb = g_Wqh; bias = g_bq; rsum = g_rsq;
        Yh = g_bufA; O = C_; oBase = ot * 128;
    } else {
        X = hx; Wb = g_Wkvh; bias = g_bkv; rsum = g_rskv;
        Yh = g_bufB; O = 2 * C_; oBase = (ot - 2) * 128;
    }

    int tid = threadIdx.x;
    int wid = tid >> 5, lane = tid & 31;
    int g = lane >> 2, tig = lane & 3;
    int oW = (wid >> 2) * 64;
    int pW = (wid & 3) * 32;
    uint32_t smBase = smem_u32(sm);
    uint32_t aRowOff = (uint32_t)((lane & 15) * SA_U * 4 + (lane >> 4) * 16);

    const float* Xb = X + (size_t)b * C_ * HW_;

    int lk2 = tid >> 5;
    int lp0 = (tid & 31) * 4;

    uint4 wR[2];
    float4 xR[2][2];
    auto ldg = [&](int kc) {
        int k0 = kc * 32;
#pragma unroll
        for (int i = 0; i < 2; i++) {
            int idx = tid + i * 256;
            int o = idx >> 2, q = idx & 3;
            wR[i] = *reinterpret_cast<const uint4*>(Wb + (size_t)(oBase + o) * 128 + k0 / 2 + q * 4);
        }
#pragma unroll
        for (int i = 0; i < 2; i++) {
            int kk = k0 + 2 * (lk2 + i * 8);
            xR[i][0] = *reinterpret_cast<const float4*>(Xb + (size_t)kk * HW_ + pBase + lp0);
            xR[i][1] = *reinterpret_cast<const float4*>(Xb + (size_t)(kk + 1) * HW_ + pBase + lp0);
        }
    };
    float stS[4] = {}, stQ[4] = {};
    auto sts = [&](int st) {
        unsigned* sA = sm + st * STG_U;
        unsigned* sB = sA + 128 * SA_U;
#pragma unroll
        for (int i = 0; i < 2; i++) {
            int idx = tid + i * 256;
            int o = idx >> 2, q = idx & 3;
            *reinterpret_cast<uint4*>(sA + o * SA_U + q * 4) = wR[i];
        }
#pragma unroll
        for (int i = 0; i < 2; i++) {
            float4 a = xR[i][0], c = xR[i][1];
            stS[0] += a.x + c.x; stQ[0] += a.x * a.x + c.x * c.x;
            stS[1] += a.y + c.y; stQ[1] += a.y * a.y + c.y * c.y;
            stS[2] += a.z + c.z; stQ[2] += a.z * a.z + c.z * c.z;
            stS[3] += a.w + c.w; stQ[3] += a.w * a.w + c.w * c.w;
            uint4 u;
            u.x = packbf(a.x, c.x);
            u.y = packbf(a.y, c.y);
            u.z = packbf(a.z, c.z);
            u.w = packbf(a.w, c.w);
            *reinterpret_cast<uint4*>(sB + (lk2 + i * 8) * SB_U + lp0) = u;
        }
    };

    float acc[4][4][4] = {};
    ldg(0);
    for (int kc = 0; kc < 8; kc++) {
        sts(kc & 1);
        __syncthreads();
        if (kc < 7) ldg(kc + 1);
        uint32_t sAaddr = smBase + (kc & 1) * STG_U * 4;
        unsigned* sB = sm + (kc & 1) * STG_U + 128 * SA_U;
#pragma unroll
        for (int s2 = 0; s2 < 16; s2 += 8) {
            unsigned afr[4][4];
#pragma unroll
            for (int mt = 0; mt < 4; mt++)
                ldsm_x4(afr[mt], sAaddr + (uint32_t)((oW + mt * 16) * SA_U + s2) * 4 + aRowOff);
#pragma unroll
            for (int nt = 0; nt < 4; nt++) {
                int cp = pW + nt * 8 + g;
                unsigned b0 = sB[(s2 + tig) * SB_U + cp];
                unsigned b1 = sB[(s2 + 4 + tig) * SB_U + cp];
#pragma unroll
                for (int mt = 0; mt < 4; mt++)
                    mma_bf16(acc[mt][nt], afr[mt], b0, b1);
            }
        }
        // no trailing sync — ping-pong buffers make it redundant
    }

    __syncthreads();
    *reinterpret_cast<float4*>(&sS[lk2][lp0]) = make_float4(stS[0], stS[1], stS[2], stS[3]);
    *reinterpret_cast<float4*>(&sQ[lk2][lp0]) = make_float4(stQ[0], stQ[1], stQ[2], stQ[3]);
    __syncthreads();
    float mu[4][2], iv[4][2];
#pragma unroll
    for (int nt = 0; nt < 4; nt++) {
#pragma unroll
        for (int u = 0; u < 2; u++) {
            int pl = pW + nt * 8 + 2 * tig + u;
            float s0 = 0.f, q0 = 0.f;
#pragma unroll
            for (int wrow = 0; wrow < 8; wrow++) { s0 += sS[wrow][pl]; q0 += sQ[wrow][pl]; }
            float m = s0 * (1.f / 256.f);
            float var = q0 * (1.f / 256.f) - m * m;
            mu[nt][u] = m;
            iv[nt][u] = rsqrtf(var + 1e-5f);
        }
    }
#pragma unroll
    for (int mt = 0; mt < 4; mt++) {
        int o0 = oBase + oW + mt * 16 + g;
        int o1 = o0 + 8;
        float rs0 = rsum[o0], b0v = bias[o0];
        float rs1 = rsum[o1], b1v = bias[o1];
#pragma unroll
        for (int nt = 0; nt < 4; nt++) {
            int p = pBase + pW + nt * 8 + 2 * tig;
            bf162 r0 = __floats2bfloat162_rn(
                iv[nt][0] * (acc[mt][nt][0] - mu[nt][0] * rs0) + b0v,
                iv[nt][1] * (acc[mt][nt][1] - mu[nt][1] * rs0) + b0v);
            bf162 r1 = __floats2bfloat162_rn(
                iv[nt][0] * (acc[mt][nt][2] - mu[nt][0] * rs1) + b1v,
                iv[nt][1] * (acc[mt][nt][3] - mu[nt][1] * rs1) + b1v);
            *reinterpret_cast<bf162*>(Yh + ((size_t)b * O + o0) * HW_ + p) = r0;
            *reinterpret_cast<bf162*>(Yh + ((size_t)b * O + o1) * HW_ + p) = r1;
        }
    }
}

// ===== merged q+k register-strip depthwise 3x3 (+bias, +sumsq), no smem =======
__global__ __launch_bounds__(256, 4) void dwqk_kernel(const float* __restrict__ qw9,
                                                      const float* __restrict__ qb,
                                                      const float* __restrict__ kvw9,
                                                      const float* __restrict__ kvb) {
    int b = blockIdx.z, ci = blockIdx.y;
    int tid = threadIdx.x;
    int cg = tid & 15, rg = tid >> 4;
    int c0 = cg * 8, r0 = blockIdx.x * 64 + rg * 4;

    const bf16* Xc;
    const float* w9;
    const float* bp;
    bf16* D;
    float* ssq;
    if (ci < C_) {
        Xc = g_bufA + ((size_t)(b * C_ + ci)) * HW_;
        w9 = qw9 + (size_t)ci * 9;
        bp = qb + ci;
        D = g_q + ((size_t)(b * C_ + ci)) * HW_;
        ssq = &g_ss[b * C_ + ci];
    } else {
        int c = ci - C_;
        Xc = g_bufB + ((size_t)(b * 2 * C_ + c)) * HW_;
        w9 = kvw9 + (size_t)c * 9;
        bp = kvb + c;
        D = g_k + ((size_t)(b * C_ + c)) * HW_;
        ssq = &g_ss[B_ * C_ + b * C_ + c];
    }
    float wk[9];
#pragma unroll
    for (int t = 0; t < 9; t++) wk[t] = __ldg(w9 + t);
    float bv = __ldg(bp);

    float acc[4][8];
#pragma unroll
    for (int r = 0; r < 4; r++)
#pragma unroll
        for (int u = 0; u < 8; u++) acc[r][u] = bv;
#pragma unroll
    for (int t = 0; t < 6; t++) {
        int ir = r0 - 1 + t;
        float f[10];
#pragma unroll
        for (int u = 0; u < 10; u++) f[u] = 0.f;
        if (ir >= 0 && ir < H_) {
            uint4 u4 = *reinterpret_cast<const uint4*>(Xc + (size_t)ir * W_ + c0);
            float4 lo, hi;
            u4_to_f8(u4, lo, hi);
            f[1] = lo.x; f[2] = lo.y; f[3] = lo.z; f[4] = lo.w;
            f[5] = hi.x; f[6] = hi.y; f[7] = hi.z; f[8] = hi.w;
            if (c0 > 0) f[0] = __bfloat162float(__ldg(Xc + (size_t)ir * W_ + c0 - 1));
            if (c0 + 8 < W_) f[9] = __bfloat162float(__ldg(Xc + (size_t)ir * W_ + c0 + 8));
        }
        if (t >= 2) {
#pragma unroll
            for (int u = 0; u < 8; u++)
                acc[t - 2][u] += wk[6] * f[u] + wk[7] * f[u + 1] + wk[8] * f[u + 2];
        }
        if (t >= 1 && t <= 4) {
#pragma unroll
            for (int u = 0; u < 8; u++)
                acc[t - 1][u] += wk[3] * f[u] + wk[4] * f[u + 1] + wk[5] * f[u + 2];
        }
        if (t <= 3) {
#pragma unroll
            for (int u = 0; u < 8; u++)
                acc[t][u] += wk[0] * f[u] + wk[1] * f[u + 1] + wk[2] * f[u + 2];
        }
    }
    float ss = 0.f;
#pragma unroll
    for (int r = 0; r < 4; r++) {
        *reinterpret_cast<uint4*>(D + (size_t)(r0 + r) * W_ + c0) = f8_to_u4(acc[r]);
#pragma unroll
        for (int u = 0; u < 8; u++) ss += acc[r][u] * acc[r][u];
    }
#pragma unroll
    for (int d = 16; d > 0; d >>= 1) ss += __shfl_down_sync(0xffffffffu, ss, d);
    if ((tid & 31) == 0) atomicAdd(ssq, ss);
}

// ------- v dwconv + positional branch (32-row tiles, 2-row stream units) ------
__global__ __launch_bounds__(256) void vpe_kernel(const float* __restrict__ kvw9,
                                                  const float* __restrict__ kvb,
                                                  const float* __restrict__ pe1,
                                                  const float* __restrict__ pe2) {
    __shared__ float sbuf[(38 + 36) * 136];
    float (*svi)[136] = reinterpret_cast<float(*)[136]>(sbuf);            // 38 rows
    float (*sv)[136]  = reinterpret_cast<float(*)[136]>(sbuf + 38 * 136); // 36 rows
    float (*st1)[136] = svi;                                              // alias (34 rows)
    int b = blockIdx.z, c = blockIdx.y, r0 = blockIdx.x * 32;
    int tid = threadIdx.x;
    const bf16* Vc = g_bufB + ((size_t)(b * 2 * C_ + C_ + c)) * HW_;
    fill_rows<38>(svi, Vc, r0, -3, tid);
    {
        float4 z4 = make_float4(0.f, 0.f, 0.f, 0.f);
        for (int i = tid; i < 36 * 2; i += 256)
            *reinterpret_cast<float4*>(&sv[i >> 1][(i & 1) ? 132 : 0]) = z4;
    }
    float wkv[9], w1[9], w2[9];
#pragma unroll
    for (int t = 0; t < 9; t++) {
        wkv[t] = __ldg(kvw9 + (size_t)(C_ + c) * 9 + t);
        w1[t] = __ldg(pe1 + (size_t)c * 9 + t);
        w2[t] = __ldg(pe2 + (size_t)c * 9 + t);
    }
    float bvv = __ldg(kvb + C_ + c);
    __syncthreads();

    bf16* Dv = g_v + ((size_t)(b * C_ + c)) * HW_;
    // ---- stage v: 36 rows as 18 two-row units x 16 col groups ----
    for (int i = tid; i < 18 * 16; i += 256) {
        int un = i >> 4, cc = (i & 15) * 8;
        int ra = un * 2;               // sv rows ra, ra+1; svi taps ra..ra+3
        int ga = r0 - 2 + ra;          // global row of sv row ra
        float o0[8] = {}, o1[8] = {};
        bool in0 = (ga >= 0 && ga < H_), in1 = (ga + 1 >= 0 && ga + 1 < H_);
        if (in0) { for (int u = 0; u < 8; u++) o0[u] = bvv; }
        if (in1) { for (int u = 0; u < 8; u++) o1[u] = bvv; }
        Row8 rA = load_row8(svi[ra], cc);
        Row8 rB = load_row8(svi[ra + 1], cc);
        Row8 rC = load_row8(svi[ra + 2], cc);
        Row8 rD = load_row8(svi[ra + 3], cc);
        if (in0) {
            apply_row8(o0, rA, wkv[0], wkv[1], wkv[2]);
            apply_row8(o0, rB, wkv[3], wkv[4], wkv[5]);
            apply_row8(o0, rC, wkv[6], wkv[7], wkv[8]);
        }
        if (in1) {
            apply_row8(o1, rB, wkv[0], wkv[1], wkv[2]);
            apply_row8(o1, rC, wkv[3], wkv[4], wkv[5]);
            apply_row8(o1, rD, wkv[6], wkv[7], wkv[8]);
        }
        *reinterpret_cast<float4*>(&sv[ra][4 + cc]) = make_float4(o0[0], o0[1], o0[2], o0[3]);
        *reinterpret_cast<float4*>(&sv[ra][8 + cc]) = make_float4(o0[4], o0[5], o0[6], o0[7]);
        *reinterpret_cast<float4*>(&sv[ra + 1][4 + cc]) = make_float4(o1[0], o1[1], o1[2], o1[3]);
        *reinterpret_cast<float4*>(&sv[ra + 1][8 + cc]) = make_float4(o1[4], o1[5], o1[6], o1[7]);
        if (ra >= 2 && ra < 34)
            *reinterpret_cast<uint4*>(Dv + (size_t)ga * W_ + cc) = f8_to_u4(o0);
        if (ra + 1 >= 2 && ra + 1 < 34)
            *reinterpret_cast<uint4*>(Dv + (size_t)(ga + 1) * W_ + cc) = f8_to_u4(o1);
    }
    __syncthreads();

    // ---- stage t1 = gelu(dw(v, pe1)): 34 rows as 17 two-row units ----
    for (int i = tid; i < 17 * 16; i += 256) {
        int un = i >> 4, cc = (i & 15) * 8;
        int ra = un * 2;               // st1 rows ra, ra+1; sv taps ra..ra+3
        int ga = r0 - 1 + ra;
        float o0[8] = {}, o1[8] = {};
        bool in0 = (ga >= 0 && ga < H_), in1 = (ga + 1 >= 0 && ga + 1 < H_);
        Row8 rA = load_row8(sv[ra], cc);
        Row8 rB = load_row8(sv[ra + 1], cc);
        Row8 rC = load_row8(sv[ra + 2], cc);
        Row8 rD = load_row8(sv[ra + 3], cc);
        if (in0) {
            apply_row8(o0, rA, w1[0], w1[1], w1[2]);
            apply_row8(o0, rB, w1[3], w1[4], w1[5]);
            apply_row8(o0, rC, w1[6], w1[7], w1[8]);
#pragma unroll
            for (int u = 0; u < 8; u++) o0[u] = gelu_tanh(o0[u]);
        }
        if (in1) {
            apply_row8(o1, rB, w1[0], w1[1], w1[2]);
            apply_row8(o1, rC, w1[3], w1[4], w1[5]);
            apply_row8(o1, rD, w1[6], w1[7], w1[8]);
#pragma unroll
            for (int u = 0; u < 8; u++) o1[u] = gelu_tanh(o1[u]);
        }
        *reinterpret_cast<float4*>(&st1[ra][4 + cc]) = make_float4(o0[0], o0[1], o0[2], o0[3]);
        *reinterpret_cast<float4*>(&st1[ra][8 + cc]) = make_float4(o0[4], o0[5], o0[6], o0[7]);
        *reinterpret_cast<float4*>(&st1[ra + 1][4 + cc]) = make_float4(o1[0], o1[1], o1[2], o1[3]);
        *reinterpret_cast<float4*>(&st1[ra + 1][8 + cc]) = make_float4(o1[4], o1[5], o1[6], o1[7]);
    }
    __syncthreads();

    // ---- stage pe: 32 rows as 16 two-row units (exactly one per thread) ----
    bf16* Dp = g_pe + ((size_t)(b * C_ + c)) * HW_;
    {
        int un = tid >> 4, cc = (tid & 15) * 8;
        int ra = un * 2;               // pe rows ra, ra+1; st1 taps ra..ra+3
        float o0[8] = {}, o1[8] = {};
        Row8 rA = load_row8(st1[ra], cc);
        Row8 rB = load_row8(st1[ra + 1], cc);
        Row8 rC = load_row8(st1[ra + 2], cc);
        Row8 rD = load_row8(st1[ra + 3], cc);
        apply_row8(o0, rA, w2[0], w2[1], w2[2]);
        apply_row8(o0, rB, w2[3], w2[4], w2[5]);
        apply_row8(o0, rC, w2[6], w2[7], w2[8]);
        apply_row8(o1, rB, w2[0], w2[1], w2[2]);
        apply_row8(o1, rC, w2[3], w2[4], w2[5]);
        apply_row8(o1, rD, w2[6], w2[7], w2[8]);
        *reinterpret_cast<uint4*>(Dp + (size_t)(r0 + ra) * W_ + cc) = f8_to_u4(o0);
        *reinterpret_cast<uint4*>(Dp + (size_t)(r0 + ra + 1) * W_ + cc) = f8_to_u4(o1);
    }
}

// ---------------- gram via bf16 mma m16n8k16, double-buffered, split-K=8 ------
__global__ __launch_bounds__(256) void gram_mma() {
    __shared__ float sbuf[8704];
    bf16* tile = reinterpret_cast<bf16*>(sbuf);
    int seg = blockIdx.x, h = blockIdx.y, b = blockIdx.z;
    const bf16* Q = g_q + ((size_t)(b * C_ + h * HD_)) * HW_;
    const bf16* K = g_k + ((size_t)(b * C_ + h * HD_)) * HW_;
    int tid = threadIdx.x, wid = tid >> 5, lane = tid & 31;
    int g = lane >> 2, tig = lane & 3;
    float acc[2][4][4] = {};
    int n0 = seg * (HW_ / GSEG);
    int klu = wid * 8;

    auto load = [&](int ch, int st) {
        int base = n0 + ch * 128;
        bf16* sq = tile + st * 8704;
        bf16* sk = sq + 4352;
        for (int i = tid; i < 32 * 16; i += 256) {
            int row = i >> 4, c8 = (i & 15) * 8;
            *reinterpret_cast<uint4*>(sq + row * 136 + c8) =
                *reinterpret_cast<const uint4*>(Q + (size_t)row * HW_ + base + c8);
            *reinterpret_cast<uint4*>(sk + row * 136 + c8) =
                *reinterpret_cast<const uint4*>(K + (size_t)row * HW_ + base + c8);
        }
    };

    load(0, 0);
    const int NCH = (HW_ / GSEG) / 128;   // 16
    for (int ch = 0; ch < NCH; ch++) {
        __syncthreads();
        if (ch + 1 < NCH) load(ch + 1, (ch + 1) & 1);
        unsigned* squ = reinterpret_cast<unsigned*>(tile + (ch & 1) * 8704);
        unsigned* sku = squ + 2176;
        unsigned afr[2][4];
#pragma unroll
        for (int mt = 0; mt < 2; mt++) {
            int r = mt * 16 + g;
            afr[mt][0] = squ[r * 68 + klu + tig];
            afr[mt][1] = squ[(r + 8) * 68 + klu + tig];
            afr[mt][2] = squ[r * 68 + klu + 4 + tig];
            afr[mt][3] = squ[(r + 8) * 68 + klu + 4 + tig];
        }
#pragma unroll
        for (int nt = 0; nt < 4; nt++) {
            unsigned b0 = sku[(nt * 8 + g) * 68 + klu + tig];
            unsigned b1 = sku[(nt * 8 + g) * 68 + klu + 4 + tig];
#pragma unroll
            for (int mt = 0; mt < 2; mt++)
                mma_bf16(acc[mt][nt], afr[mt], b0, b1);
        }
    }
    __syncthreads();
    float* red = sbuf;
#pragma unroll
    for (int mt = 0; mt < 2; mt++)
#pragma unroll
        for (int nt = 0; nt < 4; nt++) {
            int r = mt * 16 + g, cl = nt * 8 + 2 * tig;
            red[wid * 1024 + r * 32 + cl] = acc[mt][nt][0];
            red[wid * 1024 + r * 32 + cl + 1] = acc[mt][nt][1];
            red[wid * 1024 + (r + 8) * 32 + cl] = acc[mt][nt][2];
            red[wid * 1024 + (r + 8) * 32 + cl + 1] = acc[mt][nt][3];
        }
    __syncthreads();
    float* outp = g_part + ((size_t)(b * HEADS_ + h) * GSEG + seg) * 1024;
    for (int i = tid; i < 1024; i += 256) {
        float s = 0.f;
#pragma unroll
        for (int w = 0; w < 8; w++) s += red[w * 1024 + i];
        outp[i] = s;
    }
}

// === fused: reduce partials + scales + temperature + softmax + M projection ===
__global__ void buildM_kernel(const float* __restrict__ ao_w,
                              const float* __restrict__ temp) {
    int h = blockIdx.x, b = blockIdx.y;
    int tid = threadIdx.x;
    __shared__ float sa[32][33];
    __shared__ float sqs[32], sks[32];

    if (tid < 32)
        sqs[tid] = 1.f / fmaxf(sqrtf(g_ss[b * C_ + h * HD_ + tid]), 1e-12f);
    else if (tid < 64)
        sks[tid - 32] = 1.f / fmaxf(sqrtf(g_ss[B_ * C_ + b * C_ + h * HD_ + tid - 32]), 1e-12f);

#pragma unroll
    for (int t = 0; t < 4; t++) {
        int idx = tid + t * 256;
        float s = 0.f;
#pragma unroll
        for (int seg = 0; seg < GSEG; seg++)
            s += g_part[((size_t)(b * HEADS_ + h) * GSEG + seg) * 1024 + idx];
        sa[idx >> 5][idx & 31] = s;
    }
    __syncthreads();

    if (tid < 32) {
        int i = tid;
        float qs = sqs[i];
        float T = __ldg(temp + h);
        float v[32];
        float mx = -1e30f;
#pragma unroll
        for (int j = 0; j < 32; j++) {
            float val = sa[i][j] * qs * sks[j] * T;
            v[j] = val;
            mx = fmaxf(mx, val);
        }
        float sum = 0.f;
#pragma unroll
        for (int j = 0; j < 32; j++) {
            v[j] = expf(v[j] - mx);
            sum += v[j];
        }
        float inv = 1.f / sum;
#pragma unroll
        for (int j = 0; j < 32; j++) sa[i][j] = v[j] * inv;
    }
    __syncthreads();

    float wreg[32];
#pragma unroll
    for (int c = 0; c < 32; c++) wreg[c] = ao_w[(size_t)tid * C_ + h * HD_ + c];
    float m[32];
#pragma unroll 4
    for (int d = 0; d < 32; d++) {
        float s = 0.f;
#pragma unroll
        for (int c = 0; c < 32; c++) s += wreg[c] * sa[c][d];
        m[d] = s;
    }
    unsigned* Mo = g_Mh + ((size_t)(b * C_) + tid) * 128 + h * 16;
#pragma unroll
    for (int j = 0; j < 16; j++) Mo[j] = packbf(m[2 * j], m[2 * j + 1]);
}

// ======= final GEMM: out = M@v + ao_b + pemb + hx (bf16 mma + ldmatrix) ======
__global__ __launch_bounds__(256, 2) void gemm_outh_kernel(const float* __restrict__ bias,
                                                           const float* __restrict__ hx,
                                                           float* __restrict__ out) {
    __shared__ unsigned sm[2 * STG_U];
    int b = blockIdx.z;
    int oBase = blockIdx.x * 128;
    int pBase = blockIdx.y * 128;
    int tid = threadIdx.x;
    int wid = tid >> 5, lane = tid & 31;
    int g = lane >> 2, tig = lane & 3;
    int oW = (wid >> 2) * 64;
    int pW = (wid & 3) * 32;
    uint32_t smBase = smem_u32(sm);
    uint32_t aRowOff = (uint32_t)((lane & 15) * SA_U * 4 + (lane >> 4) * 16);

    const unsigned* Mb = g_Mh + (size_t)b * C_ * 128;
    const bf16* Vb = g_v + (size_t)b * C_ * HW_;

    int lk2 = tid >> 4;
    int lp8 = (tid & 15) * 8;

    uint4 aR[2];
    uint4 vA, vB;
    auto ldg = [&](int kc) {
        int k0 = kc * 32;
#pragma unroll
        for (int i = 0; i < 2; i++) {
            int idx = tid + i * 256;
            int o = idx >> 2, q = idx & 3;
            aR[i] = *reinterpret_cast<const uint4*>(Mb + (size_t)(oBase + o) * 128 + k0 / 2 + q * 4);
        }
        int kk = k0 + 2 * lk2;
        vA = *reinterpret_cast<const uint4*>(Vb + (size_t)kk * HW_ + pBase + lp8);
        vB = *reinterpret_cast<const uint4*>(Vb + (size_t)(kk + 1) * HW_ + pBase + lp8);
    };
    auto sts = [&](int st) {
        unsigned* sA = sm + st * STG_U;
        unsigned* sB = sA + 128 * SA_U;
#pragma unroll
        for (int i = 0; i < 2; i++) {
            int idx = tid + i * 256;
            int o = idx >> 2, q = idx & 3;
            *reinterpret_cast<uint4*>(sA + o * SA_U + q * 4) = aR[i];
        }
        uint4 o0, o1;
        o0.x = __byte_perm(vA.x, vB.x, 0x5410);
        o0.y = __byte_perm(vA.x, vB.x, 0x7632);
        o0.z = __byte_perm(vA.y, vB.y, 0x5410);
        o0.w = __byte_perm(vA.y, vB.y, 0x7632);
        o1.x = __byte_perm(vA.z, vB.z, 0x5410);
        o1.y = __byte_perm(vA.z, vB.z, 0x7632);
        o1.z = __byte_perm(vA.w, vB.w, 0x5410);
        o1.w = __byte_perm(vA.w, vB.w, 0x7632);
        *reinterpret_cast<uint4*>(sB + lk2 * SB_U + lp8) = o0;
        *reinterpret_cast<uint4*>(sB + lk2 * SB_U + lp8 + 4) = o1;
    };

    float acc[4][4][4] = {};
    ldg(0);
    for (int kc = 0; kc < 8; kc++) {
        sts(kc & 1);
        __syncthreads();
        if (kc < 7) ldg(kc + 1);
        uint32_t sAaddr = smBase + (kc & 1) * STG_U * 4;
        unsigned* sB = sm + (kc & 1) * STG_U + 128 * SA_U;
#pragma unroll
        for (int s2 = 0; s2 < 16; s2 += 8) {
            unsigned afr[4][4];
#pragma unroll
            for (int mt = 0; mt < 4; mt++)
                ldsm_x4(afr[mt], sAaddr + (uint32_t)((oW + mt * 16) * SA_U + s2) * 4 + aRowOff);
#pragma unroll
            for (int nt = 0; nt < 4; nt++) {
                int cp = pW + nt * 8 + g;
                unsigned b0 = sB[(s2 + tig) * SB_U + cp];
                unsigned b1 = sB[(s2 + 4 + tig) * SB_U + cp];
#pragma unroll
                for (int mt = 0; mt < 4; mt++)
                    mma_bf16(acc[mt][nt], afr[mt], b0, b1);
            }
        }
        // no trailing sync (ping-pong safe)
    }

    const bf16* PEb = g_pe + (size_t)b * C_ * HW_;
    const float* HXb = hx + (size_t)b * C_ * HW_;
#pragma unroll
    for (int mt = 0; mt < 4; mt++) {
        int o0 = oBase + oW + mt * 16 + g;
        int o1 = o0 + 8;
        float b0v = bias[o0], b1v = bias[o1];
#pragma unroll
        for (int nt = 0; nt < 4; nt++) {
            int p = pBase + pW + nt * 8 + 2 * tig;
            float2 h0 = *reinterpret_cast<const float2*>(HXb + (size_t)o0 * HW_ + p);
            float2 h1 = *reinterpret_cast<const float2*>(HXb + (size_t)o1 * HW_ + p);
            float2 pf0 = __bfloat1622float2(
                *reinterpret_cast<const bf162*>(PEb + (size_t)o0 * HW_ + p));
            float2 pf1 = __bfloat1622float2(
                *reinterpret_cast<const bf162*>(PEb + (size_t)o1 * HW_ + p));
            float2 r0, r1;
            r0.x = acc[mt][nt][0] + b0v + pf0.x + h0.x;
            r0.y = acc[mt][nt][1] + b0v + pf0.y + h0.y;
            r1.x = acc[mt][nt][2] + b1v + pf1.x + h1.x;
            r1.y = acc[mt][nt][3] + b1v + pf1.y + h1.y;
            *reinterpret_cast<float2*>(out + ((size_t)b * C_ + o0) * HW_ + p) = r0;
            *reinterpret_cast<float2*>(out + ((size_t)b * C_ + o1) * HW_ + p) = r1;
        }
    }
}

// -----------------------------------------------------------------------------
extern "C" void kernel_launch(void* const* d_in, const int* in_sizes, int n_in,
                              void* d_out, int out_size) {
    const float* x = (const float*)d_in[0];
    const float* hx = (const float*)d_in[1];
    const float* ln1_w = (const float*)d_in[2];
    const float* ln1_b = (const float*)d_in[3];
    const float* ln2_w = (const float*)d_in[4];
    const float* ln2_b = (const float*)d_in[5];
    const float* q_w = (const float*)d_in[6];
    const float* q_b = (const float*)d_in[7];
    const float* q_dw_w = (const float*)d_in[8];
    const float* q_dw_b = (const float*)d_in[9];
    const float* kv_w = (const float*)d_in[10];
    const float* kv_b = (const float*)d_in[11];
    const float* kv_dw_w = (const float*)d_in[12];
    const float* kv_dw_b = (const float*)d_in[13];
    const float* ao_w = (const float*)d_in[14];
    const float* ao_b = (const float*)d_in[15];
    const float* pe1_w = (const float*)d_in[16];
    const float* pe2_w = (const float*)d_in[17];
    const float* temperature = (const float*)d_in[18];
    float* out = (float*)d_out;

    // 1. fold LN into weights (pack bf16 pairs); zero sumsq accumulators
    prep_w_kernel<<<3 * C_, 256>>>(q_w, q_b, ln1_w, ln1_b, kv_w, kv_b, ln2_w, ln2_b);

    // 2. both LN GEMMs in ONE launch: q_pre -> bufA, kv_pre -> bufB
    gemm_ln2_kernel<<<dim3(6, HW_ / 128, B_), 256>>>(x, hx);

    // 3. merged q+k dwconvs (register-strip, 4-row patches) -> g_q, g_k (+sumsq)
    dwqk_kernel<<<dim3(2, 2 * C_, B_), 256>>>(q_dw_w, q_dw_b, kv_dw_w, kv_dw_b);

    // 4. v dwconv + positional branch (32-row tiles, 2-row units) -> g_v, g_pe
    vpe_kernel<<<dim3(4, C_, B_), 256>>>(kv_dw_w, kv_dw_b, pe1_w, pe2_w);

    // 5. gram (bf16 mma, double-buffered, split-K=8)
    gram_mma<<<dim3(GSEG, HEADS_, B_), 256>>>();

    // 6. fused softmax + attn-fold into output projection; final fused GEMM
    buildM_kernel<<<dim3(HEADS_, B_), 256>>>(ao_w, temperature);
    gemm_outh_kernel<<<dim3(C_ / 128, HW_ / 128, B_), 256>>>(ao_b, hx, out);
}

// round 16
// speedup vs baseline: 1.2173x; 1.0589x over previous
#include <cuda_runtime.h>
#include <cuda_bf16.h>
#include <math.h>
#include <stdint.h>

#define B_ 8
#define C_ 256
#define H_ 128
#define W_ 128
#define HW_ 16384
#define HEADS_ 8
#define HD_ 32
#define GSEG 8

typedef __nv_bfloat16 bf16;
typedef __nv_bfloat162 bf162;

// ---------------- scratch (device globals; no allocation allowed) ------------
__device__ bf16 g_bufA[B_ * C_ * HW_];           // q_pre
__device__ bf16 g_bufB[B_ * 2 * C_ * HW_];       // kv_pre
__device__ bf16 g_q[B_ * C_ * HW_];
__device__ bf16 g_k[B_ * C_ * HW_];
__device__ bf16 g_v[B_ * C_ * HW_];
__device__ bf16 g_pe[B_ * C_ * HW_];             // pemb (WITHOUT hx)
__device__ unsigned g_Wqh[C_ * 128];             // bf16-pair packed folded weights
__device__ unsigned g_Wkvh[2 * C_ * 128];
__device__ unsigned g_Mh[B_ * C_ * 128];         // packed M = ao_w @ blockdiag(attn)
__device__ float g_bq[C_];
__device__ float g_bkv[2 * C_];
__device__ float g_rsq[C_];
__device__ float g_rskv[2 * C_];
__device__ float g_ss[2 * B_ * C_];
__device__ float g_part[B_ * HEADS_ * GSEG * 1024];

// ---------------- helpers ------------------------------------------------
__device__ __forceinline__ void mma_bf16(float* c, const unsigned* a, unsigned b0, unsigned b1) {
    asm volatile(
        "mma.sync.aligned.m16n8k16.row.col.f32.bf16.bf16.f32 "
        "{%0,%1,%2,%3}, {%4,%5,%6,%7}, {%8,%9}, {%0,%1,%2,%3};\n"
        : "+f"(c[0]), "+f"(c[1]), "+f"(c[2]), "+f"(c[3])
        : "r"(a[0]), "r"(a[1]), "r"(a[2]), "r"(a[3]), "r"(b0), "r"(b1));
}
__device__ __forceinline__ void ldsm_x4(unsigned* r, uint32_t addr) {
    asm volatile("ldmatrix.sync.aligned.m8n8.x4.shared.b16 {%0,%1,%2,%3}, [%4];"
                 : "=r"(r[0]), "=r"(r[1]), "=r"(r[2]), "=r"(r[3])
                 : "r"(addr));
}
__device__ __forceinline__ uint32_t smem_u32(const void* p) {
    return (uint32_t)__cvta_generic_to_shared(p);
}
__device__ __forceinline__ unsigned packbf(float lo, float hi) {
    bf162 t = __floats2bfloat162_rn(lo, hi);
    return *reinterpret_cast<unsigned*>(&t);
}
__device__ __forceinline__ float gelu_tanh(float s) {
    float x3 = s * s * s;
    return 0.5f * s * (1.f + tanhf(0.7978845608028654f * (s + 0.044715f * x3)));
}
__device__ __forceinline__ void u4_to_f8(uint4 u, float4& lo, float4& hi) {
    bf162 h0 = *reinterpret_cast<bf162*>(&u.x);
    bf162 h1 = *reinterpret_cast<bf162*>(&u.y);
    bf162 h2 = *reinterpret_cast<bf162*>(&u.z);
    bf162 h3 = *reinterpret_cast<bf162*>(&u.w);
    float2 f0 = __bfloat1622float2(h0), f1 = __bfloat1622float2(h1);
    float2 f2 = __bfloat1622float2(h2), f3 = __bfloat1622float2(h3);
    lo = make_float4(f0.x, f0.y, f1.x, f1.y);
    hi = make_float4(f2.x, f2.y, f3.x, f3.y);
}
__device__ __forceinline__ uint4 f8_to_u4(const float* o) {
    uint4 r;
    r.x = packbf(o[0], o[1]);
    r.y = packbf(o[2], o[3]);
    r.z = packbf(o[4], o[5]);
    r.w = packbf(o[6], o[7]);
    return r;
}

// row view for register-streamed stencils: 10 floats (8 data + 2 halos)
struct Row8 { float v[10]; };
// bf16 smem row: stride 144 bf16, data at +8, pads 0..7 / 136..143 zero
__device__ __forceinline__ Row8 load_row8h(const bf16* R, int s) {
    Row8 r;
    uint4 u = *reinterpret_cast<const uint4*>(R + 8 + s);
    float4 lo, hi;
    u4_to_f8(u, lo, hi);
    r.v[0] = __bfloat162float(R[7 + s]);
    r.v[1] = lo.x; r.v[2] = lo.y; r.v[3] = lo.z; r.v[4] = lo.w;
    r.v[5] = hi.x; r.v[6] = hi.y; r.v[7] = hi.z; r.v[8] = hi.w;
    r.v[9] = __bfloat162float(R[16 + s]);
    return r;
}
__device__ __forceinline__ void apply_row8(float* o, const Row8& r, float w0, float w1, float w2) {
#pragma unroll
    for (int u = 0; u < 8; u++) o[u] += w0 * r.v[u] + w1 * r.v[u + 1] + w2 * r.v[u + 2];
}

// single-pass fill of N bf16 padded rows (stride 144) from bf16 global
template <int NROWS>
__device__ __forceinline__ void fill_rows_h(bf16 (*dst)[144], const bf16* src, int r0, int roff,
                                            int tid) {
    uint4 z4 = make_uint4(0u, 0u, 0u, 0u);
    for (int i = tid; i < NROWS * 16; i += 256) {
        int row = i >> 4, c8 = (i & 15) * 8;
        int gr = r0 + roff + row;
        uint4 u = z4;
        if (gr >= 0 && gr < H_)
            u = *reinterpret_cast<const uint4*>(src + (size_t)gr * W_ + c8);
        *reinterpret_cast<uint4*>(&dst[row][8 + c8]) = u;
    }
    for (int i = tid; i < NROWS * 2; i += 256) {
        int row = i >> 1;
        *reinterpret_cast<uint4*>(&dst[row][(i & 1) ? 136 : 0]) = z4;
    }
}

// ---------------- weight prep: fold LN gamma/beta, pack to bf16 pairs --------
__global__ void prep_w_kernel(const float* __restrict__ qw, const float* __restrict__ qb,
                              const float* __restrict__ ln1w, const float* __restrict__ ln1b,
                              const float* __restrict__ kvw, const float* __restrict__ kvb,
                              const float* __restrict__ ln2w, const float* __restrict__ ln2b) {
    int r = blockIdx.x;
    int tid = threadIdx.x;
    if (r < 16) g_ss[r * 256 + tid] = 0.f;
    const float *w, *lnw, *lnb;
    float cb;
    unsigned* dWh;
    float *dB, *dR;
    if (r < C_) {
        int o = r;
        w = qw + (size_t)o * C_; lnw = ln1w; lnb = ln1b; cb = qb[o];
        dWh = g_Wqh + (size_t)o * 128; dB = g_bq + o; dR = g_rsq + o;
    } else {
        int o = r - C_;
        w = kvw + (size_t)o * C_; lnw = ln2w; lnb = ln2b; cb = kvb[o];
        dWh = g_Wkvh + (size_t)o * 128; dB = g_bkv + o; dR = g_rskv + o;
    }
    float wv = w[tid];
    float we = wv * lnw[tid];
    float we_r = __bfloat162float(__float2bfloat16(we));
    __shared__ float shw[256], sh1[256], sh2[256];
    shw[tid] = we_r;
    sh1[tid] = we_r;
    sh2[tid] = wv * lnb[tid];
    __syncthreads();
    if (tid < 128) dWh[tid] = packbf(shw[2 * tid], shw[2 * tid + 1]);
    for (int s = 128; s > 0; s >>= 1) {
        if (tid < s) { sh1[tid] += sh1[tid + s]; sh2[tid] += sh2[tid + s]; }
        __syncthreads();
    }
    if (tid == 0) { *dR = sh1[0]; *dB = cb + sh2[0]; }
}

// ===== combined LN-fused GEMM (q + kv in ONE launch): bf16 mma + ldmatrix =====
#define SA_U 20
#define SB_U 136
#define STG_U (128 * SA_U + 16 * SB_U)   // 4736 uints / stage

__global__ __launch_bounds__(256, 2) void gemm_ln2_kernel(
    const float* __restrict__ x, const float* __restrict__ hx) {
    __shared__ unsigned sm[2 * STG_U];
    __shared__ float sS[8][128], sQ[8][128];
    int b = blockIdx.z;
    int ot = blockIdx.x;
    int pBase = blockIdx.y * 128;

    const float* X;
    const unsigned* Wb;
    const float* bias;
    const float* rsum;
    bf16* Yh;
    int O, oBase;
    if (ot < 2) {
        X = x; Wb = g_Wqh; bias = g_bq; rsum = g_rsq;
        Yh = g_bufA; O = C_; oBase = ot * 128;
    } else {
        X = hx; Wb = g_Wkvh; bias = g_bkv; rsum = g_rskv;
        Yh = g_bufB; O = 2 * C_; oBase = (ot - 2) * 128;
    }

    int tid = threadIdx.x;
    int wid = tid >> 5, lane = tid & 31;
    int g = lane >> 2, tig = lane & 3;
    int oW = (wid >> 2) * 64;
    int pW = (wid & 3) * 32;
    uint32_t smBase = smem_u32(sm);
    uint32_t aRowOff = (uint32_t)((lane & 15) * SA_U * 4 + (lane >> 4) * 16);

    const float* Xb = X + (size_t)b * C_ * HW_;

    int lk2 = tid >> 5;
    int lp0 = (tid & 31) * 4;

    uint4 wR[2];
    float4 xR[2][2];
    auto ldg = [&](int kc) {
        int k0 = kc * 32;
#pragma unroll
        for (int i = 0; i < 2; i++) {
            int idx = tid + i * 256;
            int o = idx >> 2, q = idx & 3;
            wR[i] = *reinterpret_cast<const uint4*>(Wb + (size_t)(oBase + o) * 128 + k0 / 2 + q * 4);
        }
#pragma unroll
        for (int i = 0; i < 2; i++) {
            int kk = k0 + 2 * (lk2 + i * 8);
            xR[i][0] = *reinterpret_cast<const float4*>(Xb + (size_t)kk * HW_ + pBase + lp0);
            xR[i][1] = *reinterpret_cast<const float4*>(Xb + (size_t)(kk + 1) * HW_ + pBase + lp0);
        }
    };
    float stS[4] = {}, stQ[4] = {};
    auto sts = [&](int st) {
        unsigned* sA = sm + st * STG_U;
        unsigned* sB = sA + 128 * SA_U;
#pragma unroll
        for (int i = 0; i < 2; i++) {
            int idx = tid + i * 256;
            int o = idx >> 2, q = idx & 3;
            *reinterpret_cast<uint4*>(sA + o * SA_U + q * 4) = wR[i];
        }
#pragma unroll
        for (int i = 0; i < 2; i++) {
            float4 a = xR[i][0], c = xR[i][1];
            stS[0] += a.x + c.x; stQ[0] += a.x * a.x + c.x * c.x;
            stS[1] += a.y + c.y; stQ[1] += a.y * a.y + c.y * c.y;
            stS[2] += a.z + c.z; stQ[2] += a.z * a.z + c.z * c.z;
            stS[3] += a.w + c.w; stQ[3] += a.w * a.w + c.w * c.w;
            uint4 u;
            u.x = packbf(a.x, c.x);
            u.y = packbf(a.y, c.y);
            u.z = packbf(a.z, c.z);
            u.w = packbf(a.w, c.w);
            *reinterpret_cast<uint4*>(sB + (lk2 + i * 8) * SB_U + lp0) = u;
        }
    };

    float acc[4][4][4] = {};
    ldg(0);
    for (int kc = 0; kc < 8; kc++) {
        sts(kc & 1);
        __syncthreads();
        if (kc < 7) ldg(kc + 1);
        uint32_t sAaddr = smBase + (kc & 1) * STG_U * 4;
        unsigned* sB = sm + (kc & 1) * STG_U + 128 * SA_U;
#pragma unroll
        for (int s2 = 0; s2 < 16; s2 += 8) {
            unsigned afr[4][4];
#pragma unroll
            for (int mt = 0; mt < 4; mt++)
                ldsm_x4(afr[mt], sAaddr + (uint32_t)((oW + mt * 16) * SA_U + s2) * 4 + aRowOff);
#pragma unroll
            for (int nt = 0; nt < 4; nt++) {
                int cp = pW + nt * 8 + g;
                unsigned b0 = sB[(s2 + tig) * SB_U + cp];
                unsigned b1 = sB[(s2 + 4 + tig) * SB_U + cp];
#pragma unroll
                for (int mt = 0; mt < 4; mt++)
                    mma_bf16(acc[mt][nt], afr[mt], b0, b1);
            }
        }
        // no trailing sync — ping-pong buffers make it redundant
    }

    __syncthreads();
    *reinterpret_cast<float4*>(&sS[lk2][lp0]) = make_float4(stS[0], stS[1], stS[2], stS[3]);
    *reinterpret_cast<float4*>(&sQ[lk2][lp0]) = make_float4(stQ[0], stQ[1], stQ[2], stQ[3]);
    __syncthreads();
    float mu[4][2], iv[4][2];
#pragma unroll
    for (int nt = 0; nt < 4; nt++) {
#pragma unroll
        for (int u = 0; u < 2; u++) {
            int pl = pW + nt * 8 + 2 * tig + u;
            float s0 = 0.f, q0 = 0.f;
#pragma unroll
            for (int wrow = 0; wrow < 8; wrow++) { s0 += sS[wrow][pl]; q0 += sQ[wrow][pl]; }
            float m = s0 * (1.f / 256.f);
            float var = q0 * (1.f / 256.f) - m * m;
            mu[nt][u] = m;
            iv[nt][u] = rsqrtf(var + 1e-5f);
        }
    }
#pragma unroll
    for (int mt = 0; mt < 4; mt++) {
        int o0 = oBase + oW + mt * 16 + g;
        int o1 = o0 + 8;
        float rs0 = rsum[o0], b0v = bias[o0];
        float rs1 = rsum[o1], b1v = bias[o1];
#pragma unroll
        for (int nt = 0; nt < 4; nt++) {
            int p = pBase + pW + nt * 8 + 2 * tig;
            bf162 r0 = __floats2bfloat162_rn(
                iv[nt][0] * (acc[mt][nt][0] - mu[nt][0] * rs0) + b0v,
                iv[nt][1] * (acc[mt][nt][1] - mu[nt][1] * rs0) + b0v);
            bf162 r1 = __floats2bfloat162_rn(
                iv[nt][0] * (acc[mt][nt][2] - mu[nt][0] * rs1) + b1v,
                iv[nt][1] * (acc[mt][nt][3] - mu[nt][1] * rs1) + b1v);
            *reinterpret_cast<bf162*>(Yh + ((size_t)b * O + o0) * HW_ + p) = r0;
            *reinterpret_cast<bf162*>(Yh + ((size_t)b * O + o1) * HW_ + p) = r1;
        }
    }
}

// ===== merged q+k register-strip depthwise 3x3 (+bias, +sumsq), no smem =======
__global__ __launch_bounds__(256, 4) void dwqk_kernel(const float* __restrict__ qw9,
                                                      const float* __restrict__ qb,
                                                      const float* __restrict__ kvw9,
                                                      const float* __restrict__ kvb) {
    int b = blockIdx.z, ci = blockIdx.y;
    int tid = threadIdx.x;
    int cg = tid & 15, rg = tid >> 4;
    int c0 = cg * 8, r0 = blockIdx.x * 64 + rg * 4;

    const bf16* Xc;
    const float* w9;
    const float* bp;
    bf16* D;
    float* ssq;
    if (ci < C_) {
        Xc = g_bufA + ((size_t)(b * C_ + ci)) * HW_;
        w9 = qw9 + (size_t)ci * 9;
        bp = qb + ci;
        D = g_q + ((size_t)(b * C_ + ci)) * HW_;
        ssq = &g_ss[b * C_ + ci];
    } else {
        int c = ci - C_;
        Xc = g_bufB + ((size_t)(b * 2 * C_ + c)) * HW_;
        w9 = kvw9 + (size_t)c * 9;
        bp = kvb + c;
        D = g_k + ((size_t)(b * C_ + c)) * HW_;
        ssq = &g_ss[B_ * C_ + b * C_ + c];
    }
    float wk[9];
#pragma unroll
    for (int t = 0; t < 9; t++) wk[t] = __ldg(w9 + t);
    float bv = __ldg(bp);

    float acc[4][8];
#pragma unroll
    for (int r = 0; r < 4; r++)
#pragma unroll
        for (int u = 0; u < 8; u++) acc[r][u] = bv;
#pragma unroll
    for (int t = 0; t < 6; t++) {
        int ir = r0 - 1 + t;
        float f[10];
#pragma unroll
        for (int u = 0; u < 10; u++) f[u] = 0.f;
        if (ir >= 0 && ir < H_) {
            uint4 u4 = *reinterpret_cast<const uint4*>(Xc + (size_t)ir * W_ + c0);
            float4 lo, hi;
            u4_to_f8(u4, lo, hi);
            f[1] = lo.x; f[2] = lo.y; f[3] = lo.z; f[4] = lo.w;
            f[5] = hi.x; f[6] = hi.y; f[7] = hi.z; f[8] = hi.w;
            if (c0 > 0) f[0] = __bfloat162float(__ldg(Xc + (size_t)ir * W_ + c0 - 1));
            if (c0 + 8 < W_) f[9] = __bfloat162float(__ldg(Xc + (size_t)ir * W_ + c0 + 8));
        }
        if (t >= 2) {
#pragma unroll
            for (int u = 0; u < 8; u++)
                acc[t - 2][u] += wk[6] * f[u] + wk[7] * f[u + 1] + wk[8] * f[u + 2];
        }
        if (t >= 1 && t <= 4) {
#pragma unroll
            for (int u = 0; u < 8; u++)
                acc[t - 1][u] += wk[3] * f[u] + wk[4] * f[u + 1] + wk[5] * f[u + 2];
        }
        if (t <= 3) {
#pragma unroll
            for (int u = 0; u < 8; u++)
                acc[t][u] += wk[0] * f[u] + wk[1] * f[u + 1] + wk[2] * f[u + 2];
        }
    }
    float ss = 0.f;
#pragma unroll
    for (int r = 0; r < 4; r++) {
        *reinterpret_cast<uint4*>(D + (size_t)(r0 + r) * W_ + c0) = f8_to_u4(acc[r]);
#pragma unroll
        for (int u = 0; u < 8; u++) ss += acc[r][u] * acc[r][u];
    }
#pragma unroll
    for (int d = 16; d > 0; d >>= 1) ss += __shfl_down_sync(0xffffffffu, ss, d);
    if ((tid & 31) == 0) atomicAdd(ssq, ss);
}

// ------- v dwconv + positional branch (32-row tiles, 2-row units, bf16 smem) --
__global__ __launch_bounds__(256) void vpe_kernel(const float* __restrict__ kvw9,
                                                  const float* __restrict__ kvb,
                                                  const float* __restrict__ pe1,
                                                  const float* __restrict__ pe2) {
    __shared__ bf16 sbuf[(38 + 36) * 144];
    bf16 (*svi)[144] = reinterpret_cast<bf16(*)[144]>(sbuf);             // 38 rows
    bf16 (*sv)[144]  = reinterpret_cast<bf16(*)[144]>(sbuf + 38 * 144);  // 36 rows
    bf16 (*st1)[144] = svi;                                              // alias (34 rows)
    int b = blockIdx.z, c = blockIdx.y, r0 = blockIdx.x * 32;
    int tid = threadIdx.x;
    const bf16* Vc = g_bufB + ((size_t)(b * 2 * C_ + C_ + c)) * HW_;
    fill_rows_h<38>(svi, Vc, r0, -3, tid);
    {
        uint4 z4 = make_uint4(0u, 0u, 0u, 0u);
        for (int i = tid; i < 36 * 2; i += 256)
            *reinterpret_cast<uint4*>(&sv[i >> 1][(i & 1) ? 136 : 0]) = z4;
    }
    float wkv[9], w1[9], w2[9];
#pragma unroll
    for (int t = 0; t < 9; t++) {
        wkv[t] = __ldg(kvw9 + (size_t)(C_ + c) * 9 + t);
        w1[t] = __ldg(pe1 + (size_t)c * 9 + t);
        w2[t] = __ldg(pe2 + (size_t)c * 9 + t);
    }
    float bvv = __ldg(kvb + C_ + c);
    __syncthreads();

    bf16* Dv = g_v + ((size_t)(b * C_ + c)) * HW_;
    // ---- stage v: 36 rows as 18 two-row units x 16 col groups ----
    for (int i = tid; i < 18 * 16; i += 256) {
        int un = i >> 4, cc = (i & 15) * 8;
        int ra = un * 2;
        int ga = r0 - 2 + ra;
        float o0[8] = {}, o1[8] = {};
        bool in0 = (ga >= 0 && ga < H_), in1 = (ga + 1 >= 0 && ga + 1 < H_);
        if (in0) { for (int u = 0; u < 8; u++) o0[u] = bvv; }
        if (in1) { for (int u = 0; u < 8; u++) o1[u] = bvv; }
        Row8 rA = load_row8h(svi[ra], cc);
        Row8 rB = load_row8h(svi[ra + 1], cc);
        Row8 rC = load_row8h(svi[ra + 2], cc);
        Row8 rD = load_row8h(svi[ra + 3], cc);
        if (in0) {
            apply_row8(o0, rA, wkv[0], wkv[1], wkv[2]);
            apply_row8(o0, rB, wkv[3], wkv[4], wkv[5]);
            apply_row8(o0, rC, wkv[6], wkv[7], wkv[8]);
        }
        if (in1) {
            apply_row8(o1, rB, wkv[0], wkv[1], wkv[2]);
            apply_row8(o1, rC, wkv[3], wkv[4], wkv[5]);
            apply_row8(o1, rD, wkv[6], wkv[7], wkv[8]);
        }
        uint4 p0 = f8_to_u4(o0);
        uint4 p1 = f8_to_u4(o1);
        *reinterpret_cast<uint4*>(&sv[ra][8 + cc]) = p0;
        *reinterpret_cast<uint4*>(&sv[ra + 1][8 + cc]) = p1;
        if (ra >= 2 && ra < 34)
            *reinterpret_cast<uint4*>(Dv + (size_t)ga * W_ + cc) = p0;
        if (ra + 1 >= 2 && ra + 1 < 34)
            *reinterpret_cast<uint4*>(Dv + (size_t)(ga + 1) * W_ + cc) = p1;
    }
    __syncthreads();

    // ---- stage t1 = gelu(dw(v, pe1)): 34 rows as 17 two-row units ----
    for (int i = tid; i < 17 * 16; i += 256) {
        int un = i >> 4, cc = (i & 15) * 8;
        int ra = un * 2;
        int ga = r0 - 1 + ra;
        float o0[8] = {}, o1[8] = {};
        bool in0 = (ga >= 0 && ga < H_), in1 = (ga + 1 >= 0 && ga + 1 < H_);
        Row8 rA = load_row8h(sv[ra], cc);
        Row8 rB = load_row8h(sv[ra + 1], cc);
        Row8 rC = load_row8h(sv[ra + 2], cc);
        Row8 rD = load_row8h(sv[ra + 3], cc);
        if (in0) {
            apply_row8(o0, rA, w1[0], w1[1], w1[2]);
            apply_row8(o0, rB, w1[3], w1[4], w1[5]);
            apply_row8(o0, rC, w1[6], w1[7], w1[8]);
#pragma unroll
            for (int u = 0; u < 8; u++) o0[u] = gelu_tanh(o0[u]);
        }
        if (in1) {
            apply_row8(o1, rB, w1[0], w1[1], w1[2]);
            apply_row8(o1, rC, w1[3], w1[4], w1[5]);
            apply_row8(o1, rD, w1[6], w1[7], w1[8]);
#pragma unroll
            for (int u = 0; u < 8; u++) o1[u] = gelu_tanh(o1[u]);
        }
        *reinterpret_cast<uint4*>(&st1[ra][8 + cc]) = f8_to_u4(o0);
        *reinterpret_cast<uint4*>(&st1[ra + 1][8 + cc]) = f8_to_u4(o1);
    }
    __syncthreads();

    // ---- stage pe: 32 rows as 16 two-row units (one per thread) ----
    bf16* Dp = g_pe + ((size_t)(b * C_ + c)) * HW_;
    {
        int un = tid >> 4, cc = (tid & 15) * 8;
        int ra = un * 2;
        float o0[8] = {}, o1[8] = {};
        Row8 rA = load_row8h(st1[ra], cc);
        Row8 rB = load_row8h(st1[ra + 1], cc);
        Row8 rC = load_row8h(st1[ra + 2], cc);
        Row8 rD = load_row8h(st1[ra + 3], cc);
        apply_row8(o0, rA, w2[0], w2[1], w2[2]);
        apply_row8(o0, rB, w2[3], w2[4], w2[5]);
        apply_row8(o0, rC, w2[6], w2[7], w2[8]);
        apply_row8(o1, rB, w2[0], w2[1], w2[2]);
        apply_row8(o1, rC, w2[3], w2[4], w2[5]);
        apply_row8(o1, rD, w2[6], w2[7], w2[8]);
        *reinterpret_cast<uint4*>(Dp + (size_t)(r0 + ra) * W_ + cc) = f8_to_u4(o0);
        *reinterpret_cast<uint4*>(Dp + (size_t)(r0 + ra + 1) * W_ + cc) = f8_to_u4(o1);
    }
}

// ---------------- gram via bf16 mma m16n8k16, double-buffered, split-K=8 ------
__global__ __launch_bounds__(256) void gram_mma() {
    __shared__ float sbuf[8704];
    bf16* tile = reinterpret_cast<bf16*>(sbuf);
    int seg = blockIdx.x, h = blockIdx.y, b = blockIdx.z;
    const bf16* Q = g_q + ((size_t)(b * C_ + h * HD_)) * HW_;
    const bf16* K = g_k + ((size_t)(b * C_ + h * HD_)) * HW_;
    int tid = threadIdx.x, wid = tid >> 5, lane = tid & 31;
    int g = lane >> 2, tig = lane & 3;
    float acc[2][4][4] = {};
    int n0 = seg * (HW_ / GSEG);
    int klu = wid * 8;

    auto load = [&](int ch, int st) {
        int base = n0 + ch * 128;
        bf16* sq = tile + st * 8704;
        bf16* sk = sq + 4352;
        for (int i = tid; i < 32 * 16; i += 256) {
            int row = i >> 4, c8 = (i & 15) * 8;
            *reinterpret_cast<uint4*>(sq + row * 136 + c8) =
                *reinterpret_cast<const uint4*>(Q + (size_t)row * HW_ + base + c8);
            *reinterpret_cast<uint4*>(sk + row * 136 + c8) =
                *reinterpret_cast<const uint4*>(K + (size_t)row * HW_ + base + c8);
        }
    };

    load(0, 0);
    const int NCH = (HW_ / GSEG) / 128;   // 16
    for (int ch = 0; ch < NCH; ch++) {
        __syncthreads();
        if (ch + 1 < NCH) load(ch + 1, (ch + 1) & 1);
        unsigned* squ = reinterpret_cast<unsigned*>(tile + (ch & 1) * 8704);
        unsigned* sku = squ + 2176;
        unsigned afr[2][4];
#pragma unroll
        for (int mt = 0; mt < 2; mt++) {
            int r = mt * 16 + g;
            afr[mt][0] = squ[r * 68 + klu + tig];
            afr[mt][1] = squ[(r + 8) * 68 + klu + tig];
            afr[mt][2] = squ[r * 68 + klu + 4 + tig];
            afr[mt][3] = squ[(r + 8) * 68 + klu + 4 + tig];
        }
#pragma unroll
        for (int nt = 0; nt < 4; nt++) {
            unsigned b0 = sku[(nt * 8 + g) * 68 + klu + tig];
            unsigned b1 = sku[(nt * 8 + g) * 68 + klu + 4 + tig];
#pragma unroll
            for (int mt = 0; mt < 2; mt++)
                mma_bf16(acc[mt][nt], afr[mt], b0, b1);
        }
    }
    __syncthreads();
    float* red = sbuf;
#pragma unroll
    for (int mt = 0; mt < 2; mt++)
#pragma unroll
        for (int nt = 0; nt < 4; nt++) {
            int r = mt * 16 + g, cl = nt * 8 + 2 * tig;
            red[wid * 1024 + r * 32 + cl] = acc[mt][nt][0];
            red[wid * 1024 + r * 32 + cl + 1] = acc[mt][nt][1];
            red[wid * 1024 + (r + 8) * 32 + cl] = acc[mt][nt][2];
            red[wid * 1024 + (r + 8) * 32 + cl + 1] = acc[mt][nt][3];
        }
    __syncthreads();
    float* outp = g_part + ((size_t)(b * HEADS_ + h) * GSEG + seg) * 1024;
    for (int i = tid; i < 1024; i += 256) {
        float s = 0.f;
#pragma unroll
        for (int w = 0; w < 8; w++) s += red[w * 1024 + i];
        outp[i] = s;
    }
}

// === fused: reduce partials + scales + temperature + softmax + M projection ===
__global__ void buildM_kernel(const float* __restrict__ ao_w,
                              const float* __restrict__ temp) {
    int h = blockIdx.x, b = blockIdx.y;
    int tid = threadIdx.x;
    __shared__ float sa[32][33];
    __shared__ float sqs[32], sks[32];

    if (tid < 32)
        sqs[tid] = 1.f / fmaxf(sqrtf(g_ss[b * C_ + h * HD_ + tid]), 1e-12f);
    else if (tid < 64)
        sks[tid - 32] = 1.f / fmaxf(sqrtf(g_ss[B_ * C_ + b * C_ + h * HD_ + tid - 32]), 1e-12f);

#pragma unroll
    for (int t = 0; t < 4; t++) {
        int idx = tid + t * 256;
        float s = 0.f;
#pragma unroll
        for (int seg = 0; seg < GSEG; seg++)
            s += g_part[((size_t)(b * HEADS_ + h) * GSEG + seg) * 1024 + idx];
        sa[idx >> 5][idx & 31] = s;
    }
    __syncthreads();

    if (tid < 32) {
        int i = tid;
        float qs = sqs[i];
        float T = __ldg(temp + h);
        float v[32];
        float mx = -1e30f;
#pragma unroll
        for (int j = 0; j < 32; j++) {
            float val = sa[i][j] * qs * sks[j] * T;
            v[j] = val;
            mx = fmaxf(mx, val);
        }
        float sum = 0.f;
#pragma unroll
        for (int j = 0; j < 32; j++) {
            v[j] = expf(v[j] - mx);
            sum += v[j];
        }
        float inv = 1.f / sum;
#pragma unroll
        for (int j = 0; j < 32; j++) sa[i][j] = v[j] * inv;
    }
    __syncthreads();

    float wreg[32];
#pragma unroll
    for (int c = 0; c < 32; c++) wreg[c] = ao_w[(size_t)tid * C_ + h * HD_ + c];
    float m[32];
#pragma unroll 4
    for (int d = 0; d < 32; d++) {
        float s = 0.f;
#pragma unroll
        for (int c = 0; c < 32; c++) s += wreg[c] * sa[c][d];
        m[d] = s;
    }
    unsigned* Mo = g_Mh + ((size_t)(b * C_) + tid) * 128 + h * 16;
#pragma unroll
    for (int j = 0; j < 16; j++) Mo[j] = packbf(m[2 * j], m[2 * j + 1]);
}

// ======= final GEMM: out = M@v + ao_b + pemb + hx (bf16 mma + ldmatrix) ======
__global__ __launch_bounds__(256, 2) void gemm_outh_kernel(const float* __restrict__ bias,
                                                           const float* __restrict__ hx,
                                                           float* __restrict__ out) {
    __shared__ unsigned sm[2 * STG_U];
    int b = blockIdx.z;
    int oBase = blockIdx.x * 128;
    int pBase = blockIdx.y * 128;
    int tid = threadIdx.x;
    int wid = tid >> 5, lane = tid & 31;
    int g = lane >> 2, tig = lane & 3;
    int oW = (wid >> 2) * 64;
    int pW = (wid & 3) * 32;
    uint32_t smBase = smem_u32(sm);
    uint32_t aRowOff = (uint32_t)((lane & 15) * SA_U * 4 + (lane >> 4) * 16);

    const unsigned* Mb = g_Mh + (size_t)b * C_ * 128;
    const bf16* Vb = g_v + (size_t)b * C_ * HW_;

    int lk2 = tid >> 4;
    int lp8 = (tid & 15) * 8;

    uint4 aR[2];
    uint4 vA, vB;
    auto ldg = [&](int kc) {
        int k0 = kc * 32;
#pragma unroll
        for (int i = 0; i < 2; i++) {
            int idx = tid + i * 256;
            int o = idx >> 2, q = idx & 3;
            aR[i] = *reinterpret_cast<const uint4*>(Mb + (size_t)(oBase + o) * 128 + k0 / 2 + q * 4);
        }
        int kk = k0 + 2 * lk2;
        vA = *reinterpret_cast<const uint4*>(Vb + (size_t)kk * HW_ + pBase + lp8);
        vB = *reinterpret_cast<const uint4*>(Vb + (size_t)(kk + 1) * HW_ + pBase + lp8);
    };
    auto sts = [&](int st) {
        unsigned* sA = sm + st * STG_U;
        unsigned* sB = sA + 128 * SA_U;
#pragma unroll
        for (int i = 0; i < 2; i++) {
            int idx = tid + i * 256;
            int o = idx >> 2, q = idx & 3;
            *reinterpret_cast<uint4*>(sA + o * SA_U + q * 4) = aR[i];
        }
        uint4 o0, o1;
        o0.x = __byte_perm(vA.x, vB.x, 0x5410);
        o0.y = __byte_perm(vA.x, vB.x, 0x7632);
        o0.z = __byte_perm(vA.y, vB.y, 0x5410);
        o0.w = __byte_perm(vA.y, vB.y, 0x7632);
        o1.x = __byte_perm(vA.z, vB.z, 0x5410);
        o1.y = __byte_perm(vA.z, vB.z, 0x7632);
        o1.z = __byte_perm(vA.w, vB.w, 0x5410);
        o1.w = __byte_perm(vA.w, vB.w, 0x7632);
        *reinterpret_cast<uint4*>(sB + lk2 * SB_U + lp8) = o0;
        *reinterpret_cast<uint4*>(sB + lk2 * SB_U + lp8 + 4) = o1;
    };

    float acc[4][4][4] = {};
    ldg(0);
    for (int kc = 0; kc < 8; kc++) {
        sts(kc & 1);
        __syncthreads();
        if (kc < 7) ldg(kc + 1);
        uint32_t sAaddr = smBase + (kc & 1) * STG_U * 4;
        unsigned* sB = sm + (kc & 1) * STG_U + 128 * SA_U;
#pragma unroll
        for (int s2 = 0; s2 < 16; s2 += 8) {
            unsigned afr[4][4];
#pragma unroll
            for (int mt = 0; mt < 4; mt++)
                ldsm_x4(afr[mt], sAaddr + (uint32_t)((oW + mt * 16) * SA_U + s2) * 4 + aRowOff);
#pragma unroll
            for (int nt = 0; nt < 4; nt++) {
                int cp = pW + nt * 8 + g;
                unsigned b0 = sB[(s2 + tig) * SB_U + cp];
                unsigned b1 = sB[(s2 + 4 + tig) * SB_U + cp];
#pragma unroll
                for (int mt = 0; mt < 4; mt++)
                    mma_bf16(acc[mt][nt], afr[mt], b0, b1);
            }
        }
        // no trailing sync (ping-pong safe)
    }

    const bf16* PEb = g_pe + (size_t)b * C_ * HW_;
    const float* HXb = hx + (size_t)b * C_ * HW_;
#pragma unroll
    for (int mt = 0; mt < 4; mt++) {
        int o0 = oBase + oW + mt * 16 + g;
        int o1 = o0 + 8;
        float b0v = bias[o0], b1v = bias[o1];
#pragma unroll
        for (int nt = 0; nt < 4; nt++) {
            int p = pBase + pW + nt * 8 + 2 * tig;
            float2 h0 = *reinterpret_cast<const float2*>(HXb + (size_t)o0 * HW_ + p);
            float2 h1 = *reinterpret_cast<const float2*>(HXb + (size_t)o1 * HW_ + p);
            float2 pf0 = __bfloat1622float2(
                *reinterpret_cast<const bf162*>(PEb + (size_t)o0 * HW_ + p));
            float2 pf1 = __bfloat1622float2(
                *reinterpret_cast<const bf162*>(PEb + (size_t)o1 * HW_ + p));
            float2 r0, r1;
            r0.x = acc[mt][nt][0] + b0v + pf0.x + h0.x;
            r0.y = acc[mt][nt][1] + b0v + pf0.y + h0.y;
            r1.x = acc[mt][nt][2] + b1v + pf1.x + h1.x;
            r1.y = acc[mt][nt][3] + b1v + pf1.y + h1.y;
            *reinterpret_cast<float2*>(out + ((size_t)b * C_ + o0) * HW_ + p) = r0;
            *reinterpret_cast<float2*>(out + ((size_t)b * C_ + o1) * HW_ + p) = r1;
        }
    }
}

// -----------------------------------------------------------------------------
extern "C" void kernel_launch(void* const* d_in, const int* in_sizes, int n_in,
                              void* d_out, int out_size) {
    const float* x = (const float*)d_in[0];
    const float* hx = (const float*)d_in[1];
    const float* ln1_w = (const float*)d_in[2];
    const float* ln1_b = (const float*)d_in[3];
    const float* ln2_w = (const float*)d_in[4];
    const float* ln2_b = (const float*)d_in[5];
    const float* q_w = (const float*)d_in[6];
    const float* q_b = (const float*)d_in[7];
    const float* q_dw_w = (const float*)d_in[8];
    const float* q_dw_b = (const float*)d_in[9];
    const float* kv_w = (const float*)d_in[10];
    const float* kv_b = (const float*)d_in[11];
    const float* kv_dw_w = (const float*)d_in[12];
    const float* kv_dw_b = (const float*)d_in[13];
    const float* ao_w = (const float*)d_in[14];
    const float* ao_b = (const float*)d_in[15];
    const float* pe1_w = (const float*)d_in[16];
    const float* pe2_w = (const float*)d_in[17];
    const float* temperature = (const float*)d_in[18];
    float* out = (float*)d_out;

    // 1. fold LN into weights (pack bf16 pairs); zero sumsq accumulators
    prep_w_kernel<<<3 * C_, 256>>>(q_w, q_b, ln1_w, ln1_b, kv_w, kv_b, ln2_w, ln2_b);

    // 2. both LN GEMMs in ONE launch: q_pre -> bufA, kv_pre -> bufB
    gemm_ln2_kernel<<<dim3(6, HW_ / 128, B_), 256>>>(x, hx);

    // 3. merged q+k dwconvs (register-strip, 4-row patches) -> g_q, g_k (+sumsq)
    dwqk_kernel<<<dim3(2, 2 * C_, B_), 256>>>(q_dw_w, q_dw_b, kv_dw_w, kv_dw_b);

    // 4. v dwconv + positional branch (bf16 smem tiles) -> g_v, g_pe
    vpe_kernel<<<dim3(4, C_, B_), 256>>>(kv_dw_w, kv_dw_b, pe1_w, pe2_w);

    // 5. gram (bf16 mma, double-buffered, split-K=8)
    gram_mma<<<dim3(GSEG, HEADS_, B_), 256>>>();

    // 6. fused softmax + attn-fold into output projection; final fused GEMM
    buildM_kernel<<<dim3(HEADS_, B_), 256>>>(ao_w, temperature);
    gemm_outh_kernel<<<dim3(C_ / 128, HW_ / 128, B_), 256>>>(ao_b, hx, out);
}

// round 17
// speedup vs baseline: 1.2439x; 1.0218x over previous
#include <cuda_runtime.h>
#include <cuda_bf16.h>
#include <math.h>
#include <stdint.h>

#define B_ 8
#define C_ 256
#define H_ 128
#define W_ 128
#define HW_ 16384
#define HEADS_ 8
#define HD_ 32
#define GSEG 8

typedef __nv_bfloat16 bf16;
typedef __nv_bfloat162 bf162;

// ---------------- scratch (device globals; no allocation allowed) ------------
__device__ bf16 g_bufA[B_ * C_ * HW_];           // q_pre
__device__ bf16 g_bufB[B_ * 2 * C_ * HW_];       // kv_pre
__device__ bf16 g_q[B_ * C_ * HW_];
__device__ bf16 g_k[B_ * C_ * HW_];
__device__ bf16 g_v[B_ * C_ * HW_];
__device__ bf16 g_pe[B_ * C_ * HW_];             // pemb (WITHOUT hx)
__device__ unsigned g_Wqh[C_ * 128];             // bf16-pair packed folded weights
__device__ unsigned g_Wkvh[2 * C_ * 128];
__device__ unsigned g_Mh[B_ * C_ * 128];         // packed M = ao_w @ blockdiag(attn)
__device__ float g_bq[C_];
__device__ float g_bkv[2 * C_];
__device__ float g_rsq[C_];
__device__ float g_rskv[2 * C_];
__device__ float g_ss[2 * B_ * C_];
__device__ float g_part[B_ * HEADS_ * GSEG * 1024];

// ---------------- helpers ------------------------------------------------
__device__ __forceinline__ void mma_bf16(float* c, const unsigned* a, unsigned b0, unsigned b1) {
    asm volatile(
        "mma.sync.aligned.m16n8k16.row.col.f32.bf16.bf16.f32 "
        "{%0,%1,%2,%3}, {%4,%5,%6,%7}, {%8,%9}, {%0,%1,%2,%3};\n"
        : "+f"(c[0]), "+f"(c[1]), "+f"(c[2]), "+f"(c[3])
        : "r"(a[0]), "r"(a[1]), "r"(a[2]), "r"(a[3]), "r"(b0), "r"(b1));
}
__device__ __forceinline__ void ldsm_x4(unsigned* r, uint32_t addr) {
    asm volatile("ldmatrix.sync.aligned.m8n8.x4.shared.b16 {%0,%1,%2,%3}, [%4];"
                 : "=r"(r[0]), "=r"(r[1]), "=r"(r[2]), "=r"(r[3])
                 : "r"(addr));
}
__device__ __forceinline__ uint32_t smem_u32(const void* p) {
    return (uint32_t)__cvta_generic_to_shared(p);
}
__device__ __forceinline__ unsigned packbf(float lo, float hi) {
    bf162 t = __floats2bfloat162_rn(lo, hi);
    return *reinterpret_cast<unsigned*>(&t);
}
__device__ __forceinline__ float tanh_fast(float x) {
    float y;
    asm("tanh.approx.f32 %0, %1;" : "=f"(y) : "f"(x));
    return y;
}
__device__ __forceinline__ float gelu_tanh(float s) {
    float x3 = s * s * s;
    return 0.5f * s * (1.f + tanh_fast(0.7978845608028654f * (s + 0.044715f * x3)));
}
__device__ __forceinline__ void u4_to_f8(uint4 u, float4& lo, float4& hi) {
    bf162 h0 = *reinterpret_cast<bf162*>(&u.x);
    bf162 h1 = *reinterpret_cast<bf162*>(&u.y);
    bf162 h2 = *reinterpret_cast<bf162*>(&u.z);
    bf162 h3 = *reinterpret_cast<bf162*>(&u.w);
    float2 f0 = __bfloat1622float2(h0), f1 = __bfloat1622float2(h1);
    float2 f2 = __bfloat1622float2(h2), f3 = __bfloat1622float2(h3);
    lo = make_float4(f0.x, f0.y, f1.x, f1.y);
    hi = make_float4(f2.x, f2.y, f3.x, f3.y);
}
__device__ __forceinline__ uint4 f8_to_u4(const float* o) {
    uint4 r;
    r.x = packbf(o[0], o[1]);
    r.y = packbf(o[2], o[3]);
    r.z = packbf(o[4], o[5]);
    r.w = packbf(o[6], o[7]);
    return r;
}

// row view for register-streamed stencils: 10 floats (8 data + 2 halos)
struct Row8 { float v[10]; };
// bf16 smem row: stride 144 bf16, data at +8, pads 0..7 / 136..143 zero
__device__ __forceinline__ Row8 load_row8h(const bf16* R, int s) {
    Row8 r;
    uint4 u = *reinterpret_cast<const uint4*>(R + 8 + s);
    float4 lo, hi;
    u4_to_f8(u, lo, hi);
    r.v[0] = __bfloat162float(R[7 + s]);
    r.v[1] = lo.x; r.v[2] = lo.y; r.v[3] = lo.z; r.v[4] = lo.w;
    r.v[5] = hi.x; r.v[6] = hi.y; r.v[7] = hi.z; r.v[8] = hi.w;
    r.v[9] = __bfloat162float(R[16 + s]);
    return r;
}
__device__ __forceinline__ void apply_row8(float* o, const Row8& r, float w0, float w1, float w2) {
#pragma unroll
    for (int u = 0; u < 8; u++) o[u] += w0 * r.v[u] + w1 * r.v[u + 1] + w2 * r.v[u + 2];
}

// single-pass fill of N bf16 padded rows (stride 144) from bf16 global
template <int NROWS>
__device__ __forceinline__ void fill_rows_h(bf16 (*dst)[144], const bf16* src, int r0, int roff,
                                            int tid) {
    uint4 z4 = make_uint4(0u, 0u, 0u, 0u);
    for (int i = tid; i < NROWS * 16; i += 256) {
        int row = i >> 4, c8 = (i & 15) * 8;
        int gr = r0 + roff + row;
        uint4 u = z4;
        if (gr >= 0 && gr < H_)
            u = *reinterpret_cast<const uint4*>(src + (size_t)gr * W_ + c8);
        *reinterpret_cast<uint4*>(&dst[row][8 + c8]) = u;
    }
    for (int i = tid; i < NROWS * 2; i += 256) {
        int row = i >> 1;
        *reinterpret_cast<uint4*>(&dst[row][(i & 1) ? 136 : 0]) = z4;
    }
}

// ---------------- weight prep: fold LN gamma/beta, pack to bf16 pairs --------
__global__ void prep_w_kernel(const float* __restrict__ qw, const float* __restrict__ qb,
                              const float* __restrict__ ln1w, const float* __restrict__ ln1b,
                              const float* __restrict__ kvw, const float* __restrict__ kvb,
                              const float* __restrict__ ln2w, const float* __restrict__ ln2b) {
    int r = blockIdx.x;
    int tid = threadIdx.x;
    if (r < 16) g_ss[r * 256 + tid] = 0.f;
    const float *w, *lnw, *lnb;
    float cb;
    unsigned* dWh;
    float *dB, *dR;
    if (r < C_) {
        int o = r;
        w = qw + (size_t)o * C_; lnw = ln1w; lnb = ln1b; cb = qb[o];
        dWh = g_Wqh + (size_t)o * 128; dB = g_bq + o; dR = g_rsq + o;
    } else {
        int o = r - C_;
        w = kvw + (size_t)o * C_; lnw = ln2w; lnb = ln2b; cb = kvb[o];
        dWh = g_Wkvh + (size_t)o * 128; dB = g_bkv + o; dR = g_rskv + o;
    }
    float wv = w[tid];
    float we = wv * lnw[tid];
    float we_r = __bfloat162float(__float2bfloat16(we));
    __shared__ float shw[256], sh1[256], sh2[256];
    shw[tid] = we_r;
    sh1[tid] = we_r;
    sh2[tid] = wv * lnb[tid];
    __syncthreads();
    if (tid < 128) dWh[tid] = packbf(shw[2 * tid], shw[2 * tid + 1]);
    for (int s = 128; s > 0; s >>= 1) {
        if (tid < s) { sh1[tid] += sh1[tid + s]; sh2[tid] += sh2[tid + s]; }
        __syncthreads();
    }
    if (tid == 0) { *dR = sh1[0]; *dB = cb + sh2[0]; }
}

// ===== combined LN-fused GEMM (q + kv in ONE launch): bf16 mma + ldmatrix =====
#define SA_U 20
#define SB_U 136
#define STG_U (128 * SA_U + 16 * SB_U)   // 4736 uints / stage

__global__ __launch_bounds__(256, 2) void gemm_ln2_kernel(
    const float* __restrict__ x, const float* __restrict__ hx) {
    __shared__ unsigned sm[2 * STG_U];
    __shared__ float sS[8][128], sQ[8][128];
    int b = blockIdx.z;
    int ot = blockIdx.x;
    int pBase = blockIdx.y * 128;

    const float* X;
    const unsigned* Wb;
    const float* bias;
    const float* rsum;
    bf16* Yh;
    int O, oBase;
    if (ot < 2) {
        X = x; Wb = g_Wqh; bias = g_bq; rsum = g_rsq;
        Yh = g_bufA; O = C_; oBase = ot * 128;
    } else {
        X = hx; Wb = g_Wkvh; bias = g_bkv; rsum = g_rskv;
        Yh = g_bufB; O = 2 * C_; oBase = (ot - 2) * 128;
    }

    int tid = threadIdx.x;
    int wid = tid >> 5, lane = tid & 31;
    int g = lane >> 2, tig = lane & 3;
    int oW = (wid >> 2) * 64;
    int pW = (wid & 3) * 32;
    uint32_t smBase = smem_u32(sm);
    uint32_t aRowOff = (uint32_t)((lane & 15) * SA_U * 4 + (lane >> 4) * 16);

    const float* Xb = X + (size_t)b * C_ * HW_;

    int lk2 = tid >> 5;
    int lp0 = (tid & 31) * 4;

    uint4 wR[2];
    float4 xR[2][2];
    auto ldg = [&](int kc) {
        int k0 = kc * 32;
#pragma unroll
        for (int i = 0; i < 2; i++) {
            int idx = tid + i * 256;
            int o = idx >> 2, q = idx & 3;
            wR[i] = *reinterpret_cast<const uint4*>(Wb + (size_t)(oBase + o) * 128 + k0 / 2 + q * 4);
        }
#pragma unroll
        for (int i = 0; i < 2; i++) {
            int kk = k0 + 2 * (lk2 + i * 8);
            xR[i][0] = *reinterpret_cast<const float4*>(Xb + (size_t)kk * HW_ + pBase + lp0);
            xR[i][1] = *reinterpret_cast<const float4*>(Xb + (size_t)(kk + 1) * HW_ + pBase + lp0);
        }
    };
    float stS[4] = {}, stQ[4] = {};
    auto sts = [&](int st) {
        unsigned* sA = sm + st * STG_U;
        unsigned* sB = sA + 128 * SA_U;
#pragma unroll
        for (int i = 0; i < 2; i++) {
            int idx = tid + i * 256;
            int o = idx >> 2, q = idx & 3;
            *reinterpret_cast<uint4*>(sA + o * SA_U + q * 4) = wR[i];
        }
#pragma unroll
        for (int i = 0; i < 2; i++) {
            float4 a = xR[i][0], c = xR[i][1];
            stS[0] += a.x + c.x; stQ[0] += a.x * a.x + c.x * c.x;
            stS[1] += a.y + c.y; stQ[1] += a.y * a.y + c.y * c.y;
            stS[2] += a.z + c.z; stQ[2] += a.z * a.z + c.z * c.z;
            stS[3] += a.w + c.w; stQ[3] += a.w * a.w + c.w * c.w;
            uint4 u;
            u.x = packbf(a.x, c.x);
            u.y = packbf(a.y, c.y);
            u.z = packbf(a.z, c.z);
            u.w = packbf(a.w, c.w);
            *reinterpret_cast<uint4*>(sB + (lk2 + i * 8) * SB_U + lp0) = u;
        }
    };

    float acc[4][4][4] = {};
    ldg(0);
    for (int kc = 0; kc < 8; kc++) {
        sts(kc & 1);
        __syncthreads();
        if (kc < 7) ldg(kc + 1);
        uint32_t sAaddr = smBase + (kc & 1) * STG_U * 4;
        unsigned* sB = sm + (kc & 1) * STG_U + 128 * SA_U;
#pragma unroll
        for (int s2 = 0; s2 < 16; s2 += 8) {
            unsigned afr[4][4];
#pragma unroll
            for (int mt = 0; mt < 4; mt++)
                ldsm_x4(afr[mt], sAaddr + (uint32_t)((oW + mt * 16) * SA_U + s2) * 4 + aRowOff);
#pragma unroll
            for (int nt = 0; nt < 4; nt++) {
                int cp = pW + nt * 8 + g;
                unsigned b0 = sB[(s2 + tig) * SB_U + cp];
                unsigned b1 = sB[(s2 + 4 + tig) * SB_U + cp];
#pragma unroll
                for (int mt = 0; mt < 4; mt++)
                    mma_bf16(acc[mt][nt], afr[mt], b0, b1);
            }
        }
        // no trailing sync — ping-pong buffers make it redundant
    }

    __syncthreads();
    *reinterpret_cast<float4*>(&sS[lk2][lp0]) = make_float4(stS[0], stS[1], stS[2], stS[3]);
    *reinterpret_cast<float4*>(&sQ[lk2][lp0]) = make_float4(stQ[0], stQ[1], stQ[2], stQ[3]);
    __syncthreads();
    float mu[4][2], iv[4][2];
#pragma unroll
    for (int nt = 0; nt < 4; nt++) {
#pragma unroll
        for (int u = 0; u < 2; u++) {
            int pl = pW + nt * 8 + 2 * tig + u;
            float s0 = 0.f, q0 = 0.f;
#pragma unroll
            for (int wrow = 0; wrow < 8; wrow++) { s0 += sS[wrow][pl]; q0 += sQ[wrow][pl]; }
            float m = s0 * (1.f / 256.f);
            float var = q0 * (1.f / 256.f) - m * m;
            mu[nt][u] = m;
            iv[nt][u] = rsqrtf(var + 1e-5f);
        }
    }
#pragma unroll
    for (int mt = 0; mt < 4; mt++) {
        int o0 = oBase + oW + mt * 16 + g;
        int o1 = o0 + 8;
        float rs0 = rsum[o0], b0v = bias[o0];
        float rs1 = rsum[o1], b1v = bias[o1];
#pragma unroll
        for (int nt = 0; nt < 4; nt++) {
            int p = pBase + pW + nt * 8 + 2 * tig;
            bf162 r0 = __floats2bfloat162_rn(
                iv[nt][0] * (acc[mt][nt][0] - mu[nt][0] * rs0) + b0v,
                iv[nt][1] * (acc[mt][nt][1] - mu[nt][1] * rs0) + b0v);
            bf162 r1 = __floats2bfloat162_rn(
                iv[nt][0] * (acc[mt][nt][2] - mu[nt][0] * rs1) + b1v,
                iv[nt][1] * (acc[mt][nt][3] - mu[nt][1] * rs1) + b1v);
            *reinterpret_cast<bf162*>(Yh + ((size_t)b * O + o0) * HW_ + p) = r0;
            *reinterpret_cast<bf162*>(Yh + ((size_t)b * O + o1) * HW_ + p) = r1;
        }
    }
}

// ===== merged q+k register-strip depthwise 3x3 (+bias, +sumsq), no smem =======
__global__ __launch_bounds__(256, 4) void dwqk_kernel(const float* __restrict__ qw9,
                                                      const float* __restrict__ qb,
                                                      const float* __restrict__ kvw9,
                                                      const float* __restrict__ kvb) {
    int b = blockIdx.z, ci = blockIdx.y;
    int tid = threadIdx.x;
    int cg = tid & 15, rg = tid >> 4;
    int c0 = cg * 8, r0 = blockIdx.x * 64 + rg * 4;

    const bf16* Xc;
    const float* w9;
    const float* bp;
    bf16* D;
    float* ssq;
    if (ci < C_) {
        Xc = g_bufA + ((size_t)(b * C_ + ci)) * HW_;
        w9 = qw9 + (size_t)ci * 9;
        bp = qb + ci;
        D = g_q + ((size_t)(b * C_ + ci)) * HW_;
        ssq = &g_ss[b * C_ + ci];
    } else {
        int c = ci - C_;
        Xc = g_bufB + ((size_t)(b * 2 * C_ + c)) * HW_;
        w9 = kvw9 + (size_t)c * 9;
        bp = kvb + c;
        D = g_k + ((size_t)(b * C_ + c)) * HW_;
        ssq = &g_ss[B_ * C_ + b * C_ + c];
    }
    float wk[9];
#pragma unroll
    for (int t = 0; t < 9; t++) wk[t] = __ldg(w9 + t);
    float bv = __ldg(bp);

    float acc[4][8];
#pragma unroll
    for (int r = 0; r < 4; r++)
#pragma unroll
        for (int u = 0; u < 8; u++) acc[r][u] = bv;
#pragma unroll
    for (int t = 0; t < 6; t++) {
        int ir = r0 - 1 + t;
        float f[10];
#pragma unroll
        for (int u = 0; u < 10; u++) f[u] = 0.f;
        if (ir >= 0 && ir < H_) {
            uint4 u4 = *reinterpret_cast<const uint4*>(Xc + (size_t)ir * W_ + c0);
            float4 lo, hi;
            u4_to_f8(u4, lo, hi);
            f[1] = lo.x; f[2] = lo.y; f[3] = lo.z; f[4] = lo.w;
            f[5] = hi.x; f[6] = hi.y; f[7] = hi.z; f[8] = hi.w;
            if (c0 > 0) f[0] = __bfloat162float(__ldg(Xc + (size_t)ir * W_ + c0 - 1));
            if (c0 + 8 < W_) f[9] = __bfloat162float(__ldg(Xc + (size_t)ir * W_ + c0 + 8));
        }
        if (t >= 2) {
#pragma unroll
            for (int u = 0; u < 8; u++)
                acc[t - 2][u] += wk[6] * f[u] + wk[7] * f[u + 1] + wk[8] * f[u + 2];
        }
        if (t >= 1 && t <= 4) {
#pragma unroll
            for (int u = 0; u < 8; u++)
                acc[t - 1][u] += wk[3] * f[u] + wk[4] * f[u + 1] + wk[5] * f[u + 2];
        }
        if (t <= 3) {
#pragma unroll
            for (int u = 0; u < 8; u++)
                acc[t][u] += wk[0] * f[u] + wk[1] * f[u + 1] + wk[2] * f[u + 2];
        }
    }
    float ss = 0.f;
#pragma unroll
    for (int r = 0; r < 4; r++) {
        *reinterpret_cast<uint4*>(D + (size_t)(r0 + r) * W_ + c0) = f8_to_u4(acc[r]);
#pragma unroll
        for (int u = 0; u < 8; u++) ss += acc[r][u] * acc[r][u];
    }
#pragma unroll
    for (int d = 16; d > 0; d >>= 1) ss += __shfl_down_sync(0xffffffffu, ss, d);
    if ((tid & 31) == 0) atomicAdd(ssq, ss);
}

// ------- v dwconv + positional branch (32-row tiles, 2-row units, bf16 smem) --
__global__ __launch_bounds__(256) void vpe_kernel(const float* __restrict__ kvw9,
                                                  const float* __restrict__ kvb,
                                                  const float* __restrict__ pe1,
                                                  const float* __restrict__ pe2) {
    __shared__ bf16 sbuf[(38 + 36) * 144];
    bf16 (*svi)[144] = reinterpret_cast<bf16(*)[144]>(sbuf);             // 38 rows
    bf16 (*sv)[144]  = reinterpret_cast<bf16(*)[144]>(sbuf + 38 * 144);  // 36 rows
    bf16 (*st1)[144] = svi;                                              // alias (34 rows)
    int b = blockIdx.z, c = blockIdx.y, r0 = blockIdx.x * 32;
    int tid = threadIdx.x;
    const bf16* Vc = g_bufB + ((size_t)(b * 2 * C_ + C_ + c)) * HW_;
    fill_rows_h<38>(svi, Vc, r0, -3, tid);
    {
        uint4 z4 = make_uint4(0u, 0u, 0u, 0u);
        for (int i = tid; i < 36 * 2; i += 256)
            *reinterpret_cast<uint4*>(&sv[i >> 1][(i & 1) ? 136 : 0]) = z4;
    }
    float wkv[9], w1[9], w2[9];
#pragma unroll
    for (int t = 0; t < 9; t++) {
        wkv[t] = __ldg(kvw9 + (size_t)(C_ + c) * 9 + t);
        w1[t] = __ldg(pe1 + (size_t)c * 9 + t);
        w2[t] = __ldg(pe2 + (size_t)c * 9 + t);
    }
    float bvv = __ldg(kvb + C_ + c);
    __syncthreads();

    bf16* Dv = g_v + ((size_t)(b * C_ + c)) * HW_;
    // ---- stage v: 36 rows as 18 two-row units x 16 col groups ----
    for (int i = tid; i < 18 * 16; i += 256) {
        int un = i >> 4, cc = (i & 15) * 8;
        int ra = un * 2;
        int ga = r0 - 2 + ra;
        float o0[8] = {}, o1[8] = {};
        bool in0 = (ga >= 0 && ga < H_), in1 = (ga + 1 >= 0 && ga + 1 < H_);
        if (in0) { for (int u = 0; u < 8; u++) o0[u] = bvv; }
        if (in1) { for (int u = 0; u < 8; u++) o1[u] = bvv; }
        Row8 rA = load_row8h(svi[ra], cc);
        Row8 rB = load_row8h(svi[ra + 1], cc);
        Row8 rC = load_row8h(svi[ra + 2], cc);
        Row8 rD = load_row8h(svi[ra + 3], cc);
        if (in0) {
            apply_row8(o0, rA, wkv[0], wkv[1], wkv[2]);
            apply_row8(o0, rB, wkv[3], wkv[4], wkv[5]);
            apply_row8(o0, rC, wkv[6], wkv[7], wkv[8]);
        }
        if (in1) {
            apply_row8(o1, rB, wkv[0], wkv[1], wkv[2]);
            apply_row8(o1, rC, wkv[3], wkv[4], wkv[5]);
            apply_row8(o1, rD, wkv[6], wkv[7], wkv[8]);
        }
        uint4 p0 = f8_to_u4(o0);
        uint4 p1 = f8_to_u4(o1);
        *reinterpret_cast<uint4*>(&sv[ra][8 + cc]) = p0;
        *reinterpret_cast<uint4*>(&sv[ra + 1][8 + cc]) = p1;
        if (ra >= 2 && ra < 34)
            *reinterpret_cast<uint4*>(Dv + (size_t)ga * W_ + cc) = p0;
        if (ra + 1 >= 2 && ra + 1 < 34)
            *reinterpret_cast<uint4*>(Dv + (size_t)(ga + 1) * W_ + cc) = p1;
    }
    __syncthreads();

    // ---- stage t1 = gelu(dw(v, pe1)): 34 rows as 17 two-row units ----
    for (int i = tid; i < 17 * 16; i += 256) {
        int un = i >> 4, cc = (i & 15) * 8;
        int ra = un * 2;
        int ga = r0 - 1 + ra;
        float o0[8] = {}, o1[8] = {};
        bool in0 = (ga >= 0 && ga < H_), in1 = (ga + 1 >= 0 && ga + 1 < H_);
        Row8 rA = load_row8h(sv[ra], cc);
        Row8 rB = load_row8h(sv[ra + 1], cc);
        Row8 rC = load_row8h(sv[ra + 2], cc);
        Row8 rD = load_row8h(sv[ra + 3], cc);
        if (in0) {
            apply_row8(o0, rA, w1[0], w1[1], w1[2]);
            apply_row8(o0, rB, w1[3], w1[4], w1[5]);
            apply_row8(o0, rC, w1[6], w1[7], w1[8]);
#pragma unroll
            for (int u = 0; u < 8; u++) o0[u] = gelu_tanh(o0[u]);
        }
        if (in1) {
            apply_row8(o1, rB, w1[0], w1[1], w1[2]);
            apply_row8(o1, rC, w1[3], w1[4], w1[5]);
            apply_row8(o1, rD, w1[6], w1[7], w1[8]);
#pragma unroll
            for (int u = 0; u < 8; u++) o1[u] = gelu_tanh(o1[u]);
        }
        *reinterpret_cast<uint4*>(&st1[ra][8 + cc]) = f8_to_u4(o0);
        *reinterpret_cast<uint4*>(&st1[ra + 1][8 + cc]) = f8_to_u4(o1);
    }
    __syncthreads();

    // ---- stage pe: 32 rows as 16 two-row units (one per thread) ----
    bf16* Dp = g_pe + ((size_t)(b * C_ + c)) * HW_;
    {
        int un = tid >> 4, cc = (tid & 15) * 8;
        int ra = un * 2;
        float o0[8] = {}, o1[8] = {};
        Row8 rA = load_row8h(st1[ra], cc);
        Row8 rB = load_row8h(st1[ra + 1], cc);
        Row8 rC = load_row8h(st1[ra + 2], cc);
        Row8 rD = load_row8h(st1[ra + 3], cc);
        apply_row8(o0, rA, w2[0], w2[1], w2[2]);
        apply_row8(o0, rB, w2[3], w2[4], w2[5]);
        apply_row8(o0, rC, w2[6], w2[7], w2[8]);
        apply_row8(o1, rB, w2[0], w2[1], w2[2]);
        apply_row8(o1, rC, w2[3], w2[4], w2[5]);
        apply_row8(o1, rD, w2[6], w2[7], w2[8]);
        *reinterpret_cast<uint4*>(Dp + (size_t)(r0 + ra) * W_ + cc) = f8_to_u4(o0);
        *reinterpret_cast<uint4*>(Dp + (size_t)(r0 + ra + 1) * W_ + cc) = f8_to_u4(o1);
    }
}

// ---------------- gram via bf16 mma m16n8k16, double-buffered, split-K=8 ------
__global__ __launch_bounds__(256) void gram_mma() {
    __shared__ float sbuf[8704];
    bf16* tile = reinterpret_cast<bf16*>(sbuf);
    int seg = blockIdx.x, h = blockIdx.y, b = blockIdx.z;
    const bf16* Q = g_q + ((size_t)(b * C_ + h * HD_)) * HW_;
    const bf16* K = g_k + ((size_t)(b * C_ + h * HD_)) * HW_;
    int tid = threadIdx.x, wid = tid >> 5, lane = tid & 31;
    int g = lane >> 2, tig = lane & 3;
    float acc[2][4][4] = {};
    int n0 = seg * (HW_ / GSEG);
    int klu = wid * 8;

    auto load = [&](int ch, int st) {
        int base = n0 + ch * 128;
        bf16* sq = tile + st * 8704;
        bf16* sk = sq + 4352;
        for (int i = tid; i < 32 * 16; i += 256) {
            int row = i >> 4, c8 = (i & 15) * 8;
            *reinterpret_cast<uint4*>(sq + row * 136 + c8) =
                *reinterpret_cast<const uint4*>(Q + (size_t)row * HW_ + base + c8);
            *reinterpret_cast<uint4*>(sk + row * 136 + c8) =
                *reinterpret_cast<const uint4*>(K + (size_t)row * HW_ + base + c8);
        }
    };

    load(0, 0);
    const int NCH = (HW_ / GSEG) / 128;   // 16
    for (int ch = 0; ch < NCH; ch++) {
        __syncthreads();
        if (ch + 1 < NCH) load(ch + 1, (ch + 1) & 1);
        unsigned* squ = reinterpret_cast<unsigned*>(tile + (ch & 1) * 8704);
        unsigned* sku = squ + 2176;
        unsigned afr[2][4];
#pragma unroll
        for (int mt = 0; mt < 2; mt++) {
            int r = mt * 16 + g;
            afr[mt][0] = squ[r * 68 + klu + tig];
            afr[mt][1] = squ[(r + 8) * 68 + klu + tig];
            afr[mt][2] = squ[r * 68 + klu + 4 + tig];
            afr[mt][3] = squ[(r + 8) * 68 + klu + 4 + tig];
        }
#pragma unroll
        for (int nt = 0; nt < 4; nt++) {
            unsigned b0 = sku[(nt * 8 + g) * 68 + klu + tig];
            unsigned b1 = sku[(nt * 8 + g) * 68 + klu + 4 + tig];
#pragma unroll
            for (int mt = 0; mt < 2; mt++)
                mma_bf16(acc[mt][nt], afr[mt], b0, b1);
        }
    }
    __syncthreads();
    float* red = sbuf;
#pragma unroll
    for (int mt = 0; mt < 2; mt++)
#pragma unroll
        for (int nt = 0; nt < 4; nt++) {
            int r = mt * 16 + g, cl = nt * 8 + 2 * tig;
            red[wid * 1024 + r * 32 + cl] = acc[mt][nt][0];
            red[wid * 1024 + r * 32 + cl + 1] = acc[mt][nt][1];
            red[wid * 1024 + (r + 8) * 32 + cl] = acc[mt][nt][2];
            red[wid * 1024 + (r + 8) * 32 + cl + 1] = acc[mt][nt][3];
        }
    __syncthreads();
    float* outp = g_part + ((size_t)(b * HEADS_ + h) * GSEG + seg) * 1024;
    for (int i = tid; i < 1024; i += 256) {
        float s = 0.f;
#pragma unroll
        for (int w = 0; w < 8; w++) s += red[w * 1024 + i];
        outp[i] = s;
    }
}

// === fused: reduce partials + scales + temperature + softmax + M projection ===
__global__ void buildM_kernel(const float* __restrict__ ao_w,
                              const float* __restrict__ temp) {
    int h = blockIdx.x, b = blockIdx.y;
    int tid = threadIdx.x;
    __shared__ float sa[32][33];
    __shared__ float sqs[32], sks[32];

    if (tid < 32)
        sqs[tid] = 1.f / fmaxf(sqrtf(g_ss[b * C_ + h * HD_ + tid]), 1e-12f);
    else if (tid < 64)
        sks[tid - 32] = 1.f / fmaxf(sqrtf(g_ss[B_ * C_ + b * C_ + h * HD_ + tid - 32]), 1e-12f);

#pragma unroll
    for (int t = 0; t < 4; t++) {
        int idx = tid + t * 256;
        float s = 0.f;
#pragma unroll
        for (int seg = 0; seg < GSEG; seg++)
            s += g_part[((size_t)(b * HEADS_ + h) * GSEG + seg) * 1024 + idx];
        sa[idx >> 5][idx & 31] = s;
    }
    __syncthreads();

    if (tid < 32) {
        int i = tid;
        float qs = sqs[i];
        float T = __ldg(temp + h);
        float v[32];
        float mx = -1e30f;
#pragma unroll
        for (int j = 0; j < 32; j++) {
            float val = sa[i][j] * qs * sks[j] * T;
            v[j] = val;
            mx = fmaxf(mx, val);
        }
        float sum = 0.f;
#pragma unroll
        for (int j = 0; j < 32; j++) {
            v[j] = expf(v[j] - mx);
            sum += v[j];
        }
        float inv = 1.f / sum;
#pragma unroll
        for (int j = 0; j < 32; j++) sa[i][j] = v[j] * inv;
    }
    __syncthreads();

    float wreg[32];
#pragma unroll
    for (int c = 0; c < 32; c++) wreg[c] = ao_w[(size_t)tid * C_ + h * HD_ + c];
    float m[32];
#pragma unroll 4
    for (int d = 0; d < 32; d++) {
        float s = 0.f;
#pragma unroll
        for (int c = 0; c < 32; c++) s += wreg[c] * sa[c][d];
        m[d] = s;
    }
    unsigned* Mo = g_Mh + ((size_t)(b * C_) + tid) * 128 + h * 16;
#pragma unroll
    for (int j = 0; j < 16; j++) Mo[j] = packbf(m[2 * j], m[2 * j + 1]);
}

// ======= final GEMM: out = M@v + ao_b + pemb + hx (bf16 mma + ldmatrix) ======
__global__ __launch_bounds__(256, 2) void gemm_outh_kernel(const float* __restrict__ bias,
                                                           const float* __restrict__ hx,
                                                           float* __restrict__ out) {
    __shared__ unsigned sm[2 * STG_U];
    int b = blockIdx.z;
    int oBase = blockIdx.x * 128;
    int pBase = blockIdx.y * 128;
    int tid = threadIdx.x;
    int wid = tid >> 5, lane = tid & 31;
    int g = lane >> 2, tig = lane & 3;
    int oW = (wid >> 2) * 64;
    int pW = (wid & 3) * 32;
    uint32_t smBase = smem_u32(sm);
    uint32_t aRowOff = (uint32_t)((lane & 15) * SA_U * 4 + (lane >> 4) * 16);

    const unsigned* Mb = g_Mh + (size_t)b * C_ * 128;
    const bf16* Vb = g_v + (size_t)b * C_ * HW_;

    int lk2 = tid >> 4;
    int lp8 = (tid & 15) * 8;

    uint4 aR[2];
    uint4 vA, vB;
    auto ldg = [&](int kc) {
        int k0 = kc * 32;
#pragma unroll
        for (int i = 0; i < 2; i++) {
            int idx = tid + i * 256;
            int o = idx >> 2, q = idx & 3;
            aR[i] = *reinterpret_cast<const uint4*>(Mb + (size_t)(oBase + o) * 128 + k0 / 2 + q * 4);
        }
        int kk = k0 + 2 * lk2;
        vA = *reinterpret_cast<const uint4*>(Vb + (size_t)kk * HW_ + pBase + lp8);
        vB = *reinterpret_cast<const uint4*>(Vb + (size_t)(kk + 1) * HW_ + pBase + lp8);
    };
    auto sts = [&](int st) {
        unsigned* sA = sm + st * STG_U;
        unsigned* sB = sA + 128 * SA_U;
#pragma unroll
        for (int i = 0; i < 2; i++) {
            int idx = tid + i * 256;
            int o = idx >> 2, q = idx & 3;
            *reinterpret_cast<uint4*>(sA + o * SA_U + q * 4) = aR[i];
        }
        uint4 o0, o1;
        o0.x = __byte_perm(vA.x, vB.x, 0x5410);
        o0.y = __byte_perm(vA.x, vB.x, 0x7632);
        o0.z = __byte_perm(vA.y, vB.y, 0x5410);
        o0.w = __byte_perm(vA.y, vB.y, 0x7632);
        o1.x = __byte_perm(vA.z, vB.z, 0x5410);
        o1.y = __byte_perm(vA.z, vB.z, 0x7632);
        o1.z = __byte_perm(vA.w, vB.w, 0x5410);
        o1.w = __byte_perm(vA.w, vB.w, 0x7632);
        *reinterpret_cast<uint4*>(sB + lk2 * SB_U + lp8) = o0;
        *reinterpret_cast<uint4*>(sB + lk2 * SB_U + lp8 + 4) = o1;
    };

    float acc[4][4][4] = {};
    ldg(0);
    for (int kc = 0; kc < 8; kc++) {
        sts(kc & 1);
        __syncthreads();
        if (kc < 7) ldg(kc + 1);
        uint32_t sAaddr = smBase + (kc & 1) * STG_U * 4;
        unsigned* sB = sm + (kc & 1) * STG_U + 128 * SA_U;
#pragma unroll
        for (int s2 = 0; s2 < 16; s2 += 8) {
            unsigned afr[4][4];
#pragma unroll
            for (int mt = 0; mt < 4; mt++)
                ldsm_x4(afr[mt], sAaddr + (uint32_t)((oW + mt * 16) * SA_U + s2) * 4 + aRowOff);
#pragma unroll
            for (int nt = 0; nt < 4; nt++) {
                int cp = pW + nt * 8 + g;
                unsigned b0 = sB[(s2 + tig) * SB_U + cp];
                unsigned b1 = sB[(s2 + 4 + tig) * SB_U + cp];
#pragma unroll
                for (int mt = 0; mt < 4; mt++)
                    mma_bf16(acc[mt][nt], afr[mt], b0, b1);
            }
        }
        // no trailing sync (ping-pong safe)
    }

    const bf16* PEb = g_pe + (size_t)b * C_ * HW_;
    const float* HXb = hx + (size_t)b * C_ * HW_;
#pragma unroll
    for (int mt = 0; mt < 4; mt++) {
        int o0 = oBase + oW + mt * 16 + g;
        int o1 = o0 + 8;
        float b0v = bias[o0], b1v = bias[o1];
#pragma unroll
        for (int nt = 0; nt < 4; nt++) {
            int p = pBase + pW + nt * 8 + 2 * tig;
            float2 h0 = *reinterpret_cast<const float2*>(HXb + (size_t)o0 * HW_ + p);
            float2 h1 = *reinterpret_cast<const float2*>(HXb + (size_t)o1 * HW_ + p);
            float2 pf0 = __bfloat1622float2(
                *reinterpret_cast<const bf162*>(PEb + (size_t)o0 * HW_ + p));
            float2 pf1 = __bfloat1622float2(
                *reinterpret_cast<const bf162*>(PEb + (size_t)o1 * HW_ + p));
            float2 r0, r1;
            r0.x = acc[mt][nt][0] + b0v + pf0.x + h0.x;
            r0.y = acc[mt][nt][1] + b0v + pf0.y + h0.y;
            r1.x = acc[mt][nt][2] + b1v + pf1.x + h1.x;
            r1.y = acc[mt][nt][3] + b1v + pf1.y + h1.y;
            *reinterpret_cast<float2*>(out + ((size_t)b * C_ + o0) * HW_ + p) = r0;
            *reinterpret_cast<float2*>(out + ((size_t)b * C_ + o1) * HW_ + p) = r1;
        }
    }
}

// -----------------------------------------------------------------------------
extern "C" void kernel_launch(void* const* d_in, const int* in_sizes, int n_in,
                              void* d_out, int out_size) {
    const float* x = (const float*)d_in[0];
    const float* hx = (const float*)d_in[1];
    const float* ln1_w = (const float*)d_in[2];
    const float* ln1_b = (const float*)d_in[3];
    const float* ln2_w = (const float*)d_in[4];
    const float* ln2_b = (const float*)d_in[5];
    const float* q_w = (const float*)d_in[6];
    const float* q_b = (const float*)d_in[7];
    const float* q_dw_w = (const float*)d_in[8];
    const float* q_dw_b = (const float*)d_in[9];
    const float* kv_w = (const float*)d_in[10];
    const float* kv_b = (const float*)d_in[11];
    const float* kv_dw_w = (const float*)d_in[12];
    const float* kv_dw_b = (const float*)d_in[13];
    const float* ao_w = (const float*)d_in[14];
    const float* ao_b = (const float*)d_in[15];
    const float* pe1_w = (const float*)d_in[16];
    const float* pe2_w = (const float*)d_in[17];
    const float* temperature = (const float*)d_in[18];
    float* out = (float*)d_out;

    // 1. fold LN into weights (pack bf16 pairs); zero sumsq accumulators
    prep_w_kernel<<<3 * C_, 256>>>(q_w, q_b, ln1_w, ln1_b, kv_w, kv_b, ln2_w, ln2_b);

    // 2. both LN GEMMs in ONE launch: q_pre -> bufA, kv_pre -> bufB
    gemm_ln2_kernel<<<dim3(6, HW_ / 128, B_), 256>>>(x, hx);

    // 3. merged q+k dwconvs (register-strip, 4-row patches) -> g_q, g_k (+sumsq)
    dwqk_kernel<<<dim3(2, 2 * C_, B_), 256>>>(q_dw_w, q_dw_b, kv_dw_w, kv_dw_b);

    // 4. v dwconv + positional branch (bf16 smem tiles, fast gelu) -> g_v, g_pe
    vpe_kernel<<<dim3(4, C_, B_), 256>>>(kv_dw_w, kv_dw_b, pe1_w, pe2_w);

    // 5. gram (bf16 mma, double-buffered, split-K=8)
    gram_mma<<<dim3(GSEG, HEADS_, B_), 256>>>();

    // 6. fused softmax + attn-fold into output projection; final fused GEMM
    buildM_kernel<<<dim3(HEADS_, B_), 256>>>(ao_w, temperature);
    gemm_outh_kernel<<<dim3(C_ / 128, HW_ / 128, B_), 256>>>(ao_b, hx, out);
}